// round 3
// baseline (speedup 1.0000x reference)
#include <cuda_runtime.h>
#include <math.h>
#include <string.h>

#define NB 4
#define NS 256
#define ND 768
#define NF 3072
#define NL 4
#define NH 12
#define NDH 64
#define NR (NB*NS)   /* 1024 rows */
#define NT 6
#define N3 (3*ND)    /* 2304 */

typedef unsigned long long ull;

// ---------------- scratch (static device globals; no allocs) ----------------
static __device__ float g_xin [NR*ND];
static __device__ float g_prev[NR*ND];
static __device__ float g_qkv [NR*N3];
static __device__ float g_ctx [NR*ND];
static __device__ float g_aout[4*NR*ND];   // O-proj split-K partials
static __device__ float g_x1  [NR*ND];
static __device__ float g_fout[4*NR*ND];   // FFN2 split-K partials
static __device__ float g_ffh [NR*NF];
static __device__ float g_cur0[NR*ND];     // layer-0 block output (constant over t)
static __device__ float g_mem [NL*NR*ND];
static __device__ float g_cnt [NL*NR*ND];
static __device__ float g_wqkv[NL*ND*N3];  // packed [l][k][q|k|v]
static __device__ float g_bqkv[NL*N3];

// ---------------- helpers ----------------
__device__ __forceinline__ float gelu_f(float x) {
    float x3 = x * x * x;
    float t = tanhf(0.7978845608028654f * (x + 0.044715f * x3));
    return 0.5f * x * (1.0f + t);
}

__device__ __forceinline__ float blk_sum(float v, volatile float* red, int tid) {
    #pragma unroll
    for (int o = 16; o; o >>= 1) v += __shfl_xor_sync(0xffffffffu, v, o);
    if ((tid & 31) == 0) red[tid >> 5] = v;
    __syncthreads();
    float tot = 0.f;
    #pragma unroll
    for (int i = 0; i < 8; i++) tot += red[i];
    return tot;
}

// packed fp32x2 FMA (Blackwell): d = a*b + d, two IEEE fp32 lanes
#define FMA2(d, a, b) asm("fma.rn.f32x2 %0, %1, %2, %0;" : "+l"(d) : "l"(a), "l"(b))

__device__ __forceinline__ ull dup_f(float v) {
    unsigned u = __float_as_uint(v);
    return ((ull)u << 32) | (ull)u;
}
__device__ __forceinline__ float lo_f(ull v) { return __uint_as_float((unsigned)v); }
__device__ __forceinline__ float hi_f(ull v) { return __uint_as_float((unsigned)(v >> 32)); }

// ---------------- x_in = u + seg_emb[segment_ids]; also writes z[0] ----------------
__global__ __launch_bounds__(256) void xin_kernel(
    const float* __restrict__ u, const int* __restrict__ seg,
    const float* __restrict__ semb, float* __restrict__ z0)
{
    int idx = blockIdx.x * 256 + threadIdx.x;
    int srow = idx / ND;
    int d = idx - srow * ND;
    float val = u[idx] + semb[seg[srow] * ND + d];
    g_xin[idx] = val;
    z0[idx] = val;
}

// ---------------- pack Wq|Wk|Wv -> [L][768][2304], biases too ----------------
__global__ __launch_bounds__(256) void pack_qkv_kernel(
    const float* __restrict__ Wq, const float* __restrict__ Wk, const float* __restrict__ Wv,
    const float* __restrict__ bq, const float* __restrict__ bk, const float* __restrict__ bv)
{
    int idx = blockIdx.x * 256 + threadIdx.x;   // 0 .. NL*ND*N3-1
    int l = idx / (ND * N3);
    int r = idx - l * (ND * N3);
    int kk = r / N3;
    int n = r - kk * N3;
    int which = n / ND;
    int nn = n - which * ND;
    const float* W = (which == 0) ? Wq : (which == 1) ? Wk : Wv;
    g_wqkv[idx] = W[((size_t)l * ND + kk) * ND + nn];
    if (idx < NL * N3) {
        int ll = idx / N3;
        int n2 = idx - ll * N3;
        int wh = n2 / ND, nn2 = n2 - wh * ND;
        const float* bb = (wh == 0) ? bq : (wh == 1) ? bk : bv;
        g_bqkv[idx] = bb[ll * ND + nn2];
    }
}

// ---------------- layer-0 closed-form spike rate ----------------
__global__ __launch_bounds__(256) void rate0_kernel(
    float tplus1, float* __restrict__ zout)
{
    int idx = blockIdx.x * 256 + threadIdx.x;
    float c = g_cur0[idx];
    float f = floorf(tplus1 * c);
    f = fminf(fmaxf(f, 0.0f), tplus1);
    float r = f / tplus1;
    g_prev[idx] = r;
    if (zout) zout[idx] = r;
}

// ---------------- fp32x2 GEMM: 128x128 tile, BK=16, double-buffered, split-K --------
// smem: Asd (A transposed + lane-duplicated, u64) [2][16][130], Ws [2][16][128]
#define GSM_ASZ (2*16*130)                 // ulls
#define GSM_BYTES (GSM_ASZ*8 + 2*16*128*4)

__global__ __launch_bounds__(256, 2) void gemm128(
    const float* __restrict__ A, const float* __restrict__ W,
    const float* __restrict__ bias, float* __restrict__ C,
    int N, int K, int klen, int do_gelu)
{
    extern __shared__ unsigned char smraw[];
    ull   (*Asd)[16][130] = (ull (*)[16][130])smraw;
    float (*Ws)[16][128]  = (float (*)[16][128])(smraw + GSM_ASZ * 8);

    const int bx = blockIdx.x, by = blockIdx.y, bz = blockIdx.z;
    const int tid = threadIdx.x;
    const int tx = tid & 15, ty = tid >> 4;
    const int arow = tid >> 1, acol = (tid & 1) * 8;
    const int wrow = tid >> 4, wcol = (tid & 15) * 8;
    const int k0 = bz * klen;

    const float* Ap = A + (size_t)(by * 128 + arow) * K + k0 + acol;
    const float* Wp = W + (size_t)(k0 + wrow) * N + bx * 128 + wcol;
    if (gridDim.z > 1) C += (size_t)bz * ((size_t)NR * N);

    ull acc[8][4];
    #pragma unroll
    for (int i = 0; i < 8; i++)
        #pragma unroll
        for (int j = 0; j < 4; j++) acc[i][j] = 0ull;

    const int nkt = klen >> 4;

    float4 a0 = *(const float4*)Ap;
    float4 a1 = *(const float4*)(Ap + 4);
    float4 w0 = *(const float4*)Wp;
    float4 w1 = *(const float4*)(Wp + 4);
    {
        float av[8] = {a0.x, a0.y, a0.z, a0.w, a1.x, a1.y, a1.z, a1.w};
        #pragma unroll
        for (int e = 0; e < 8; e++) Asd[0][acol + e][arow] = dup_f(av[e]);
        *(float4*)&Ws[0][wrow][wcol] = w0;
        *(float4*)&Ws[0][wrow][wcol + 4] = w1;
    }
    __syncthreads();

    for (int kt = 0; kt < nkt; kt++) {
        const int cur = kt & 1;
        if (kt + 1 < nkt) {
            a0 = *(const float4*)(Ap + (kt + 1) * 16);
            a1 = *(const float4*)(Ap + (kt + 1) * 16 + 4);
            w0 = *(const float4*)(Wp + (size_t)(kt + 1) * 16 * N);
            w1 = *(const float4*)(Wp + (size_t)(kt + 1) * 16 * N + 4);
        }
        #pragma unroll
        for (int kk = 0; kk < 16; kk++) {
            ull a2[8], b2[4];
            longlong2 t;
            t = *(const longlong2*)&Asd[cur][kk][ty * 8 + 0]; a2[0] = t.x; a2[1] = t.y;
            t = *(const longlong2*)&Asd[cur][kk][ty * 8 + 2]; a2[2] = t.x; a2[3] = t.y;
            t = *(const longlong2*)&Asd[cur][kk][ty * 8 + 4]; a2[4] = t.x; a2[5] = t.y;
            t = *(const longlong2*)&Asd[cur][kk][ty * 8 + 6]; a2[6] = t.x; a2[7] = t.y;
            t = *(const longlong2*)&Ws[cur][kk][tx * 8 + 0];  b2[0] = t.x; b2[1] = t.y;
            t = *(const longlong2*)&Ws[cur][kk][tx * 8 + 4];  b2[2] = t.x; b2[3] = t.y;
            #pragma unroll
            for (int i = 0; i < 8; i++) {
                FMA2(acc[i][0], a2[i], b2[0]);
                FMA2(acc[i][1], a2[i], b2[1]);
                FMA2(acc[i][2], a2[i], b2[2]);
                FMA2(acc[i][3], a2[i], b2[3]);
            }
        }
        if (kt + 1 < nkt) {
            const int nx = (kt & 1) ^ 1;
            float av[8] = {a0.x, a0.y, a0.z, a0.w, a1.x, a1.y, a1.z, a1.w};
            #pragma unroll
            for (int e = 0; e < 8; e++) Asd[nx][acol + e][arow] = dup_f(av[e]);
            *(float4*)&Ws[nx][wrow][wcol] = w0;
            *(float4*)&Ws[nx][wrow][wcol + 4] = w1;
        }
        __syncthreads();
    }

    const int n0 = bx * 128 + tx * 8;
    #pragma unroll
    for (int i = 0; i < 8; i++) {
        const int m = by * 128 + ty * 8 + i;
        float o[8];
        #pragma unroll
        for (int j = 0; j < 4; j++) { o[2*j] = lo_f(acc[i][j]); o[2*j+1] = hi_f(acc[i][j]); }
        if (bias) {
            #pragma unroll
            for (int e = 0; e < 8; e++) o[e] += bias[n0 + e];
        }
        if (do_gelu) {
            #pragma unroll
            for (int e = 0; e < 8; e++) o[e] = gelu_f(o[e]);
        }
        float4 v0 = make_float4(o[0], o[1], o[2], o[3]);
        float4 v1 = make_float4(o[4], o[5], o[6], o[7]);
        *(float4*)&C[(size_t)m * N + n0] = v0;
        *(float4*)&C[(size_t)m * N + n0 + 4] = v1;
    }
}

// ---------------- fused attention on packed qkv (row stride 2304) ----------------
#define ATTN_SMEM_FLOATS (64*257 + 256*64 + 64*256 + 64*64)

__global__ __launch_bounds__(256) void attn_kernel(
    const float* __restrict__ qkv, const float* __restrict__ mask,
    float* __restrict__ asum, float* __restrict__ ctx,
    float wgt, int accum)
{
    extern __shared__ float sm[];
    float* Ks = sm;                     // [64][257]
    float* Vs = sm + 64 * 257;          // [256][64]
    float* Ss = Vs + 256 * 64;          // [64][256]
    float* Qs = Ss + 64 * 256;          // [64][64]

    const int rb = blockIdx.x, h = blockIdx.y, b = blockIdx.z;
    const int tid = threadIdx.x;
    const int lane = tid & 31, w = tid >> 5;
    const int i0 = rb * 64;

    const int dq = (tid & 15) * 4;
    const int jb = tid >> 4;

    const float* qb = qkv + ((size_t)b * NS + i0) * N3 + h * NDH;
    const float* kb = qkv + (size_t)b * NS * N3 + ND + h * NDH;
    const float* vb = qkv + (size_t)b * NS * N3 + 2 * ND + h * NDH;

    #pragma unroll
    for (int it = 0; it < 16; it++) {
        int j = jb + it * 16;
        float4 kv = *(const float4*)(kb + (size_t)j * N3 + dq);
        Ks[(dq + 0) * 257 + j] = kv.x;
        Ks[(dq + 1) * 257 + j] = kv.y;
        Ks[(dq + 2) * 257 + j] = kv.z;
        Ks[(dq + 3) * 257 + j] = kv.w;
        float4 vv = *(const float4*)(vb + (size_t)j * N3 + dq);
        *(float4*)&Vs[j * 64 + dq] = vv;
    }
    #pragma unroll
    for (int it = 0; it < 4; it++) {
        int i = jb + it * 16;
        float4 qv = *(const float4*)(qb + (size_t)i * N3 + dq);
        *(float4*)&Qs[i * 64 + dq] = qv;
    }
    __syncthreads();

    float extr[8];
    #pragma unroll
    for (int jj = 0; jj < 8; jj++)
        extr[jj] = (1.0f - mask[b * NS + lane + 32 * jj]) * -10000.0f;

    float acc[8][8];
    #pragma unroll
    for (int r = 0; r < 8; r++)
        #pragma unroll
        for (int jj = 0; jj < 8; jj++) acc[r][jj] = 0.f;

    const int r0 = w * 8;
    for (int d = 0; d < 64; d++) {
        float kr[8];
        #pragma unroll
        for (int jj = 0; jj < 8; jj++) kr[jj] = Ks[d * 257 + lane + 32 * jj];
        #pragma unroll
        for (int r = 0; r < 8; r++) {
            float qv = Qs[(r0 + r) * 64 + d];
            #pragma unroll
            for (int jj = 0; jj < 8; jj++) acc[r][jj] = fmaf(qv, kr[jj], acc[r][jj]);
        }
    }

    #pragma unroll
    for (int r = 0; r < 8; r++) {
        float mx = -3.0e38f;
        #pragma unroll
        for (int jj = 0; jj < 8; jj++) {
            float s = acc[r][jj] * 0.125f + extr[jj];
            acc[r][jj] = s;
            mx = fmaxf(mx, s);
        }
        #pragma unroll
        for (int o = 16; o; o >>= 1) mx = fmaxf(mx, __shfl_xor_sync(0xffffffffu, mx, o));
        float sum = 0.f;
        #pragma unroll
        for (int jj = 0; jj < 8; jj++) { float e = expf(acc[r][jj] - mx); acc[r][jj] = e; sum += e; }
        #pragma unroll
        for (int o = 16; o; o >>= 1) sum += __shfl_xor_sync(0xffffffffu, sum, o);
        float rinv = 1.0f / sum;
        int i = r0 + r;
        float* ar = asum + (((size_t)(b * NH + h)) * NS + (i0 + i)) * NS;
        #pragma unroll
        for (int jj = 0; jj < 8; jj++) {
            float p = acc[r][jj] * rinv;
            int j = lane + 32 * jj;
            Ss[i * 256 + j] = p;
            ar[j] = accum ? (ar[j] + p * wgt) : (p * wgt);
        }
    }
    __syncwarp();

    float c0[8], c1[8];
    #pragma unroll
    for (int r = 0; r < 8; r++) { c0[r] = 0.f; c1[r] = 0.f; }
    for (int j = 0; j < 256; j++) {
        float v0 = Vs[j * 64 + lane];
        float v1 = Vs[j * 64 + lane + 32];
        #pragma unroll
        for (int r = 0; r < 8; r++) {
            float p = Ss[(r0 + r) * 256 + j];
            c0[r] = fmaf(p, v0, c0[r]);
            c1[r] = fmaf(p, v1, c1[r]);
        }
    }
    #pragma unroll
    for (int r = 0; r < 8; r++) {
        size_t base = ((size_t)b * NS + i0 + r0 + r) * ND + h * NDH;
        ctx[base + lane] = c0[r];
        ctx[base + lane + 32] = c1[r];
    }
}

// ---------------- fused: residual + 4 split-K partials + bias + LayerNorm ----------------
__global__ __launch_bounds__(256) void add_ln4_kernel(
    const float* __restrict__ x, const float* __restrict__ part,
    const float* __restrict__ gbias,
    const float* __restrict__ g, const float* __restrict__ bb,
    float* __restrict__ out)
{
    __shared__ float redA[8], redB[8];
    const int row = blockIdx.x, tid = threadIdx.x;
    const size_t base = (size_t)row * ND;
    const size_t slab = (size_t)NR * ND;
    float s[3];
    #pragma unroll
    for (int e = 0; e < 3; e++) {
        int col = tid + 256 * e;
        size_t idx = base + col;
        s[e] = x[idx] + part[idx] + part[idx + slab] + part[idx + 2 * slab]
             + part[idx + 3 * slab] + gbias[col];
    }
    float mean = blk_sum(s[0] + s[1] + s[2], redA, tid) * (1.0f / 768.0f);
    float d0 = s[0] - mean, d1 = s[1] - mean, d2 = s[2] - mean;
    float var = blk_sum(d0 * d0 + d1 * d1 + d2 * d2, redB, tid) * (1.0f / 768.0f);
    float rstd = 1.0f / sqrtf(var + 1e-12f);
    float dd[3] = {d0, d1, d2};
    #pragma unroll
    for (int e = 0; e < 3; e++) {
        int col = tid + 256 * e;
        out[base + col] = g[col] * dd[e] * rstd + bb[col];
    }
}

// ---------------- fused: residual + 4 partials + bias + LN + IF spike (or plain store) ----
__global__ __launch_bounds__(256) void add_ln_spike4_kernel(
    const float* __restrict__ x, const float* __restrict__ part,
    const float* __restrict__ gbias,
    const float* __restrict__ g, const float* __restrict__ bb,
    float* __restrict__ mem, float* __restrict__ cnt, float* __restrict__ prev,
    float invt, float* __restrict__ zout, int first, float* __restrict__ curout)
{
    __shared__ float redA[8], redB[8];
    const int row = blockIdx.x, tid = threadIdx.x;
    const size_t base = (size_t)row * ND;
    const size_t slab = (size_t)NR * ND;
    float s[3];
    #pragma unroll
    for (int e = 0; e < 3; e++) {
        int col = tid + 256 * e;
        size_t idx = base + col;
        s[e] = x[idx] + part[idx] + part[idx + slab] + part[idx + 2 * slab]
             + part[idx + 3 * slab] + gbias[col];
    }
    float mean = blk_sum(s[0] + s[1] + s[2], redA, tid) * (1.0f / 768.0f);
    float d0 = s[0] - mean, d1 = s[1] - mean, d2 = s[2] - mean;
    float var = blk_sum(d0 * d0 + d1 * d1 + d2 * d2, redB, tid) * (1.0f / 768.0f);
    float rstd = 1.0f / sqrtf(var + 1e-12f);
    float dd[3] = {d0, d1, d2};

    #pragma unroll
    for (int e = 0; e < 3; e++) {
        int col = tid + 256 * e;
        size_t idx = base + col;
        float cur = g[col] * dd[e] * rstd + bb[col];
        if (curout) {
            curout[idx] = cur;
        } else {
            float m = (first ? 0.0f : mem[idx]) + cur;
            float spk = (m >= 1.0f) ? 1.0f : 0.0f;
            mem[idx] = m - spk;
            float cn = (first ? 0.0f : cnt[idx]) + spk;
            cnt[idx] = cn;
            float pv = cn * invt;
            prev[idx] = pv;
            if (zout) zout[idx] = pv;
        }
    }
}

// ---------------- launch ----------------
extern "C" void kernel_launch(void* const* d_in, const int* in_sizes, int n_in,
                              void* d_out, int out_size)
{
    const float* u    = (const float*)d_in[0];
    const int*   seg  = (const int*)d_in[1];
    const float* mask = (const float*)d_in[2];
    const float* semb = (const float*)d_in[3];
    const float* Wq   = (const float*)d_in[4];  const float* bq = (const float*)d_in[5];
    const float* Wk   = (const float*)d_in[6];  const float* bk = (const float*)d_in[7];
    const float* Wv   = (const float*)d_in[8];  const float* bv = (const float*)d_in[9];
    const float* Wo   = (const float*)d_in[10]; const float* bo = (const float*)d_in[11];
    const float* ln1g = (const float*)d_in[12]; const float* ln1b = (const float*)d_in[13];
    const float* W1   = (const float*)d_in[14]; const float* b1 = (const float*)d_in[15];
    const float* W2   = (const float*)d_in[16]; const float* b2 = (const float*)d_in[17];
    const float* ln2g = (const float*)d_in[18]; const float* ln2b = (const float*)d_in[19];
    // d_in[20] = time_step (always 6)

    float* out  = (float*)d_out;
    float* z    = out;                              // [5,B,S,D]
    float* attn = out + (size_t)5 * NR * ND;        // [L,B,H,S,S]

    void* p;
    float *xin, *prev, *qkv, *ctx, *aout, *x1, *fout, *ffh, *cur0, *mem, *cnt, *wqkv, *bqkv;
    cudaGetSymbolAddress(&p, g_xin);  xin  = (float*)p;
    cudaGetSymbolAddress(&p, g_prev); prev = (float*)p;
    cudaGetSymbolAddress(&p, g_qkv);  qkv  = (float*)p;
    cudaGetSymbolAddress(&p, g_ctx);  ctx  = (float*)p;
    cudaGetSymbolAddress(&p, g_aout); aout = (float*)p;
    cudaGetSymbolAddress(&p, g_x1);   x1   = (float*)p;
    cudaGetSymbolAddress(&p, g_fout); fout = (float*)p;
    cudaGetSymbolAddress(&p, g_ffh);  ffh  = (float*)p;
    cudaGetSymbolAddress(&p, g_cur0); cur0 = (float*)p;
    cudaGetSymbolAddress(&p, g_mem);  mem  = (float*)p;
    cudaGetSymbolAddress(&p, g_cnt);  cnt  = (float*)p;
    cudaGetSymbolAddress(&p, g_wqkv); wqkv = (float*)p;
    cudaGetSymbolAddress(&p, g_bqkv); bqkv = (float*)p;

    cudaFuncSetAttribute(attn_kernel, cudaFuncAttributeMaxDynamicSharedMemorySize,
                         ATTN_SMEM_FLOATS * 4);
    cudaFuncSetAttribute(gemm128, cudaFuncAttributeMaxDynamicSharedMemorySize, GSM_BYTES);

    xin_kernel<<<(NR * ND) / 256, 256>>>(u, seg, semb, z);
    pack_qkv_kernel<<<(NL * ND * N3) / 256, 256>>>(Wq, Wk, Wv, bq, bk, bv);

    const dim3 gQKV(N3 / 128, NR / 128, 1);   // 18x8
    const dim3 gO  (ND / 128, NR / 128, 4);   // 6x8x4 split-K (klen=192)
    const dim3 gF1 (NF / 128, NR / 128, 1);   // 24x8
    const dim3 gF2 (ND / 128, NR / 128, 4);   // 6x8x4 split-K (klen=768)
    const dim3 gAttn(4, NH, NB);
    const float inv6 = 1.0f / 6.0f;

    // ---- layer 0: block output is constant across time steps; compute once ----
    {
        const int l = 0;
        gemm128<<<gQKV, 256, GSM_BYTES>>>(xin, wqkv, bqkv, qkv, N3, ND, ND, 0);
        attn_kernel<<<gAttn, 256, ATTN_SMEM_FLOATS * 4>>>(
            qkv, mask, attn, ctx, 1.0f, 0);
        gemm128<<<gO, 256, GSM_BYTES>>>(ctx, Wo + (size_t)l * ND * ND, 0, aout, ND, ND, ND / 4, 0);
        add_ln4_kernel<<<NR, 256>>>(xin, aout, bo + l * ND, ln1g + l * ND, ln1b + l * ND, x1);
        gemm128<<<gF1, 256, GSM_BYTES>>>(x1, W1 + (size_t)l * ND * NF, b1 + l * NF, ffh, NF, ND, ND, 1);
        gemm128<<<gF2, 256, GSM_BYTES>>>(ffh, W2 + (size_t)l * NF * ND, 0, fout, ND, NF, NF / 4, 0);
        add_ln_spike4_kernel<<<NR, 256>>>(x1, fout, b2 + l * ND, ln2g + l * ND, ln2b + l * ND,
            0, 0, 0, 0.f, 0, 0, cur0);
    }

    for (int t = 0; t < NT; t++) {
        float tp1 = (float)(t + 1);
        float invt = 1.0f / tp1;
        rate0_kernel<<<(NR * ND) / 256, 256>>>(tp1,
            (t == NT - 1) ? (z + (size_t)1 * NR * ND) : (float*)0);

        const float* xcur = prev;
        for (int l = 1; l < NL; l++) {
            gemm128<<<gQKV, 256, GSM_BYTES>>>(xcur, wqkv + (size_t)l * ND * N3, bqkv + l * N3,
                                              qkv, N3, ND, ND, 0);
            attn_kernel<<<gAttn, 256, ATTN_SMEM_FLOATS * 4>>>(
                qkv, mask, attn + (size_t)l * NB * NH * NS * NS, ctx, inv6, (t > 0) ? 1 : 0);
            gemm128<<<gO, 256, GSM_BYTES>>>(ctx, Wo + (size_t)l * ND * ND, 0, aout, ND, ND, ND / 4, 0);
            add_ln4_kernel<<<NR, 256>>>(xcur, aout, bo + l * ND,
                                        ln1g + l * ND, ln1b + l * ND, x1);
            gemm128<<<gF1, 256, GSM_BYTES>>>(x1, W1 + (size_t)l * ND * NF, b1 + l * NF, ffh, NF, ND, ND, 1);
            gemm128<<<gF2, 256, GSM_BYTES>>>(ffh, W2 + (size_t)l * NF * ND, 0, fout, ND, NF, 768, 0);
            add_ln_spike4_kernel<<<NR, 256>>>(x1, fout, b2 + l * ND,
                ln2g + l * ND, ln2b + l * ND,
                mem + (size_t)l * NR * ND, cnt + (size_t)l * NR * ND, prev, invt,
                (t == NT - 1) ? (z + (size_t)(1 + l) * NR * ND) : (float*)0,
                (t == 0) ? 1 : 0, 0);
            xcur = prev;
        }
    }
}

// round 11
// speedup vs baseline: 1.4368x; 1.4368x over previous
#include <cuda_runtime.h>
#include <cuda_bf16.h>
#include <math.h>

#define NB 4
#define NS 256
#define ND 768
#define NF 3072
#define NL 4
#define NH 12
#define NDH 64
#define NR (NB*NS)   /* 1024 rows */
#define NT 6
#define N3 (3*ND)    /* 2304 */

typedef unsigned int u32;
typedef unsigned short u16;

#define PLsz (NR*ND)
#define FFsz (NR*NF)

// ---------------- scratch (static device globals; no allocs) ----------------
static __device__ float g_xin [PLsz];
static __device__ float g_prev[PLsz];
static __device__ float g_x1  [PLsz];
static __device__ float g_qkv [NR*N3];
static __device__ float g_aout[4*PLsz];
static __device__ float g_fout[4*PLsz];
static __device__ float g_cur0[PLsz];
static __device__ float g_mem [NL*PLsz];
static __device__ float g_cnt [NL*PLsz];
static __device__ float g_bqkv[NL*N3];

// bf16 activation planes: [3 planes][elems]
static __device__ u16 g_xinP [3*PLsz];
static __device__ u16 g_prevP[3*PLsz];
static __device__ u16 g_x1P  [3*PLsz];
static __device__ u16 g_ctxP [3*PLsz];
static __device__ u16 g_ffhP [3*FFsz];

// fragment-packed weights (u32 = bf16 pair): [l][plane][K*N/2]
#define QKV_KN2 (ND*N3/2)
#define WO_KN2  (ND*ND/2)
#define W1_KN2  (ND*NF/2)
#define W2_KN2  (NF*ND/2)
static __device__ u32 g_wqkvP[NL*3*QKV_KN2];
static __device__ u32 g_woP  [NL*3*WO_KN2];
static __device__ u32 g_w1P  [NL*3*W1_KN2];
static __device__ u32 g_w2P  [NL*3*W2_KN2];

// ---------------- helpers ----------------
__device__ __forceinline__ void split3(float a, u16& h, u16& m, u16& l) {
    __nv_bfloat16 bh = __float2bfloat16_rn(a);
    float r1 = a - __bfloat162float(bh);
    __nv_bfloat16 bm = __float2bfloat16_rn(r1);
    float r2 = r1 - __bfloat162float(bm);
    __nv_bfloat16 bl = __float2bfloat16_rn(r2);
    h = reinterpret_cast<u16&>(bh);
    m = reinterpret_cast<u16&>(bm);
    l = reinterpret_cast<u16&>(bl);
}

__device__ __forceinline__ float gelu_f(float x) {
    float x3 = x * x * x;
    float t = tanhf(0.7978845608028654f * (x + 0.044715f * x3));
    return 0.5f * x * (1.0f + t);
}

__device__ __forceinline__ float blk_sum(float v, volatile float* red, int tid) {
    #pragma unroll
    for (int o = 16; o; o >>= 1) v += __shfl_xor_sync(0xffffffffu, v, o);
    if ((tid & 31) == 0) red[tid >> 5] = v;
    __syncthreads();
    float tot = 0.f;
    #pragma unroll
    for (int i = 0; i < 8; i++) tot += red[i];
    return tot;
}

__device__ __forceinline__ void mmabf(float* c, const uint4 a, const uint2 b) {
    asm volatile(
        "mma.sync.aligned.m16n8k16.row.col.f32.bf16.bf16.f32 "
        "{%0,%1,%2,%3},{%4,%5,%6,%7},{%8,%9},{%0,%1,%2,%3};"
        : "+f"(c[0]), "+f"(c[1]), "+f"(c[2]), "+f"(c[3])
        : "r"(a.x), "r"(a.y), "r"(a.z), "r"(a.w), "r"(b.x), "r"(b.y));
}

// ---------------- weight packing into B-fragment layout ----------------
// u32 pos = ((kc*(N/8)+nt)*32+ln)*2 + j  ->  k = kc*16+(ln&3)*2+j*8, n = nt*8+(ln>>2)
__global__ __launch_bounds__(256) void pack_w_kernel(
    const float* __restrict__ W, u32* __restrict__ ph, u32* __restrict__ pm,
    u32* __restrict__ plo, int K, int N)
{
    int pos = blockIdx.x * 256 + threadIdx.x;
    if (pos >= K * N / 2) return;
    int perchunk = N * 8;
    int kc = pos / perchunk;
    int rem = pos - kc * perchunk;
    int nt = rem >> 6;
    int r2 = rem & 63;
    int ln = r2 >> 1, j = r2 & 1;
    int k = kc * 16 + (ln & 3) * 2 + j * 8;
    int n = nt * 8 + (ln >> 2);
    float w0 = W[(size_t)k * N + n];
    float w1 = W[(size_t)(k + 1) * N + n];
    u16 h0, m0, l0, h1, m1, l1;
    split3(w0, h0, m0, l0);
    split3(w1, h1, m1, l1);
    ph[pos]  = (u32)h0 | ((u32)h1 << 16);
    pm[pos]  = (u32)m0 | ((u32)m1 << 16);
    plo[pos] = (u32)l0 | ((u32)l1 << 16);
}

// fused q|k|v pack: logical W[768, 2304] from three [768,768] matrices
__global__ __launch_bounds__(256) void pack_qkvw_kernel(
    const float* __restrict__ Wq, const float* __restrict__ Wk, const float* __restrict__ Wv,
    u32* __restrict__ ph, u32* __restrict__ pm, u32* __restrict__ plo)
{
    int pos = blockIdx.x * 256 + threadIdx.x;
    if (pos >= QKV_KN2) return;
    const int N = N3;
    int perchunk = N * 8;
    int kc = pos / perchunk;
    int rem = pos - kc * perchunk;
    int nt = rem >> 6;
    int r2 = rem & 63;
    int ln = r2 >> 1, j = r2 & 1;
    int k = kc * 16 + (ln & 3) * 2 + j * 8;
    int n = nt * 8 + (ln >> 2);
    int which = n / ND, nn = n - which * ND;
    const float* W = (which == 0) ? Wq : (which == 1) ? Wk : Wv;
    float w0 = W[(size_t)k * ND + nn];
    float w1 = W[(size_t)(k + 1) * ND + nn];
    u16 h0, m0, l0, h1, m1, l1;
    split3(w0, h0, m0, l0);
    split3(w1, h1, m1, l1);
    ph[pos]  = (u32)h0 | ((u32)h1 << 16);
    pm[pos]  = (u32)m0 | ((u32)m1 << 16);
    plo[pos] = (u32)l0 | ((u32)l1 << 16);
}

__global__ __launch_bounds__(256) void biasqkv_kernel(
    const float* __restrict__ bq, const float* __restrict__ bk, const float* __restrict__ bv)
{
    int idx = blockIdx.x * 256 + threadIdx.x;
    if (idx >= NL * N3) return;
    int l = idx / N3, n = idx - l * N3;
    int which = n / ND, nn = n - which * ND;
    const float* b = (which == 0) ? bq : (which == 1) ? bk : bv;
    g_bqkv[idx] = b[l * ND + nn];
}

// ---------------- x_in = u + seg_emb[segment_ids]; z[0]; splits ----------------
__global__ __launch_bounds__(256) void xin_kernel(
    const float* __restrict__ u, const int* __restrict__ seg,
    const float* __restrict__ semb, float* __restrict__ z0)
{
    int idx = blockIdx.x * 256 + threadIdx.x;
    int srow = idx / ND;
    int d = idx - srow * ND;
    float val = u[idx] + semb[seg[srow] * ND + d];
    g_xin[idx] = val;
    z0[idx] = val;
    u16 h, m, l; split3(val, h, m, l);
    g_xinP[idx] = h; g_xinP[PLsz + idx] = m; g_xinP[2 * PLsz + idx] = l;
}

// ---------------- layer-0 closed-form spike rate ----------------
__global__ __launch_bounds__(256) void rate0_kernel(float tplus1, float* __restrict__ zout)
{
    int idx = blockIdx.x * 256 + threadIdx.x;
    float c = g_cur0[idx];
    float f = floorf(tplus1 * c);
    f = fminf(fmaxf(f, 0.0f), tplus1);
    float r = f / tplus1;
    g_prev[idx] = r;
    u16 h, m, l; split3(r, h, m, l);
    g_prevP[idx] = h; g_prevP[PLsz + idx] = m; g_prevP[2 * PLsz + idx] = l;
    if (zout) zout[idx] = r;
}

// ---------------- exact-fp32-via-bf16 (8-term) tensor-core GEMM ----------------
// 64(M) x 128(N) block tile, BK=16, 256 threads = 8 warps of 32x32.
// A: 3 row-major bf16 planes. B: 3 fragment-packed u32 planes.
// KEY (R11): per-chunk zeroed MMA accumulators drained into IEEE fp32 registers;
// the tensor-core adder's RZ-truncation bias never sees the full-K accumulator.
__global__ __launch_bounds__(256, 2) void gemm_bf(
    const u16* __restrict__ A0, const u16* __restrict__ A1, const u16* __restrict__ A2,
    const u32* __restrict__ B0, const u32* __restrict__ B1, const u32* __restrict__ B2,
    const float* __restrict__ bias,
    float* __restrict__ Cf, u16* __restrict__ C0, u16* __restrict__ C1, u16* __restrict__ C2,
    int N, int K, int klen, int do_gelu)
{
    __shared__ __align__(16) u32 AF[2][1536];   // [pl][mt4][lane][4regs]
    __shared__ __align__(16) u32 BF[2][3072];   // [pl][nt16][lane][2regs]

    const int bx = blockIdx.x, by = blockIdx.y, bz = blockIdx.z;
    const int tid = threadIdx.x, lane = tid & 31, wid = tid >> 5;
    const int wm = wid >> 2, wn = wid & 3;
    const int K2 = K >> 1, N8 = N >> 3;

    // A producer: 6 u32 per thread per k16-chunk
    const u32* apln[3] = {(const u32*)A0, (const u32*)A1, (const u32*)A2};
    const u32* ap[6];
    #pragma unroll
    for (int s = 0; s < 6; s++) {
        int idx = s * 256 + tid;
        int j = idx & 3, ln = (idx >> 2) & 31, mt = (idx >> 7) & 3, pl = idx >> 9;
        int row = by * 64 + mt * 16 + (ln >> 2) + (j & 1) * 8;
        int c2 = (ln & 3) + (j >> 1) * 4;
        ap[s] = apln[pl] + (size_t)row * K2 + ((bz * klen) >> 1) + c2;
    }
    // B producer: 3 uint4 per thread per k16-chunk
    const u32* bpln[3] = {B0, B1, B2};
    const u32* bp[3];
    #pragma unroll
    for (int s = 0; s < 3; s++) {
        int idx4 = s * 256 + tid;
        int pl = idx4 >> 8, rem4 = idx4 & 255;
        int ntl = rem4 >> 4, lnp = (rem4 & 15) * 2;
        size_t goff = ((size_t)(((bz * klen) >> 4) * N8 + bx * 16 + ntl) * 32 + lnp) * 2;
        bp[s] = bpln[pl] + goff;
    }
    const size_t bstep = (size_t)N * 8;

    float acc[8][4];
    #pragma unroll
    for (int i = 0; i < 8; i++)
        #pragma unroll
        for (int j = 0; j < 4; j++) acc[i][j] = 0.f;

    const int nkt = klen >> 4;

    #pragma unroll
    for (int s = 0; s < 6; s++) AF[0][s * 256 + tid] = ap[s][0];
    #pragma unroll
    for (int s = 0; s < 3; s++) *(uint4*)&BF[0][(s * 256 + tid) * 4] = *(const uint4*)bp[s];
    __syncthreads();

    u32 va[6]; uint4 vb[3];
    for (int kt = 0; kt < nkt; kt++) {
        const int cur = kt & 1;
        const bool more = (kt + 1 < nkt);
        if (more) {
            #pragma unroll
            for (int s = 0; s < 6; s++) va[s] = ap[s][(kt + 1) * 8];
            #pragma unroll
            for (int s = 0; s < 3; s++) vb[s] = *(const uint4*)(bp[s] + (size_t)(kt + 1) * bstep);
        }

        uint4 aH[2], aM[2], aL[2];
        #pragma unroll
        for (int m2 = 0; m2 < 2; m2++) {
            int mt = wm * 2 + m2;
            aH[m2] = *(const uint4*)&AF[cur][(mt * 32 + lane) * 4];
            aM[m2] = *(const uint4*)&AF[cur][((4 + mt) * 32 + lane) * 4];
            aL[m2] = *(const uint4*)&AF[cur][((8 + mt) * 32 + lane) * 4];
        }
        #pragma unroll
        for (int n2 = 0; n2 < 4; n2++) {
            int nt = wn * 4 + n2;
            uint2 bH = *(const uint2*)&BF[cur][(nt * 32 + lane) * 2];
            uint2 bM = *(const uint2*)&BF[cur][1024 + (nt * 32 + lane) * 2];
            uint2 bL = *(const uint2*)&BF[cur][2048 + (nt * 32 + lane) * 2];
            #pragma unroll
            for (int m2 = 0; m2 < 2; m2++) {
                // small terms in a fresh (zeroed) accumulator, smallest first
                float cS[4] = {0.f, 0.f, 0.f, 0.f};
                mmabf(cS, aL[m2], bM);
                mmabf(cS, aM[m2], bL);
                mmabf(cS, aM[m2], bM);
                mmabf(cS, aL[m2], bH);
                mmabf(cS, aH[m2], bL);
                mmabf(cS, aM[m2], bH);
                mmabf(cS, aH[m2], bM);
                // dominant term in its own zeroed accumulator
                float cB[4] = {0.f, 0.f, 0.f, 0.f};
                mmabf(cB, aH[m2], bH);
                // IEEE fp32 RN drain into the running sum
                float* c = acc[m2 * 4 + n2];
                #pragma unroll
                for (int q = 0; q < 4; q++) c[q] += cB[q] + cS[q];
            }
        }

        if (more) {
            const int nx = cur ^ 1;
            #pragma unroll
            for (int s = 0; s < 6; s++) AF[nx][s * 256 + tid] = va[s];
            #pragma unroll
            for (int s = 0; s < 3; s++) *(uint4*)&BF[nx][(s * 256 + tid) * 4] = vb[s];
        }
        __syncthreads();
    }

    float* Cp = Cf;
    if (Cp && gridDim.z > 1) Cp += (size_t)bz * ((size_t)NR * N);

    #pragma unroll
    for (int m2 = 0; m2 < 2; m2++)
        #pragma unroll
        for (int n2 = 0; n2 < 4; n2++) {
            float* c = acc[m2 * 4 + n2];
            int row = by * 64 + wm * 32 + m2 * 16 + (lane >> 2);
            int col = bx * 128 + wn * 32 + n2 * 8 + (lane & 3) * 2;
            float o0 = c[0], o1 = c[1], o2 = c[2], o3 = c[3];
            if (bias) {
                float bb0 = bias[col], bb1 = bias[col + 1];
                o0 += bb0; o1 += bb1; o2 += bb0; o3 += bb1;
            }
            if (do_gelu) { o0 = gelu_f(o0); o1 = gelu_f(o1); o2 = gelu_f(o2); o3 = gelu_f(o3); }
            if (C0) {
                u16 h0, m0, l0, h1, m1, l1;
                split3(o0, h0, m0, l0); split3(o1, h1, m1, l1);
                size_t p = ((size_t)row * N + col) >> 1;
                ((u32*)C0)[p] = (u32)h0 | ((u32)h1 << 16);
                ((u32*)C1)[p] = (u32)m0 | ((u32)m1 << 16);
                ((u32*)C2)[p] = (u32)l0 | ((u32)l1 << 16);
                split3(o2, h0, m0, l0); split3(o3, h1, m1, l1);
                p = ((size_t)(row + 8) * N + col) >> 1;
                ((u32*)C0)[p] = (u32)h0 | ((u32)h1 << 16);
                ((u32*)C1)[p] = (u32)m0 | ((u32)m1 << 16);
                ((u32*)C2)[p] = (u32)l0 | ((u32)l1 << 16);
            } else {
                *(float2*)&Cp[(size_t)row * N + col] = make_float2(o0, o1);
                *(float2*)&Cp[(size_t)(row + 8) * N + col] = make_float2(o2, o3);
            }
        }
}

// ---------------- fused attention; ctx -> 3 bf16 planes ----------------
#define ATTN_SMEM_FLOATS (64*257 + 256*64 + 64*256 + 64*64)

__global__ __launch_bounds__(256) void attn_kernel(
    const float* __restrict__ qkv, const float* __restrict__ mask,
    float* __restrict__ asum, u16* __restrict__ ctxP,
    float wgt, int accum)
{
    extern __shared__ float smf[];
    float* Ks = smf;                    // [64][257]
    float* Vs = smf + 64 * 257;         // [256][64]
    float* Ss = Vs + 256 * 64;          // [64][256]
    float* Qs = Ss + 64 * 256;          // [64][64]

    const int rb = blockIdx.x, h = blockIdx.y, b = blockIdx.z;
    const int tid = threadIdx.x;
    const int lane = tid & 31, w = tid >> 5;
    const int i0 = rb * 64;
    const int dq = (tid & 15) * 4;
    const int jb = tid >> 4;

    const float* qb = qkv + ((size_t)b * NS + i0) * N3 + h * NDH;
    const float* kb = qkv + (size_t)b * NS * N3 + ND + h * NDH;
    const float* vb = qkv + (size_t)b * NS * N3 + 2 * ND + h * NDH;

    #pragma unroll
    for (int it = 0; it < 16; it++) {
        int j = jb + it * 16;
        float4 kv = *(const float4*)(kb + (size_t)j * N3 + dq);
        Ks[(dq + 0) * 257 + j] = kv.x;
        Ks[(dq + 1) * 257 + j] = kv.y;
        Ks[(dq + 2) * 257 + j] = kv.z;
        Ks[(dq + 3) * 257 + j] = kv.w;
        float4 vv = *(const float4*)(vb + (size_t)j * N3 + dq);
        *(float4*)&Vs[j * 64 + dq] = vv;
    }
    #pragma unroll
    for (int it = 0; it < 4; it++) {
        int i = jb + it * 16;
        float4 qv = *(const float4*)(qb + (size_t)i * N3 + dq);
        *(float4*)&Qs[i * 64 + dq] = qv;
    }
    __syncthreads();

    float extr[8];
    #pragma unroll
    for (int jj = 0; jj < 8; jj++)
        extr[jj] = (1.0f - mask[b * NS + lane + 32 * jj]) * -10000.0f;

    float acc[8][8];
    #pragma unroll
    for (int r = 0; r < 8; r++)
        #pragma unroll
        for (int jj = 0; jj < 8; jj++) acc[r][jj] = 0.f;

    const int r0 = w * 8;
    for (int d = 0; d < 64; d++) {
        float kr[8];
        #pragma unroll
        for (int jj = 0; jj < 8; jj++) kr[jj] = Ks[d * 257 + lane + 32 * jj];
        #pragma unroll
        for (int r = 0; r < 8; r++) {
            float qv = Qs[(r0 + r) * 64 + d];
            #pragma unroll
            for (int jj = 0; jj < 8; jj++) acc[r][jj] = fmaf(qv, kr[jj], acc[r][jj]);
        }
    }

    #pragma unroll
    for (int r = 0; r < 8; r++) {
        float mx = -3.0e38f;
        #pragma unroll
        for (int jj = 0; jj < 8; jj++) {
            float s = acc[r][jj] * 0.125f + extr[jj];
            acc[r][jj] = s;
            mx = fmaxf(mx, s);
        }
        #pragma unroll
        for (int o = 16; o; o >>= 1) mx = fmaxf(mx, __shfl_xor_sync(0xffffffffu, mx, o));
        float sum = 0.f;
        #pragma unroll
        for (int jj = 0; jj < 8; jj++) { float e = expf(acc[r][jj] - mx); acc[r][jj] = e; sum += e; }
        #pragma unroll
        for (int o = 16; o; o >>= 1) sum += __shfl_xor_sync(0xffffffffu, sum, o);
        float rinv = 1.0f / sum;
        int i = r0 + r;
        float* ar = asum + (((size_t)(b * NH + h)) * NS + (i0 + i)) * NS;
        #pragma unroll
        for (int jj = 0; jj < 8; jj++) {
            float p = acc[r][jj] * rinv;
            int j = lane + 32 * jj;
            Ss[i * 256 + j] = p;
            ar[j] = accum ? (ar[j] + p * wgt) : (p * wgt);
        }
    }
    __syncwarp();

    float c0[8], c1[8];
    #pragma unroll
    for (int r = 0; r < 8; r++) { c0[r] = 0.f; c1[r] = 0.f; }
    for (int j = 0; j < 256; j++) {
        float v0 = Vs[j * 64 + lane];
        float v1 = Vs[j * 64 + lane + 32];
        #pragma unroll
        for (int r = 0; r < 8; r++) {
            float p = Ss[(r0 + r) * 256 + j];
            c0[r] = fmaf(p, v0, c0[r]);
            c1[r] = fmaf(p, v1, c1[r]);
        }
    }
    #pragma unroll
    for (int r = 0; r < 8; r++) {
        size_t base = ((size_t)b * NS + i0 + r0 + r) * ND + h * NDH;
        u16 hh, mm, ll;
        split3(c0[r], hh, mm, ll);
        ctxP[base + lane] = hh;
        ctxP[PLsz + base + lane] = mm;
        ctxP[2 * PLsz + base + lane] = ll;
        split3(c1[r], hh, mm, ll);
        ctxP[base + lane + 32] = hh;
        ctxP[PLsz + base + lane + 32] = mm;
        ctxP[2 * PLsz + base + lane + 32] = ll;
    }
}

// ---------------- fused: residual + 4 split-K partials + bias + LN + splits -----
__global__ __launch_bounds__(256) void add_ln4_kernel(
    const float* __restrict__ x, const float* __restrict__ part,
    const float* __restrict__ gbias,
    const float* __restrict__ g, const float* __restrict__ bb,
    float* __restrict__ out, u16* __restrict__ outP)
{
    __shared__ float redA[8], redB[8];
    const int row = blockIdx.x, tid = threadIdx.x;
    const size_t base = (size_t)row * ND;
    const size_t slab = (size_t)PLsz;
    float s[3];
    #pragma unroll
    for (int e = 0; e < 3; e++) {
        int col = tid + 256 * e;
        size_t idx = base + col;
        s[e] = x[idx] + part[idx] + part[idx + slab] + part[idx + 2 * slab]
             + part[idx + 3 * slab] + gbias[col];
    }
    float mean = blk_sum(s[0] + s[1] + s[2], redA, tid) * (1.0f / 768.0f);
    float d0 = s[0] - mean, d1 = s[1] - mean, d2 = s[2] - mean;
    float var = blk_sum(d0 * d0 + d1 * d1 + d2 * d2, redB, tid) * (1.0f / 768.0f);
    float rstd = 1.0f / sqrtf(var + 1e-12f);
    float dd[3] = {d0, d1, d2};
    #pragma unroll
    for (int e = 0; e < 3; e++) {
        int col = tid + 256 * e;
        float v = g[col] * dd[e] * rstd + bb[col];
        out[base + col] = v;
        u16 h, m, l; split3(v, h, m, l);
        outP[base + col] = h;
        outP[PLsz + base + col] = m;
        outP[2 * PLsz + base + col] = l;
    }
}

// ---------------- fused: residual + 4 partials + bias + LN + IF spike -----------
__global__ __launch_bounds__(256) void add_ln_spike4_kernel(
    const float* __restrict__ x, const float* __restrict__ part,
    const float* __restrict__ gbias,
    const float* __restrict__ g, const float* __restrict__ bb,
    float* __restrict__ mem, float* __restrict__ cnt,
    float* __restrict__ prev, u16* __restrict__ prevP,
    float invt, float* __restrict__ zout, int first, float* __restrict__ curout)
{
    __shared__ float redA[8], redB[8];
    const int row = blockIdx.x, tid = threadIdx.x;
    const size_t base = (size_t)row * ND;
    const size_t slab = (size_t)PLsz;
    float s[3];
    #pragma unroll
    for (int e = 0; e < 3; e++) {
        int col = tid + 256 * e;
        size_t idx = base + col;
        s[e] = x[idx] + part[idx] + part[idx + slab] + part[idx + 2 * slab]
             + part[idx + 3 * slab] + gbias[col];
    }
    float mean = blk_sum(s[0] + s[1] + s[2], redA, tid) * (1.0f / 768.0f);
    float d0 = s[0] - mean, d1 = s[1] - mean, d2 = s[2] - mean;
    float var = blk_sum(d0 * d0 + d1 * d1 + d2 * d2, redB, tid) * (1.0f / 768.0f);
    float rstd = 1.0f / sqrtf(var + 1e-12f);
    float dd[3] = {d0, d1, d2};

    #pragma unroll
    for (int e = 0; e < 3; e++) {
        int col = tid + 256 * e;
        size_t idx = base + col;
        float cur = g[col] * dd[e] * rstd + bb[col];
        if (curout) {
            curout[idx] = cur;
        } else {
            float m = (first ? 0.0f : mem[idx]) + cur;
            float spk = (m >= 1.0f) ? 1.0f : 0.0f;
            mem[idx] = m - spk;
            float cn = (first ? 0.0f : cnt[idx]) + spk;
            cnt[idx] = cn;
            float pv = cn * invt;
            prev[idx] = pv;
            u16 h, mm, l; split3(pv, h, mm, l);
            prevP[idx] = h;
            prevP[PLsz + idx] = mm;
            prevP[2 * PLsz + idx] = l;
            if (zout) zout[idx] = pv;
        }
    }
}

// ---------------- launch ----------------
extern "C" void kernel_launch(void* const* d_in, const int* in_sizes, int n_in,
                              void* d_out, int out_size)
{
    const float* u    = (const float*)d_in[0];
    const int*   seg  = (const int*)d_in[1];
    const float* mask = (const float*)d_in[2];
    const float* semb = (const float*)d_in[3];
    const float* Wq   = (const float*)d_in[4];  const float* bq = (const float*)d_in[5];
    const float* Wk   = (const float*)d_in[6];  const float* bk = (const float*)d_in[7];
    const float* Wv   = (const float*)d_in[8];  const float* bv = (const float*)d_in[9];
    const float* Wo   = (const float*)d_in[10]; const float* bo = (const float*)d_in[11];
    const float* ln1g = (const float*)d_in[12]; const float* ln1b = (const float*)d_in[13];
    const float* W1   = (const float*)d_in[14]; const float* b1 = (const float*)d_in[15];
    const float* W2   = (const float*)d_in[16]; const float* b2 = (const float*)d_in[17];
    const float* ln2g = (const float*)d_in[18]; const float* ln2b = (const float*)d_in[19];
    // d_in[20] = time_step (always 6)

    float* out  = (float*)d_out;
    float* z    = out;
    float* attn = out + (size_t)5 * PLsz;

    void* p;
    #define FSYM(var, sym) cudaGetSymbolAddress(&p, sym); float* var = (float*)p
    #define USYM(var, sym) cudaGetSymbolAddress(&p, sym); u16* var = (u16*)p
    #define WSYM(var, sym) cudaGetSymbolAddress(&p, sym); u32* var = (u32*)p
    FSYM(xin,  g_xin);  FSYM(prev, g_prev); FSYM(x1, g_x1);
    FSYM(qkv,  g_qkv);  FSYM(aout, g_aout); FSYM(fout, g_fout);
    FSYM(cur0, g_cur0); FSYM(mem,  g_mem);  FSYM(cnt,  g_cnt);
    FSYM(bqkv, g_bqkv);
    USYM(xinP, g_xinP); USYM(prevP, g_prevP); USYM(x1P, g_x1P);
    USYM(ctxP, g_ctxP); USYM(ffhP, g_ffhP);
    WSYM(wqkvP, g_wqkvP); WSYM(woP, g_woP); WSYM(w1P, g_w1P); WSYM(w2P, g_w2P);
    #undef FSYM
    #undef USYM
    #undef WSYM

    cudaFuncSetAttribute(attn_kernel, cudaFuncAttributeMaxDynamicSharedMemorySize,
                         ATTN_SMEM_FLOATS * 4);

    // weight prep
    for (int l = 0; l < NL; l++) {
        pack_qkvw_kernel<<<QKV_KN2 / 256, 256>>>(
            Wq + (size_t)l * ND * ND, Wk + (size_t)l * ND * ND, Wv + (size_t)l * ND * ND,
            wqkvP + ((size_t)l * 3 + 0) * QKV_KN2,
            wqkvP + ((size_t)l * 3 + 1) * QKV_KN2,
            wqkvP + ((size_t)l * 3 + 2) * QKV_KN2);
        pack_w_kernel<<<WO_KN2 / 256, 256>>>(
            Wo + (size_t)l * ND * ND,
            woP + ((size_t)l * 3 + 0) * WO_KN2,
            woP + ((size_t)l * 3 + 1) * WO_KN2,
            woP + ((size_t)l * 3 + 2) * WO_KN2, ND, ND);
        pack_w_kernel<<<W1_KN2 / 256, 256>>>(
            W1 + (size_t)l * ND * NF,
            w1P + ((size_t)l * 3 + 0) * W1_KN2,
            w1P + ((size_t)l * 3 + 1) * W1_KN2,
            w1P + ((size_t)l * 3 + 2) * W1_KN2, ND, NF);
        pack_w_kernel<<<W2_KN2 / 256, 256>>>(
            W2 + (size_t)l * NF * ND,
            w2P + ((size_t)l * 3 + 0) * W2_KN2,
            w2P + ((size_t)l * 3 + 1) * W2_KN2,
            w2P + ((size_t)l * 3 + 2) * W2_KN2, NF, ND);
    }
    biasqkv_kernel<<<(NL * N3 + 255) / 256, 256>>>(bq, bk, bv);
    xin_kernel<<<(NR * ND) / 256, 256>>>(u, seg, semb, z);

    const dim3 gQKV(N3 / 128, NR / 64, 1);   // 18x16
    const dim3 gO  (ND / 128, NR / 64, 4);   // split-K4, klen=192
    const dim3 gF1 (NF / 128, NR / 64, 1);   // 24x16
    const dim3 gF2 (ND / 128, NR / 64, 4);   // split-K4, klen=768
    const dim3 gAttn(4, NH, NB);
    const float inv6 = 1.0f / 6.0f;

    // GEMM_F with EXPLICIT A-plane stride
    #define GEMM_F(grid, A, Astr, B, bias_, C_, Nv, Kv, kl) \
        gemm_bf<<<grid, 256>>>(A, A + (size_t)(Astr), A + 2 * (size_t)(Astr), \
            B, B + (size_t)(Kv)*(Nv)/2, B + (size_t)2*(Kv)*(Nv)/2, \
            bias_, C_, 0, 0, 0, Nv, Kv, kl, 0)

    // ---- layer 0: block output constant across time; compute once ----
    {
        GEMM_F(gQKV, xinP, PLsz, wqkvP, bqkv, qkv, N3, ND, ND);
        attn_kernel<<<gAttn, 256, ATTN_SMEM_FLOATS * 4>>>(qkv, mask, attn, ctxP, 1.0f, 0);
        GEMM_F(gO, ctxP, PLsz, woP, (const float*)0, aout, ND, ND, ND / 4);
        add_ln4_kernel<<<NR, 256>>>(xin, aout, bo, ln1g, ln1b, x1, x1P);
        gemm_bf<<<gF1, 256>>>(x1P, x1P + PLsz, x1P + 2 * PLsz,
            w1P, w1P + W1_KN2, w1P + 2 * W1_KN2, b1,
            0, ffhP, ffhP + FFsz, ffhP + 2 * FFsz, NF, ND, ND, 1);
        GEMM_F(gF2, ffhP, FFsz, w2P, (const float*)0, fout, ND, NF, NF / 4);
        add_ln_spike4_kernel<<<NR, 256>>>(x1, fout, b2, ln2g, ln2b,
            0, 0, 0, 0, 0.f, 0, 0, cur0);
    }

    for (int t = 0; t < NT; t++) {
        float tp1 = (float)(t + 1);
        float invt = 1.0f / tp1;
        rate0_kernel<<<(NR * ND) / 256, 256>>>(tp1,
            (t == NT - 1) ? (z + (size_t)1 * PLsz) : (float*)0);

        for (int l = 1; l < NL; l++) {
            gemm_bf<<<gQKV, 256>>>(prevP, prevP + PLsz, prevP + 2 * PLsz,
                wqkvP + ((size_t)l * 3 + 0) * QKV_KN2,
                wqkvP + ((size_t)l * 3 + 1) * QKV_KN2,
                wqkvP + ((size_t)l * 3 + 2) * QKV_KN2,
                bqkv + l * N3, qkv, 0, 0, 0, N3, ND, ND, 0);
            attn_kernel<<<gAttn, 256, ATTN_SMEM_FLOATS * 4>>>(
                qkv, mask, attn + (size_t)l * NB * NH * NS * NS, ctxP,
                inv6, (t > 0) ? 1 : 0);
            gemm_bf<<<gO, 256>>>(ctxP, ctxP + PLsz, ctxP + 2 * PLsz,
                woP + ((size_t)l * 3 + 0) * WO_KN2,
                woP + ((size_t)l * 3 + 1) * WO_KN2,
                woP + ((size_t)l * 3 + 2) * WO_KN2,
                (const float*)0, aout, 0, 0, 0, ND, ND, ND / 4, 0);
            add_ln4_kernel<<<NR, 256>>>(prev, aout, bo + l * ND,
                ln1g + l * ND, ln1b + l * ND, x1, x1P);
            gemm_bf<<<gF1, 256>>>(x1P, x1P + PLsz, x1P + 2 * PLsz,
                w1P + ((size_t)l * 3 + 0) * W1_KN2,
                w1P + ((size_t)l * 3 + 1) * W1_KN2,
                w1P + ((size_t)l * 3 + 2) * W1_KN2,
                b1 + l * NF, 0, ffhP, ffhP + FFsz, ffhP + 2 * FFsz, NF, ND, ND, 1);
            gemm_bf<<<gF2, 256>>>(ffhP, ffhP + FFsz, ffhP + 2 * FFsz,
                w2P + ((size_t)l * 3 + 0) * W2_KN2,
                w2P + ((size_t)l * 3 + 1) * W2_KN2,
                w2P + ((size_t)l * 3 + 2) * W2_KN2,
                (const float*)0, fout, 0, 0, 0, ND, NF, NF / 4, 0);
            add_ln_spike4_kernel<<<NR, 256>>>(x1, fout, b2 + l * ND,
                ln2g + l * ND, ln2b + l * ND,
                mem + (size_t)l * PLsz, cnt + (size_t)l * PLsz,
                prev, prevP, invt,
                (t == NT - 1) ? (z + (size_t)(1 + l) * PLsz) : (float*)0,
                (t == 0) ? 1 : 0, 0);
        }
    }
    #undef GEMM_F
}

// round 12
// speedup vs baseline: 1.7306x; 1.2045x over previous
#include <cuda_runtime.h>
#include <cuda_bf16.h>
#include <math.h>

#define NB 4
#define NS 256
#define ND 768
#define NF 3072
#define NL 4
#define NH 12
#define NDH 64
#define NR (NB*NS)   /* 1024 rows */
#define NT 6
#define N3 (3*ND)    /* 2304 */

typedef unsigned int u32;
typedef unsigned short u16;

#define PLsz (NR*ND)
#define FFsz (NR*NF)

// ---------------- scratch (static device globals; no allocs) ----------------
static __device__ float g_xin [PLsz];
static __device__ float g_prev[PLsz];
static __device__ float g_x1  [PLsz];
static __device__ float g_qkv [NR*N3];
static __device__ float g_aout[4*PLsz];
static __device__ float g_fout[4*PLsz];
static __device__ float g_cur0[PLsz];
static __device__ float g_mem [NL*PLsz];
static __device__ float g_cnt [NL*PLsz];
static __device__ float g_bqkv[NL*N3];

// bf16 activation planes
static __device__ u16 g_xinP [3*PLsz];
static __device__ u16 g_cntP [PLsz];      // QUANTIZED spike counts (exact single plane)
static __device__ u16 g_x1P  [3*PLsz];
static __device__ u16 g_ctxP [3*PLsz];
static __device__ u16 g_ffhP [3*FFsz];

// fragment-packed weights (u32 = bf16 pair): [l][plane][K*N/2]
#define QKV_KN2 (ND*N3/2)
#define WO_KN2  (ND*ND/2)
#define W1_KN2  (ND*NF/2)
#define W2_KN2  (NF*ND/2)
static __device__ u32 g_wqkvP[NL*3*QKV_KN2];
static __device__ u32 g_woP  [NL*3*WO_KN2];
static __device__ u32 g_w1P  [NL*3*W1_KN2];
static __device__ u32 g_w2P  [NL*3*W2_KN2];

// ---------------- helpers ----------------
__device__ __forceinline__ void split3(float a, u16& h, u16& m, u16& l) {
    __nv_bfloat16 bh = __float2bfloat16_rn(a);
    float r1 = a - __bfloat162float(bh);
    __nv_bfloat16 bm = __float2bfloat16_rn(r1);
    float r2 = r1 - __bfloat162float(bm);
    __nv_bfloat16 bl = __float2bfloat16_rn(r2);
    h = reinterpret_cast<u16&>(bh);
    m = reinterpret_cast<u16&>(bm);
    l = reinterpret_cast<u16&>(bl);
}

__device__ __forceinline__ float gelu_f(float x) {
    float x3 = x * x * x;
    float t = tanhf(0.7978845608028654f * (x + 0.044715f * x3));
    return 0.5f * x * (1.0f + t);
}

__device__ __forceinline__ float blk_sum(float v, volatile float* red, int tid) {
    #pragma unroll
    for (int o = 16; o; o >>= 1) v += __shfl_xor_sync(0xffffffffu, v, o);
    if ((tid & 31) == 0) red[tid >> 5] = v;
    __syncthreads();
    float tot = 0.f;
    #pragma unroll
    for (int i = 0; i < 8; i++) tot += red[i];
    return tot;
}

__device__ __forceinline__ void mmabf(float* c, const uint4 a, const uint2 b) {
    asm volatile(
        "mma.sync.aligned.m16n8k16.row.col.f32.bf16.bf16.f32 "
        "{%0,%1,%2,%3},{%4,%5,%6,%7},{%8,%9},{%0,%1,%2,%3};"
        : "+f"(c[0]), "+f"(c[1]), "+f"(c[2]), "+f"(c[3])
        : "r"(a.x), "r"(a.y), "r"(a.z), "r"(a.w), "r"(b.x), "r"(b.y));
}

// ---------------- all-layer weight packing into B-fragment layout ----------------
// frag math: u32 pos r = ((kc*(N/8)+nt)*32+ln)*2+j -> k = kc*16+(ln&3)*2+j*8, n = nt*8+(ln>>2)
__global__ __launch_bounds__(256) void pack_w_all(
    const float* __restrict__ W, u32* __restrict__ base, int K, int N)
{
    int pos = blockIdx.x * 256 + threadIdx.x;
    const int KN2 = K * N / 2;
    if (pos >= NL * KN2) return;
    int l = pos / KN2, r = pos - l * KN2;
    int perchunk = N * 8;
    int kc = r / perchunk;
    int rem = r - kc * perchunk;
    int nt = rem >> 6;
    int r2 = rem & 63;
    int ln = r2 >> 1, j = r2 & 1;
    int k = kc * 16 + (ln & 3) * 2 + j * 8;
    int n = nt * 8 + (ln >> 2);
    const float* Wl = W + (size_t)l * K * N;
    float w0 = Wl[(size_t)k * N + n];
    float w1 = Wl[(size_t)(k + 1) * N + n];
    u16 h0, m0, l0, h1, m1, l1;
    split3(w0, h0, m0, l0);
    split3(w1, h1, m1, l1);
    size_t b0 = ((size_t)l * 3 + 0) * KN2 + r;
    size_t b1 = ((size_t)l * 3 + 1) * KN2 + r;
    size_t b2 = ((size_t)l * 3 + 2) * KN2 + r;
    base[b0] = (u32)h0 | ((u32)h1 << 16);
    base[b1] = (u32)m0 | ((u32)m1 << 16);
    base[b2] = (u32)l0 | ((u32)l1 << 16);
}

// all-layer q|k|v pack (logical [768,2304]) + bias fold
__global__ __launch_bounds__(256) void pack_qkvw_all(
    const float* __restrict__ Wq, const float* __restrict__ Wk, const float* __restrict__ Wv,
    const float* __restrict__ bq, const float* __restrict__ bk, const float* __restrict__ bv)
{
    int pos = blockIdx.x * 256 + threadIdx.x;
    if (pos < NL * N3) {
        int l = pos / N3, n = pos - l * N3;
        int which = n / ND, nn = n - which * ND;
        const float* b = (which == 0) ? bq : (which == 1) ? bk : bv;
        g_bqkv[pos] = b[l * ND + nn];
    }
    if (pos >= NL * QKV_KN2) return;
    int l = pos / QKV_KN2, r = pos - l * QKV_KN2;
    const int N = N3;
    int perchunk = N * 8;
    int kc = r / perchunk;
    int rem = r - kc * perchunk;
    int nt = rem >> 6;
    int r2 = rem & 63;
    int ln = r2 >> 1, j = r2 & 1;
    int k = kc * 16 + (ln & 3) * 2 + j * 8;
    int n = nt * 8 + (ln >> 2);
    int which = n / ND, nn = n - which * ND;
    const float* W = ((which == 0) ? Wq : (which == 1) ? Wk : Wv) + (size_t)l * ND * ND;
    float w0 = W[(size_t)k * ND + nn];
    float w1 = W[(size_t)(k + 1) * ND + nn];
    u16 h0, m0, l0, h1, m1, l1;
    split3(w0, h0, m0, l0);
    split3(w1, h1, m1, l1);
    g_wqkvP[((size_t)l * 3 + 0) * QKV_KN2 + r] = (u32)h0 | ((u32)h1 << 16);
    g_wqkvP[((size_t)l * 3 + 1) * QKV_KN2 + r] = (u32)m0 | ((u32)m1 << 16);
    g_wqkvP[((size_t)l * 3 + 2) * QKV_KN2 + r] = (u32)l0 | ((u32)l1 << 16);
}

// ---------------- x_in = u + seg_emb[segment_ids]; z[0]; splits ----------------
__global__ __launch_bounds__(256) void xin_kernel(
    const float* __restrict__ u, const int* __restrict__ seg,
    const float* __restrict__ semb, float* __restrict__ z0)
{
    int idx = blockIdx.x * 256 + threadIdx.x;
    int srow = idx / ND;
    int d = idx - srow * ND;
    float val = u[idx] + semb[seg[srow] * ND + d];
    g_xin[idx] = val;
    z0[idx] = val;
    u16 h, m, l; split3(val, h, m, l);
    g_xinP[idx] = h; g_xinP[PLsz + idx] = m; g_xinP[2 * PLsz + idx] = l;
}

// ---------------- layer-0 closed-form spike rate (cnt is exact small int) -------
__global__ __launch_bounds__(256) void rate0_kernel(float tplus1, float* __restrict__ zout)
{
    int idx = blockIdx.x * 256 + threadIdx.x;
    float c = g_cur0[idx];
    float f = floorf(tplus1 * c);
    f = fminf(fmaxf(f, 0.0f), tplus1);
    float r = f / tplus1;
    g_prev[idx] = r;
    __nv_bfloat16 cb = __float2bfloat16_rn(f);   // integer <= 6: exact
    g_cntP[idx] = reinterpret_cast<u16&>(cb);
    if (zout) zout[idx] = r;
}

// ---------------- bf16-split tensor-core GEMM (templated term count) ------------
// SA=0: A is 3 planes, 6 terms (hh | hm,mh,mm,hl,lh). Dropped ml,lm ~2^-24 random-sign.
// SA=1: A is 1 EXACT plane (integer cnt), 3 terms (a*bh | a*bm, a*bl); oscale applied
//       in epilogue (qkv = (cnt@W)*1/(t+1) + bias).
// Per-chunk zeroed MMA accumulators drained into IEEE fp32 (R11 truncation fix).
template<int SA>
__global__ __launch_bounds__(256, 2) void gemm_bf(
    const u16* __restrict__ A0, const u16* __restrict__ A1, const u16* __restrict__ A2,
    const u32* __restrict__ B0, const u32* __restrict__ B1, const u32* __restrict__ B2,
    const float* __restrict__ bias, float oscale,
    float* __restrict__ Cf, u16* __restrict__ C0, u16* __restrict__ C1, u16* __restrict__ C2,
    int N, int K, int klen, int do_gelu)
{
    __shared__ __align__(16) u32 AF[2][1536];
    __shared__ __align__(16) u32 BF[2][3072];

    const int bx = blockIdx.x, by = blockIdx.y, bz = blockIdx.z;
    const int tid = threadIdx.x, lane = tid & 31, wid = tid >> 5;
    const int wm = wid >> 2, wn = wid & 3;
    const int K2 = K >> 1, N8 = N >> 3;
    const int NAS = (SA ? 2 : 6);   // A producer slots per thread

    const u32* apln[3] = {(const u32*)A0, (const u32*)A1, (const u32*)A2};
    const u32* ap[6];
    #pragma unroll
    for (int s = 0; s < NAS; s++) {
        int idx = s * 256 + tid;
        int j = idx & 3, ln = (idx >> 2) & 31, mt = (idx >> 7) & 3, pl = idx >> 9;
        int row = by * 64 + mt * 16 + (ln >> 2) + (j & 1) * 8;
        int c2 = (ln & 3) + (j >> 1) * 4;
        ap[s] = apln[pl] + (size_t)row * K2 + ((bz * klen) >> 1) + c2;
    }
    const u32* bpln[3] = {B0, B1, B2};
    const u32* bp[3];
    #pragma unroll
    for (int s = 0; s < 3; s++) {
        int idx4 = s * 256 + tid;
        int pl = idx4 >> 8, rem4 = idx4 & 255;
        int ntl = rem4 >> 4, lnp = (rem4 & 15) * 2;
        size_t goff = ((size_t)(((bz * klen) >> 4) * N8 + bx * 16 + ntl) * 32 + lnp) * 2;
        bp[s] = bpln[pl] + goff;
    }
    const size_t bstep = (size_t)N * 8;

    float acc[8][4];
    #pragma unroll
    for (int i = 0; i < 8; i++)
        #pragma unroll
        for (int j = 0; j < 4; j++) acc[i][j] = 0.f;

    const int nkt = klen >> 4;

    #pragma unroll
    for (int s = 0; s < NAS; s++) AF[0][s * 256 + tid] = ap[s][0];
    #pragma unroll
    for (int s = 0; s < 3; s++) *(uint4*)&BF[0][(s * 256 + tid) * 4] = *(const uint4*)bp[s];
    __syncthreads();

    u32 va[6]; uint4 vb[3];
    for (int kt = 0; kt < nkt; kt++) {
        const int cur = kt & 1;
        const bool more = (kt + 1 < nkt);
        if (more) {
            #pragma unroll
            for (int s = 0; s < NAS; s++) va[s] = ap[s][(kt + 1) * 8];
            #pragma unroll
            for (int s = 0; s < 3; s++) vb[s] = *(const uint4*)(bp[s] + (size_t)(kt + 1) * bstep);
        }

        uint4 aH[2], aM[2], aL[2];
        #pragma unroll
        for (int m2 = 0; m2 < 2; m2++) {
            int mt = wm * 2 + m2;
            aH[m2] = *(const uint4*)&AF[cur][(mt * 32 + lane) * 4];
            if (SA == 0) {
                aM[m2] = *(const uint4*)&AF[cur][((4 + mt) * 32 + lane) * 4];
                aL[m2] = *(const uint4*)&AF[cur][((8 + mt) * 32 + lane) * 4];
            }
        }
        #pragma unroll
        for (int n2 = 0; n2 < 4; n2++) {
            int nt = wn * 4 + n2;
            uint2 bH = *(const uint2*)&BF[cur][(nt * 32 + lane) * 2];
            uint2 bM = *(const uint2*)&BF[cur][1024 + (nt * 32 + lane) * 2];
            uint2 bL = *(const uint2*)&BF[cur][2048 + (nt * 32 + lane) * 2];
            #pragma unroll
            for (int m2 = 0; m2 < 2; m2++) {
                float cS[4] = {0.f, 0.f, 0.f, 0.f};
                float cB[4] = {0.f, 0.f, 0.f, 0.f};
                if (SA == 1) {
                    mmabf(cS, aH[m2], bL);
                    mmabf(cS, aH[m2], bM);
                    mmabf(cB, aH[m2], bH);
                } else {
                    mmabf(cS, aM[m2], bM);   // ~2^-16 terms first
                    mmabf(cS, aH[m2], bL);
                    mmabf(cS, aL[m2], bH);
                    mmabf(cS, aM[m2], bH);   // ~2^-8
                    mmabf(cS, aH[m2], bM);
                    mmabf(cB, aH[m2], bH);   // dominant, own accumulator
                }
                float* c = acc[m2 * 4 + n2];
                #pragma unroll
                for (int q = 0; q < 4; q++) c[q] += cB[q] + cS[q];
            }
        }

        if (more) {
            const int nx = cur ^ 1;
            #pragma unroll
            for (int s = 0; s < NAS; s++) AF[nx][s * 256 + tid] = va[s];
            #pragma unroll
            for (int s = 0; s < 3; s++) *(uint4*)&BF[nx][(s * 256 + tid) * 4] = vb[s];
        }
        __syncthreads();
    }

    float* Cp = Cf;
    if (Cp && gridDim.z > 1) Cp += (size_t)bz * ((size_t)NR * N);

    #pragma unroll
    for (int m2 = 0; m2 < 2; m2++)
        #pragma unroll
        for (int n2 = 0; n2 < 4; n2++) {
            float* c = acc[m2 * 4 + n2];
            int row = by * 64 + wm * 32 + m2 * 16 + (lane >> 2);
            int col = bx * 128 + wn * 32 + n2 * 8 + (lane & 3) * 2;
            float o0 = c[0] * oscale, o1 = c[1] * oscale,
                  o2 = c[2] * oscale, o3 = c[3] * oscale;
            if (bias) {
                float bb0 = bias[col], bb1 = bias[col + 1];
                o0 += bb0; o1 += bb1; o2 += bb0; o3 += bb1;
            }
            if (do_gelu) { o0 = gelu_f(o0); o1 = gelu_f(o1); o2 = gelu_f(o2); o3 = gelu_f(o3); }
            if (C0) {
                u16 h0, m0, l0, h1, m1, l1;
                split3(o0, h0, m0, l0); split3(o1, h1, m1, l1);
                size_t p = ((size_t)row * N + col) >> 1;
                ((u32*)C0)[p] = (u32)h0 | ((u32)h1 << 16);
                ((u32*)C1)[p] = (u32)m0 | ((u32)m1 << 16);
                ((u32*)C2)[p] = (u32)l0 | ((u32)l1 << 16);
                split3(o2, h0, m0, l0); split3(o3, h1, m1, l1);
                p = ((size_t)(row + 8) * N + col) >> 1;
                ((u32*)C0)[p] = (u32)h0 | ((u32)h1 << 16);
                ((u32*)C1)[p] = (u32)m0 | ((u32)m1 << 16);
                ((u32*)C2)[p] = (u32)l0 | ((u32)l1 << 16);
            } else {
                *(float2*)&Cp[(size_t)row * N + col] = make_float2(o0, o1);
                *(float2*)&Cp[(size_t)(row + 8) * N + col] = make_float2(o2, o3);
            }
        }
}

// ---------------- fused attention; ctx -> 3 bf16 planes ----------------
#define ATTN_SMEM_FLOATS (64*257 + 256*64 + 64*256 + 64*64)

__global__ __launch_bounds__(256) void attn_kernel(
    const float* __restrict__ qkv, const float* __restrict__ mask,
    float* __restrict__ asum, u16* __restrict__ ctxP,
    float wgt, int accum)
{
    extern __shared__ float smf[];
    float* Ks = smf;                    // [64][257]
    float* Vs = smf + 64 * 257;         // [256][64]
    float* Ss = Vs + 256 * 64;          // [64][256]
    float* Qs = Ss + 64 * 256;          // [64][64]

    const int rb = blockIdx.x, h = blockIdx.y, b = blockIdx.z;
    const int tid = threadIdx.x;
    const int lane = tid & 31, w = tid >> 5;
    const int i0 = rb * 64;
    const int dq = (tid & 15) * 4;
    const int jb = tid >> 4;

    const float* qb = qkv + ((size_t)b * NS + i0) * N3 + h * NDH;
    const float* kb = qkv + (size_t)b * NS * N3 + ND + h * NDH;
    const float* vb = qkv + (size_t)b * NS * N3 + 2 * ND + h * NDH;

    #pragma unroll
    for (int it = 0; it < 16; it++) {
        int j = jb + it * 16;
        float4 kv = *(const float4*)(kb + (size_t)j * N3 + dq);
        Ks[(dq + 0) * 257 + j] = kv.x;
        Ks[(dq + 1) * 257 + j] = kv.y;
        Ks[(dq + 2) * 257 + j] = kv.z;
        Ks[(dq + 3) * 257 + j] = kv.w;
        float4 vv = *(const float4*)(vb + (size_t)j * N3 + dq);
        *(float4*)&Vs[j * 64 + dq] = vv;
    }
    #pragma unroll
    for (int it = 0; it < 4; it++) {
        int i = jb + it * 16;
        float4 qv = *(const float4*)(qb + (size_t)i * N3 + dq);
        *(float4*)&Qs[i * 64 + dq] = qv;
    }
    __syncthreads();

    float extr[8];
    #pragma unroll
    for (int jj = 0; jj < 8; jj++)
        extr[jj] = (1.0f - mask[b * NS + lane + 32 * jj]) * -10000.0f;

    float acc[8][8];
    #pragma unroll
    for (int r = 0; r < 8; r++)
        #pragma unroll
        for (int jj = 0; jj < 8; jj++) acc[r][jj] = 0.f;

    const int r0 = w * 8;
    for (int d = 0; d < 64; d++) {
        float kr[8];
        #pragma unroll
        for (int jj = 0; jj < 8; jj++) kr[jj] = Ks[d * 257 + lane + 32 * jj];
        #pragma unroll
        for (int r = 0; r < 8; r++) {
            float qv = Qs[(r0 + r) * 64 + d];
            #pragma unroll
            for (int jj = 0; jj < 8; jj++) acc[r][jj] = fmaf(qv, kr[jj], acc[r][jj]);
        }
    }

    #pragma unroll
    for (int r = 0; r < 8; r++) {
        float mx = -3.0e38f;
        #pragma unroll
        for (int jj = 0; jj < 8; jj++) {
            float s = acc[r][jj] * 0.125f + extr[jj];
            acc[r][jj] = s;
            mx = fmaxf(mx, s);
        }
        #pragma unroll
        for (int o = 16; o; o >>= 1) mx = fmaxf(mx, __shfl_xor_sync(0xffffffffu, mx, o));
        float sum = 0.f;
        #pragma unroll
        for (int jj = 0; jj < 8; jj++) { float e = expf(acc[r][jj] - mx); acc[r][jj] = e; sum += e; }
        #pragma unroll
        for (int o = 16; o; o >>= 1) sum += __shfl_xor_sync(0xffffffffu, sum, o);
        float rinv = 1.0f / sum;
        int i = r0 + r;
        float* ar = asum + (((size_t)(b * NH + h)) * NS + (i0 + i)) * NS;
        #pragma unroll
        for (int jj = 0; jj < 8; jj++) {
            float p = acc[r][jj] * rinv;
            int j = lane + 32 * jj;
            Ss[i * 256 + j] = p;
            ar[j] = accum ? (ar[j] + p * wgt) : (p * wgt);
        }
    }
    __syncwarp();

    float c0[8], c1[8];
    #pragma unroll
    for (int r = 0; r < 8; r++) { c0[r] = 0.f; c1[r] = 0.f; }
    for (int j = 0; j < 256; j++) {
        float v0 = Vs[j * 64 + lane];
        float v1 = Vs[j * 64 + lane + 32];
        #pragma unroll
        for (int r = 0; r < 8; r++) {
            float p = Ss[(r0 + r) * 256 + j];
            c0[r] = fmaf(p, v0, c0[r]);
            c1[r] = fmaf(p, v1, c1[r]);
        }
    }
    #pragma unroll
    for (int r = 0; r < 8; r++) {
        size_t base = ((size_t)b * NS + i0 + r0 + r) * ND + h * NDH;
        u16 hh, mm, ll;
        split3(c0[r], hh, mm, ll);
        ctxP[base + lane] = hh;
        ctxP[PLsz + base + lane] = mm;
        ctxP[2 * PLsz + base + lane] = ll;
        split3(c1[r], hh, mm, ll);
        ctxP[base + lane + 32] = hh;
        ctxP[PLsz + base + lane + 32] = mm;
        ctxP[2 * PLsz + base + lane + 32] = ll;
    }
}

// ---------------- fused: residual + 4 split-K partials + bias + LN + splits -----
__global__ __launch_bounds__(256) void add_ln4_kernel(
    const float* __restrict__ x, const float* __restrict__ part,
    const float* __restrict__ gbias,
    const float* __restrict__ g, const float* __restrict__ bb,
    float* __restrict__ out, u16* __restrict__ outP)
{
    __shared__ float redA[8], redB[8];
    const int row = blockIdx.x, tid = threadIdx.x;
    const size_t base = (size_t)row * ND;
    const size_t slab = (size_t)PLsz;
    float s[3];
    #pragma unroll
    for (int e = 0; e < 3; e++) {
        int col = tid + 256 * e;
        size_t idx = base + col;
        s[e] = x[idx] + part[idx] + part[idx + slab] + part[idx + 2 * slab]
             + part[idx + 3 * slab] + gbias[col];
    }
    float mean = blk_sum(s[0] + s[1] + s[2], redA, tid) * (1.0f / 768.0f);
    float d0 = s[0] - mean, d1 = s[1] - mean, d2 = s[2] - mean;
    float var = blk_sum(d0 * d0 + d1 * d1 + d2 * d2, redB, tid) * (1.0f / 768.0f);
    float rstd = 1.0f / sqrtf(var + 1e-12f);
    float dd[3] = {d0, d1, d2};
    #pragma unroll
    for (int e = 0; e < 3; e++) {
        int col = tid + 256 * e;
        float v = g[col] * dd[e] * rstd + bb[col];
        out[base + col] = v;
        u16 h, m, l; split3(v, h, m, l);
        outP[base + col] = h;
        outP[PLsz + base + col] = m;
        outP[2 * PLsz + base + col] = l;
    }
}

// ---------------- fused: residual + 4 partials + bias + LN + IF spike -----------
// writes prev (fp32) + cntP (single EXACT bf16 plane of integer counts)
__global__ __launch_bounds__(256) void add_ln_spike4_kernel(
    const float* __restrict__ x, const float* __restrict__ part,
    const float* __restrict__ gbias,
    const float* __restrict__ g, const float* __restrict__ bb,
    float* __restrict__ mem, float* __restrict__ cnt,
    float* __restrict__ prev, u16* __restrict__ cntP,
    float invt, float* __restrict__ zout, int first, float* __restrict__ curout)
{
    __shared__ float redA[8], redB[8];
    const int row = blockIdx.x, tid = threadIdx.x;
    const size_t base = (size_t)row * ND;
    const size_t slab = (size_t)PLsz;
    float s[3];
    #pragma unroll
    for (int e = 0; e < 3; e++) {
        int col = tid + 256 * e;
        size_t idx = base + col;
        s[e] = x[idx] + part[idx] + part[idx + slab] + part[idx + 2 * slab]
             + part[idx + 3 * slab] + gbias[col];
    }
    float mean = blk_sum(s[0] + s[1] + s[2], redA, tid) * (1.0f / 768.0f);
    float d0 = s[0] - mean, d1 = s[1] - mean, d2 = s[2] - mean;
    float var = blk_sum(d0 * d0 + d1 * d1 + d2 * d2, redB, tid) * (1.0f / 768.0f);
    float rstd = 1.0f / sqrtf(var + 1e-12f);
    float dd[3] = {d0, d1, d2};

    #pragma unroll
    for (int e = 0; e < 3; e++) {
        int col = tid + 256 * e;
        size_t idx = base + col;
        float cur = g[col] * dd[e] * rstd + bb[col];
        if (curout) {
            curout[idx] = cur;
        } else {
            float m = (first ? 0.0f : mem[idx]) + cur;
            float spk = (m >= 1.0f) ? 1.0f : 0.0f;
            mem[idx] = m - spk;
            float cn = (first ? 0.0f : cnt[idx]) + spk;
            cnt[idx] = cn;
            float pv = cn * invt;
            prev[idx] = pv;
            __nv_bfloat16 cb = __float2bfloat16_rn(cn);   // integer <= 6: exact
            cntP[idx] = reinterpret_cast<u16&>(cb);
            if (zout) zout[idx] = pv;
        }
    }
}

// ---------------- launch ----------------
extern "C" void kernel_launch(void* const* d_in, const int* in_sizes, int n_in,
                              void* d_out, int out_size)
{
    const float* u    = (const float*)d_in[0];
    const int*   seg  = (const int*)d_in[1];
    const float* mask = (const float*)d_in[2];
    const float* semb = (const float*)d_in[3];
    const float* Wq   = (const float*)d_in[4];  const float* bq = (const float*)d_in[5];
    const float* Wk   = (const float*)d_in[6];  const float* bk = (const float*)d_in[7];
    const float* Wv   = (const float*)d_in[8];  const float* bv = (const float*)d_in[9];
    const float* Wo   = (const float*)d_in[10]; const float* bo = (const float*)d_in[11];
    const float* ln1g = (const float*)d_in[12]; const float* ln1b = (const float*)d_in[13];
    const float* W1   = (const float*)d_in[14]; const float* b1 = (const float*)d_in[15];
    const float* W2   = (const float*)d_in[16]; const float* b2 = (const float*)d_in[17];
    const float* ln2g = (const float*)d_in[18]; const float* ln2b = (const float*)d_in[19];
    // d_in[20] = time_step (always 6)

    float* out  = (float*)d_out;
    float* z    = out;
    float* attn = out + (size_t)5 * PLsz;

    void* p;
    #define FSYM(var, sym) cudaGetSymbolAddress(&p, sym); float* var = (float*)p
    #define USYM(var, sym) cudaGetSymbolAddress(&p, sym); u16* var = (u16*)p
    #define WSYM(var, sym) cudaGetSymbolAddress(&p, sym); u32* var = (u32*)p
    FSYM(xin,  g_xin);  FSYM(prev, g_prev); FSYM(x1, g_x1);
    FSYM(qkv,  g_qkv);  FSYM(aout, g_aout); FSYM(fout, g_fout);
    FSYM(cur0, g_cur0); FSYM(mem,  g_mem);  FSYM(cnt,  g_cnt);
    FSYM(bqkv, g_bqkv);
    USYM(xinP, g_xinP); USYM(cntP, g_cntP); USYM(x1P, g_x1P);
    USYM(ctxP, g_ctxP); USYM(ffhP, g_ffhP);
    WSYM(wqkvP, g_wqkvP); WSYM(woP, g_woP); WSYM(w1P, g_w1P); WSYM(w2P, g_w2P);
    #undef FSYM
    #undef USYM
    #undef WSYM

    cudaFuncSetAttribute(attn_kernel, cudaFuncAttributeMaxDynamicSharedMemorySize,
                         ATTN_SMEM_FLOATS * 4);

    // weight prep: 4 launches; launch #6 is the first GEMM (ncu -s 5 captures it)
    pack_qkvw_all<<<(NL * QKV_KN2 + 255) / 256, 256>>>(Wq, Wk, Wv, bq, bk, bv);
    pack_w_all<<<(NL * WO_KN2 + 255) / 256, 256>>>(Wo, woP, ND, ND);
    pack_w_all<<<(NL * W1_KN2 + 255) / 256, 256>>>(W1, w1P, ND, NF);
    pack_w_all<<<(NL * W2_KN2 + 255) / 256, 256>>>(W2, w2P, NF, ND);
    xin_kernel<<<(NR * ND) / 256, 256>>>(u, seg, semb, z);

    const dim3 gQKV(N3 / 128, NR / 64, 1);   // 18x16
    const dim3 gO  (ND / 128, NR / 64, 4);   // split-K4, klen=192
    const dim3 gF1 (NF / 128, NR / 64, 1);   // 24x16
    const dim3 gF2 (ND / 128, NR / 64, 4);   // split-K4, klen=768
    const dim3 gAttn(4, NH, NB);
    const float inv6 = 1.0f / 6.0f;

    // ---- layer 0: block output constant across time; compute once ----
    {
        gemm_bf<0><<<gQKV, 256>>>(xinP, xinP + PLsz, xinP + 2 * PLsz,
            wqkvP, wqkvP + QKV_KN2, wqkvP + 2 * (size_t)QKV_KN2,
            bqkv, 1.0f, qkv, 0, 0, 0, N3, ND, ND, 0);
        attn_kernel<<<gAttn, 256, ATTN_SMEM_FLOATS * 4>>>(qkv, mask, attn, ctxP, 1.0f, 0);
        gemm_bf<0><<<gO, 256>>>(ctxP, ctxP + PLsz, ctxP + 2 * PLsz,
            woP, woP + WO_KN2, woP + 2 * (size_t)WO_KN2,
            (const float*)0, 1.0f, aout, 0, 0, 0, ND, ND, ND / 4, 0);
        add_ln4_kernel<<<NR, 256>>>(xin, aout, bo, ln1g, ln1b, x1, x1P);
        gemm_bf<0><<<gF1, 256>>>(x1P, x1P + PLsz, x1P + 2 * PLsz,
            w1P, w1P + W1_KN2, w1P + 2 * (size_t)W1_KN2,
            b1, 1.0f, 0, ffhP, ffhP + FFsz, ffhP + 2 * FFsz, NF, ND, ND, 1);
        gemm_bf<0><<<gF2, 256>>>(ffhP, ffhP + FFsz, ffhP + 2 * FFsz,
            w2P, w2P + W2_KN2, w2P + 2 * (size_t)W2_KN2,
            (const float*)0, 1.0f, fout, 0, 0, 0, ND, NF, NF / 4, 0);
        add_ln_spike4_kernel<<<NR, 256>>>(x1, fout, b2, ln2g, ln2b,
            0, 0, 0, 0, 0.f, 0, 0, cur0);
    }

    for (int t = 0; t < NT; t++) {
        float tp1 = (float)(t + 1);
        float invt = 1.0f / tp1;
        rate0_kernel<<<(NR * ND) / 256, 256>>>(tp1,
            (t == NT - 1) ? (z + (size_t)1 * PLsz) : (float*)0);

        for (int l = 1; l < NL; l++) {
            // QKV on quantized counts: 3-term exact path, scale 1/(t+1) in epilogue
            gemm_bf<1><<<gQKV, 256>>>(cntP, cntP, cntP,
                wqkvP + ((size_t)l * 3 + 0) * QKV_KN2,
                wqkvP + ((size_t)l * 3 + 1) * QKV_KN2,
                wqkvP + ((size_t)l * 3 + 2) * QKV_KN2,
                bqkv + l * N3, invt, qkv, 0, 0, 0, N3, ND, ND, 0);
            attn_kernel<<<gAttn, 256, ATTN_SMEM_FLOATS * 4>>>(
                qkv, mask, attn + (size_t)l * NB * NH * NS * NS, ctxP,
                inv6, (t > 0) ? 1 : 0);
            gemm_bf<0><<<gO, 256>>>(ctxP, ctxP + PLsz, ctxP + 2 * PLsz,
                woP + ((size_t)l * 3 + 0) * WO_KN2,
                woP + ((size_t)l * 3 + 1) * WO_KN2,
                woP + ((size_t)l * 3 + 2) * WO_KN2,
                (const float*)0, 1.0f, aout, 0, 0, 0, ND, ND, ND / 4, 0);
            add_ln4_kernel<<<NR, 256>>>(prev, aout, bo + l * ND,
                ln1g + l * ND, ln1b + l * ND, x1, x1P);
            gemm_bf<0><<<gF1, 256>>>(x1P, x1P + PLsz, x1P + 2 * PLsz,
                w1P + ((size_t)l * 3 + 0) * W1_KN2,
                w1P + ((size_t)l * 3 + 1) * W1_KN2,
                w1P + ((size_t)l * 3 + 2) * W1_KN2,
                b1 + l * NF, 1.0f, 0, ffhP, ffhP + FFsz, ffhP + 2 * FFsz, NF, ND, ND, 1);
            gemm_bf<0><<<gF2, 256>>>(ffhP, ffhP + FFsz, ffhP + 2 * FFsz,
                w2P + ((size_t)l * 3 + 0) * W2_KN2,
                w2P + ((size_t)l * 3 + 1) * W2_KN2,
                w2P + ((size_t)l * 3 + 2) * W2_KN2,
                (const float*)0, 1.0f, fout, 0, 0, 0, ND, NF, NF / 4, 0);
            add_ln_spike4_kernel<<<NR, 256>>>(x1, fout, b2 + l * ND,
                ln2g + l * ND, ln2b + l * ND,
                mem + (size_t)l * PLsz, cnt + (size_t)l * PLsz,
                prev, cntP, invt,
                (t == NT - 1) ? (z + (size_t)(1 + l) * PLsz) : (float*)0,
                (t == 0) ? 1 : 0, 0);
        }
    }
}

// round 13
// speedup vs baseline: 1.8569x; 1.0730x over previous
#include <cuda_runtime.h>
#include <cuda_bf16.h>
#include <math.h>

#define NB 4
#define NS 256
#define ND 768
#define NF 3072
#define NL 4
#define NH 12
#define NDH 64
#define NR (NB*NS)   /* 1024 rows */
#define NT 6
#define N3 (3*ND)    /* 2304 */

typedef unsigned int u32;
typedef unsigned short u16;

#define PLsz (NR*ND)
#define FFsz (NR*NF)

// ---------------- scratch (static device globals; no allocs) ----------------
static __device__ float g_xin [PLsz];
static __device__ float g_prev[PLsz];
static __device__ float g_x1  [PLsz];
static __device__ float g_qkv [NR*N3];
static __device__ float g_aout[4*PLsz];
static __device__ float g_fout[4*PLsz];
static __device__ float g_cur0[PLsz];
static __device__ float g_mem [NL*PLsz];
static __device__ float g_cnt [NL*PLsz];
static __device__ float g_bqkv[NL*N3];

// bf16 activation planes
static __device__ u16 g_xinP [3*PLsz];
static __device__ u16 g_cntP [PLsz];      // QUANTIZED spike counts (exact single plane)
static __device__ u16 g_x1P  [3*PLsz];
static __device__ u16 g_ctxP [3*PLsz];
static __device__ u16 g_ffhP [3*FFsz];

// fragment-packed weights (u32 = bf16 pair): [l][plane][K*N/2]
#define QKV_KN2 (ND*N3/2)
#define WO_KN2  (ND*ND/2)
#define W1_KN2  (ND*NF/2)
#define W2_KN2  (NF*ND/2)
static __device__ u32 g_wqkvP[NL*3*QKV_KN2];
static __device__ u32 g_woP  [NL*3*WO_KN2];
static __device__ u32 g_w1P  [NL*3*W1_KN2];
static __device__ u32 g_w2P  [NL*3*W2_KN2];

// ---------------- helpers ----------------
__device__ __forceinline__ void split3(float a, u16& h, u16& m, u16& l) {
    __nv_bfloat16 bh = __float2bfloat16_rn(a);
    float r1 = a - __bfloat162float(bh);
    __nv_bfloat16 bm = __float2bfloat16_rn(r1);
    float r2 = r1 - __bfloat162float(bm);
    __nv_bfloat16 bl = __float2bfloat16_rn(r2);
    h = reinterpret_cast<u16&>(bh);
    m = reinterpret_cast<u16&>(bm);
    l = reinterpret_cast<u16&>(bl);
}

__device__ __forceinline__ float gelu_f(float x) {
    float x3 = x * x * x;
    float t = tanhf(0.7978845608028654f * (x + 0.044715f * x3));
    return 0.5f * x * (1.0f + t);
}

__device__ __forceinline__ float blk_sum(float v, volatile float* red, int tid) {
    #pragma unroll
    for (int o = 16; o; o >>= 1) v += __shfl_xor_sync(0xffffffffu, v, o);
    if ((tid & 31) == 0) red[tid >> 5] = v;
    __syncthreads();
    float tot = 0.f;
    #pragma unroll
    for (int i = 0; i < 8; i++) tot += red[i];
    return tot;
}

__device__ __forceinline__ void mmabf(float* c, const uint4 a, const uint2 b) {
    asm volatile(
        "mma.sync.aligned.m16n8k16.row.col.f32.bf16.bf16.f32 "
        "{%0,%1,%2,%3},{%4,%5,%6,%7},{%8,%9},{%0,%1,%2,%3};"
        : "+f"(c[0]), "+f"(c[1]), "+f"(c[2]), "+f"(c[3])
        : "r"(a.x), "r"(a.y), "r"(a.z), "r"(a.w), "r"(b.x), "r"(b.y));
}

// ---------------- all-layer weight packing into B-fragment layout ----------------
// frag math: u32 pos r = ((kc*(N/8)+nt)*32+ln)*2+j -> k = kc*16+(ln&3)*2+j*8, n = nt*8+(ln>>2)
__global__ __launch_bounds__(256) void pack_w_all(
    const float* __restrict__ W, u32* __restrict__ base, int K, int N)
{
    int pos = blockIdx.x * 256 + threadIdx.x;
    const int KN2 = K * N / 2;
    if (pos >= NL * KN2) return;
    int l = pos / KN2, r = pos - l * KN2;
    int perchunk = N * 8;
    int kc = r / perchunk;
    int rem = r - kc * perchunk;
    int nt = rem >> 6;
    int r2 = rem & 63;
    int ln = r2 >> 1, j = r2 & 1;
    int k = kc * 16 + (ln & 3) * 2 + j * 8;
    int n = nt * 8 + (ln >> 2);
    const float* Wl = W + (size_t)l * K * N;
    float w0 = Wl[(size_t)k * N + n];
    float w1 = Wl[(size_t)(k + 1) * N + n];
    u16 h0, m0, l0, h1, m1, l1;
    split3(w0, h0, m0, l0);
    split3(w1, h1, m1, l1);
    base[((size_t)l * 3 + 0) * KN2 + r] = (u32)h0 | ((u32)h1 << 16);
    base[((size_t)l * 3 + 1) * KN2 + r] = (u32)m0 | ((u32)m1 << 16);
    base[((size_t)l * 3 + 2) * KN2 + r] = (u32)l0 | ((u32)l1 << 16);
}

// all-layer q|k|v pack (logical [768,2304]) + bias fold
__global__ __launch_bounds__(256) void pack_qkvw_all(
    const float* __restrict__ Wq, const float* __restrict__ Wk, const float* __restrict__ Wv,
    const float* __restrict__ bq, const float* __restrict__ bk, const float* __restrict__ bv)
{
    int pos = blockIdx.x * 256 + threadIdx.x;
    if (pos < NL * N3) {
        int l = pos / N3, n = pos - l * N3;
        int which = n / ND, nn = n - which * ND;
        const float* b = (which == 0) ? bq : (which == 1) ? bk : bv;
        g_bqkv[pos] = b[l * ND + nn];
    }
    if (pos >= NL * QKV_KN2) return;
    int l = pos / QKV_KN2, r = pos - l * QKV_KN2;
    const int N = N3;
    int perchunk = N * 8;
    int kc = r / perchunk;
    int rem = r - kc * perchunk;
    int nt = rem >> 6;
    int r2 = rem & 63;
    int ln = r2 >> 1, j = r2 & 1;
    int k = kc * 16 + (ln & 3) * 2 + j * 8;
    int n = nt * 8 + (ln >> 2);
    int which = n / ND, nn = n - which * ND;
    const float* W = ((which == 0) ? Wq : (which == 1) ? Wk : Wv) + (size_t)l * ND * ND;
    float w0 = W[(size_t)k * ND + nn];
    float w1 = W[(size_t)(k + 1) * ND + nn];
    u16 h0, m0, l0, h1, m1, l1;
    split3(w0, h0, m0, l0);
    split3(w1, h1, m1, l1);
    g_wqkvP[((size_t)l * 3 + 0) * QKV_KN2 + r] = (u32)h0 | ((u32)h1 << 16);
    g_wqkvP[((size_t)l * 3 + 1) * QKV_KN2 + r] = (u32)m0 | ((u32)m1 << 16);
    g_wqkvP[((size_t)l * 3 + 2) * QKV_KN2 + r] = (u32)l0 | ((u32)l1 << 16);
}

// ---------------- x_in = u + seg_emb[segment_ids]; z[0]; splits ----------------
__global__ __launch_bounds__(256) void xin_kernel(
    const float* __restrict__ u, const int* __restrict__ seg,
    const float* __restrict__ semb, float* __restrict__ z0)
{
    int idx = blockIdx.x * 256 + threadIdx.x;
    int srow = idx / ND;
    int d = idx - srow * ND;
    float val = u[idx] + semb[seg[srow] * ND + d];
    g_xin[idx] = val;
    z0[idx] = val;
    u16 h, m, l; split3(val, h, m, l);
    g_xinP[idx] = h; g_xinP[PLsz + idx] = m; g_xinP[2 * PLsz + idx] = l;
}

// ---------------- layer-0 closed-form spike rate (float4) ----------------
__global__ __launch_bounds__(256) void rate0_kernel(float tplus1, float* __restrict__ zout)
{
    int i4 = blockIdx.x * 256 + threadIdx.x;   // float4 index
    float4 c = *((const float4*)g_cur0 + i4);
    float f0 = fminf(fmaxf(floorf(tplus1 * c.x), 0.f), tplus1);
    float f1 = fminf(fmaxf(floorf(tplus1 * c.y), 0.f), tplus1);
    float f2 = fminf(fmaxf(floorf(tplus1 * c.z), 0.f), tplus1);
    float f3 = fminf(fmaxf(floorf(tplus1 * c.w), 0.f), tplus1);
    float inv = 1.0f / tplus1;
    float4 r = make_float4(f0 * inv, f1 * inv, f2 * inv, f3 * inv);
    *((float4*)g_prev + i4) = r;
    ushort4 cb;
    __nv_bfloat16 t;
    t = __float2bfloat16_rn(f0); cb.x = reinterpret_cast<u16&>(t);
    t = __float2bfloat16_rn(f1); cb.y = reinterpret_cast<u16&>(t);
    t = __float2bfloat16_rn(f2); cb.z = reinterpret_cast<u16&>(t);
    t = __float2bfloat16_rn(f3); cb.w = reinterpret_cast<u16&>(t);
    *((ushort4*)g_cntP + i4) = cb;
    if (zout) *((float4*)zout + i4) = r;
}

// ---------------- bf16-split tensor-core GEMM (templated term count) ------------
// SA=0: 6 terms; SA=1: 3 terms on exact single-plane cnt, oscale in epilogue.
// R13: ONE zeroed per-chunk MMA accumulator (small terms first, hh last), single
// fp32 RN drain per chunk — truncation never sees the running sum (R11 fix kept).
template<int SA>
__global__ __launch_bounds__(256, 2) void gemm_bf(
    const u16* __restrict__ A0, const u16* __restrict__ A1, const u16* __restrict__ A2,
    const u32* __restrict__ B0, const u32* __restrict__ B1, const u32* __restrict__ B2,
    const float* __restrict__ bias, float oscale,
    float* __restrict__ Cf, u16* __restrict__ C0, u16* __restrict__ C1, u16* __restrict__ C2,
    int N, int K, int klen, int do_gelu)
{
    __shared__ __align__(16) u32 AF[2][1536];
    __shared__ __align__(16) u32 BF[2][3072];

    const int bx = blockIdx.x, by = blockIdx.y, bz = blockIdx.z;
    const int tid = threadIdx.x, lane = tid & 31, wid = tid >> 5;
    const int wm = wid >> 2, wn = wid & 3;
    const int K2 = K >> 1, N8 = N >> 3;
    const int NAS = (SA ? 2 : 6);

    const u32* apln[3] = {(const u32*)A0, (const u32*)A1, (const u32*)A2};
    const u32* ap[6];
    #pragma unroll
    for (int s = 0; s < NAS; s++) {
        int idx = s * 256 + tid;
        int j = idx & 3, ln = (idx >> 2) & 31, mt = (idx >> 7) & 3, pl = idx >> 9;
        int row = by * 64 + mt * 16 + (ln >> 2) + (j & 1) * 8;
        int c2 = (ln & 3) + (j >> 1) * 4;
        ap[s] = apln[pl] + (size_t)row * K2 + ((bz * klen) >> 1) + c2;
    }
    const u32* bpln[3] = {B0, B1, B2};
    const u32* bp[3];
    #pragma unroll
    for (int s = 0; s < 3; s++) {
        int idx4 = s * 256 + tid;
        int pl = idx4 >> 8, rem4 = idx4 & 255;
        int ntl = rem4 >> 4, lnp = (rem4 & 15) * 2;
        size_t goff = ((size_t)(((bz * klen) >> 4) * N8 + bx * 16 + ntl) * 32 + lnp) * 2;
        bp[s] = bpln[pl] + goff;
    }
    const size_t bstep = (size_t)N * 8;

    float acc[8][4];
    #pragma unroll
    for (int i = 0; i < 8; i++)
        #pragma unroll
        for (int j = 0; j < 4; j++) acc[i][j] = 0.f;

    const int nkt = klen >> 4;

    #pragma unroll
    for (int s = 0; s < NAS; s++) AF[0][s * 256 + tid] = ap[s][0];
    #pragma unroll
    for (int s = 0; s < 3; s++) *(uint4*)&BF[0][(s * 256 + tid) * 4] = *(const uint4*)bp[s];
    __syncthreads();

    u32 va[6]; uint4 vb[3];
    for (int kt = 0; kt < nkt; kt++) {
        const int cur = kt & 1;
        const bool more = (kt + 1 < nkt);
        if (more) {
            #pragma unroll
            for (int s = 0; s < NAS; s++) va[s] = ap[s][(kt + 1) * 8];
            #pragma unroll
            for (int s = 0; s < 3; s++) vb[s] = *(const uint4*)(bp[s] + (size_t)(kt + 1) * bstep);
        }

        uint4 aH[2], aM[2], aL[2];
        #pragma unroll
        for (int m2 = 0; m2 < 2; m2++) {
            int mt = wm * 2 + m2;
            aH[m2] = *(const uint4*)&AF[cur][(mt * 32 + lane) * 4];
            if (SA == 0) {
                aM[m2] = *(const uint4*)&AF[cur][((4 + mt) * 32 + lane) * 4];
                aL[m2] = *(const uint4*)&AF[cur][((8 + mt) * 32 + lane) * 4];
            }
        }
        #pragma unroll
        for (int n2 = 0; n2 < 4; n2++) {
            int nt = wn * 4 + n2;
            uint2 bH = *(const uint2*)&BF[cur][(nt * 32 + lane) * 2];
            uint2 bM = *(const uint2*)&BF[cur][1024 + (nt * 32 + lane) * 2];
            uint2 bL = *(const uint2*)&BF[cur][2048 + (nt * 32 + lane) * 2];
            #pragma unroll
            for (int m2 = 0; m2 < 2; m2++) {
                float cc[4] = {0.f, 0.f, 0.f, 0.f};
                if (SA == 1) {
                    mmabf(cc, aH[m2], bL);
                    mmabf(cc, aH[m2], bM);
                    mmabf(cc, aH[m2], bH);
                } else {
                    mmabf(cc, aM[m2], bM);   // ~2^-16 first
                    mmabf(cc, aH[m2], bL);
                    mmabf(cc, aL[m2], bH);
                    mmabf(cc, aM[m2], bH);   // ~2^-8
                    mmabf(cc, aH[m2], bM);
                    mmabf(cc, aH[m2], bH);   // dominant last
                }
                float* c = acc[m2 * 4 + n2];
                #pragma unroll
                for (int q = 0; q < 4; q++) c[q] += cc[q];
            }
        }

        if (more) {
            const int nx = cur ^ 1;
            #pragma unroll
            for (int s = 0; s < NAS; s++) AF[nx][s * 256 + tid] = va[s];
            #pragma unroll
            for (int s = 0; s < 3; s++) *(uint4*)&BF[nx][(s * 256 + tid) * 4] = vb[s];
        }
        __syncthreads();
    }

    float* Cp = Cf;
    if (Cp && gridDim.z > 1) Cp += (size_t)bz * ((size_t)NR * N);

    #pragma unroll
    for (int m2 = 0; m2 < 2; m2++)
        #pragma unroll
        for (int n2 = 0; n2 < 4; n2++) {
            float* c = acc[m2 * 4 + n2];
            int row = by * 64 + wm * 32 + m2 * 16 + (lane >> 2);
            int col = bx * 128 + wn * 32 + n2 * 8 + (lane & 3) * 2;
            float o0 = c[0] * oscale, o1 = c[1] * oscale,
                  o2 = c[2] * oscale, o3 = c[3] * oscale;
            if (bias) {
                float bb0 = bias[col], bb1 = bias[col + 1];
                o0 += bb0; o1 += bb1; o2 += bb0; o3 += bb1;
            }
            if (do_gelu) { o0 = gelu_f(o0); o1 = gelu_f(o1); o2 = gelu_f(o2); o3 = gelu_f(o3); }
            if (C0) {
                u16 h0, m0, l0, h1, m1, l1;
                split3(o0, h0, m0, l0); split3(o1, h1, m1, l1);
                size_t p = ((size_t)row * N + col) >> 1;
                ((u32*)C0)[p] = (u32)h0 | ((u32)h1 << 16);
                ((u32*)C1)[p] = (u32)m0 | ((u32)m1 << 16);
                ((u32*)C2)[p] = (u32)l0 | ((u32)l1 << 16);
                split3(o2, h0, m0, l0); split3(o3, h1, m1, l1);
                p = ((size_t)(row + 8) * N + col) >> 1;
                ((u32*)C0)[p] = (u32)h0 | ((u32)h1 << 16);
                ((u32*)C1)[p] = (u32)m0 | ((u32)m1 << 16);
                ((u32*)C2)[p] = (u32)l0 | ((u32)l1 << 16);
            } else {
                *(float2*)&Cp[(size_t)row * N + col] = make_float2(o0, o1);
                *(float2*)&Cp[(size_t)(row + 8) * N + col] = make_float2(o2, o3);
            }
        }
}

// ---------------- fused attention; ctx -> 3 bf16 planes ----------------
#define ATTN_SMEM_FLOATS (64*257 + 256*64 + 64*256 + 64*64)

__global__ __launch_bounds__(256) void attn_kernel(
    const float* __restrict__ qkv, const float* __restrict__ mask,
    float* __restrict__ asum, u16* __restrict__ ctxP,
    float wgt, int accum)
{
    extern __shared__ float smf[];
    float* Ks = smf;                    // [64][257]
    float* Vs = smf + 64 * 257;         // [256][64]
    float* Ss = Vs + 256 * 64;          // [64][256]
    float* Qs = Ss + 64 * 256;          // [64][64]

    const int rb = blockIdx.x, h = blockIdx.y, b = blockIdx.z;
    const int tid = threadIdx.x;
    const int lane = tid & 31, w = tid >> 5;
    const int i0 = rb * 64;
    const int dq = (tid & 15) * 4;
    const int jb = tid >> 4;

    const float* qb = qkv + ((size_t)b * NS + i0) * N3 + h * NDH;
    const float* kb = qkv + (size_t)b * NS * N3 + ND + h * NDH;
    const float* vb = qkv + (size_t)b * NS * N3 + 2 * ND + h * NDH;

    #pragma unroll
    for (int it = 0; it < 16; it++) {
        int j = jb + it * 16;
        float4 kv = *(const float4*)(kb + (size_t)j * N3 + dq);
        Ks[(dq + 0) * 257 + j] = kv.x;
        Ks[(dq + 1) * 257 + j] = kv.y;
        Ks[(dq + 2) * 257 + j] = kv.z;
        Ks[(dq + 3) * 257 + j] = kv.w;
        float4 vv = *(const float4*)(vb + (size_t)j * N3 + dq);
        *(float4*)&Vs[j * 64 + dq] = vv;
    }
    #pragma unroll
    for (int it = 0; it < 4; it++) {
        int i = jb + it * 16;
        float4 qv = *(const float4*)(qb + (size_t)i * N3 + dq);
        *(float4*)&Qs[i * 64 + dq] = qv;
    }
    __syncthreads();

    float extr[8];
    #pragma unroll
    for (int jj = 0; jj < 8; jj++)
        extr[jj] = (1.0f - mask[b * NS + lane + 32 * jj]) * -10000.0f;

    float acc[8][8];
    #pragma unroll
    for (int r = 0; r < 8; r++)
        #pragma unroll
        for (int jj = 0; jj < 8; jj++) acc[r][jj] = 0.f;

    const int r0 = w * 8;
    for (int d = 0; d < 64; d++) {
        float kr[8];
        #pragma unroll
        for (int jj = 0; jj < 8; jj++) kr[jj] = Ks[d * 257 + lane + 32 * jj];
        #pragma unroll
        for (int r = 0; r < 8; r++) {
            float qv = Qs[(r0 + r) * 64 + d];
            #pragma unroll
            for (int jj = 0; jj < 8; jj++) acc[r][jj] = fmaf(qv, kr[jj], acc[r][jj]);
        }
    }

    #pragma unroll
    for (int r = 0; r < 8; r++) {
        float mx = -3.0e38f;
        #pragma unroll
        for (int jj = 0; jj < 8; jj++) {
            float s = acc[r][jj] * 0.125f + extr[jj];
            acc[r][jj] = s;
            mx = fmaxf(mx, s);
        }
        #pragma unroll
        for (int o = 16; o; o >>= 1) mx = fmaxf(mx, __shfl_xor_sync(0xffffffffu, mx, o));
        float sum = 0.f;
        #pragma unroll
        for (int jj = 0; jj < 8; jj++) { float e = expf(acc[r][jj] - mx); acc[r][jj] = e; sum += e; }
        #pragma unroll
        for (int o = 16; o; o >>= 1) sum += __shfl_xor_sync(0xffffffffu, sum, o);
        float rinv = 1.0f / sum;
        int i = r0 + r;
        float* ar = asum + (((size_t)(b * NH + h)) * NS + (i0 + i)) * NS;
        #pragma unroll
        for (int jj = 0; jj < 8; jj++) {
            float p = acc[r][jj] * rinv;
            int j = lane + 32 * jj;
            Ss[i * 256 + j] = p;
            ar[j] = accum ? (ar[j] + p * wgt) : (p * wgt);
        }
    }
    __syncwarp();

    float c0[8], c1[8];
    #pragma unroll
    for (int r = 0; r < 8; r++) { c0[r] = 0.f; c1[r] = 0.f; }
    for (int j = 0; j < 256; j++) {
        float v0 = Vs[j * 64 + lane];
        float v1 = Vs[j * 64 + lane + 32];
        #pragma unroll
        for (int r = 0; r < 8; r++) {
            float p = Ss[(r0 + r) * 256 + j];
            c0[r] = fmaf(p, v0, c0[r]);
            c1[r] = fmaf(p, v1, c1[r]);
        }
    }
    #pragma unroll
    for (int r = 0; r < 8; r++) {
        size_t base = ((size_t)b * NS + i0 + r0 + r) * ND + h * NDH;
        u16 hh, mm, ll;
        split3(c0[r], hh, mm, ll);
        ctxP[base + lane] = hh;
        ctxP[PLsz + base + lane] = mm;
        ctxP[2 * PLsz + base + lane] = ll;
        split3(c1[r], hh, mm, ll);
        ctxP[base + lane + 32] = hh;
        ctxP[PLsz + base + lane + 32] = mm;
        ctxP[2 * PLsz + base + lane + 32] = ll;
    }
}

// ---------------- fused: residual + 4 partials + bias + LN + splits (float4) ----
__global__ __launch_bounds__(256) void add_ln4_kernel(
    const float* __restrict__ x, const float* __restrict__ part,
    const float* __restrict__ gbias,
    const float* __restrict__ g, const float* __restrict__ bb,
    float* __restrict__ out, u16* __restrict__ outP)
{
    __shared__ float redA[8], redB[8];
    const int row = blockIdx.x, tid = threadIdx.x;
    const size_t base = (size_t)row * ND;
    const size_t slab = (size_t)PLsz;
    const int col = tid * 4;                 // valid for tid < 192
    const bool act = (tid < 192);

    float4 s = make_float4(0.f, 0.f, 0.f, 0.f);
    if (act) {
        size_t idx = base + col;
        float4 xv = *(const float4*)&x[idx];
        float4 p0 = *(const float4*)&part[idx];
        float4 p1 = *(const float4*)&part[idx + slab];
        float4 p2 = *(const float4*)&part[idx + 2 * slab];
        float4 p3 = *(const float4*)&part[idx + 3 * slab];
        float4 gb = *(const float4*)&gbias[col];
        s.x = xv.x + p0.x + p1.x + p2.x + p3.x + gb.x;
        s.y = xv.y + p0.y + p1.y + p2.y + p3.y + gb.y;
        s.z = xv.z + p0.z + p1.z + p2.z + p3.z + gb.z;
        s.w = xv.w + p0.w + p1.w + p2.w + p3.w + gb.w;
    }
    float mean = blk_sum(s.x + s.y + s.z + s.w, redA, tid) * (1.0f / 768.0f);
    float4 d = make_float4(s.x - mean, s.y - mean, s.z - mean, s.w - mean);
    float vsum = act ? (d.x * d.x + d.y * d.y + d.z * d.z + d.w * d.w) : 0.f;
    float var = blk_sum(vsum, redB, tid) * (1.0f / 768.0f);
    float rstd = 1.0f / sqrtf(var + 1e-12f);
    if (act) {
        float4 gv = *(const float4*)&g[col];
        float4 bv = *(const float4*)&bb[col];
        float o[4] = {gv.x * d.x * rstd + bv.x, gv.y * d.y * rstd + bv.y,
                      gv.z * d.z * rstd + bv.z, gv.w * d.w * rstd + bv.w};
        *(float4*)&out[base + col] = make_float4(o[0], o[1], o[2], o[3]);
        ushort4 vh, vm, vl;
        u16 h, m, l;
        split3(o[0], h, m, l); vh.x = h; vm.x = m; vl.x = l;
        split3(o[1], h, m, l); vh.y = h; vm.y = m; vl.y = l;
        split3(o[2], h, m, l); vh.z = h; vm.z = m; vl.z = l;
        split3(o[3], h, m, l); vh.w = h; vm.w = m; vl.w = l;
        *(ushort4*)&outP[base + col] = vh;
        *(ushort4*)&outP[slab + base + col] = vm;
        *(ushort4*)&outP[2 * slab + base + col] = vl;
    }
}

// ---------------- fused: residual + 4 partials + bias + LN + IF spike (float4) --
__global__ __launch_bounds__(256) void add_ln_spike4_kernel(
    const float* __restrict__ x, const float* __restrict__ part,
    const float* __restrict__ gbias,
    const float* __restrict__ g, const float* __restrict__ bb,
    float* __restrict__ mem, float* __restrict__ cnt,
    float* __restrict__ prev, u16* __restrict__ cntP,
    float invt, float* __restrict__ zout, int first, float* __restrict__ curout)
{
    __shared__ float redA[8], redB[8];
    const int row = blockIdx.x, tid = threadIdx.x;
    const size_t base = (size_t)row * ND;
    const size_t slab = (size_t)PLsz;
    const int col = tid * 4;
    const bool act = (tid < 192);

    float4 s = make_float4(0.f, 0.f, 0.f, 0.f);
    if (act) {
        size_t idx = base + col;
        float4 xv = *(const float4*)&x[idx];
        float4 p0 = *(const float4*)&part[idx];
        float4 p1 = *(const float4*)&part[idx + slab];
        float4 p2 = *(const float4*)&part[idx + 2 * slab];
        float4 p3 = *(const float4*)&part[idx + 3 * slab];
        float4 gb = *(const float4*)&gbias[col];
        s.x = xv.x + p0.x + p1.x + p2.x + p3.x + gb.x;
        s.y = xv.y + p0.y + p1.y + p2.y + p3.y + gb.y;
        s.z = xv.z + p0.z + p1.z + p2.z + p3.z + gb.z;
        s.w = xv.w + p0.w + p1.w + p2.w + p3.w + gb.w;
    }
    float mean = blk_sum(s.x + s.y + s.z + s.w, redA, tid) * (1.0f / 768.0f);
    float4 d = make_float4(s.x - mean, s.y - mean, s.z - mean, s.w - mean);
    float vsum = act ? (d.x * d.x + d.y * d.y + d.z * d.z + d.w * d.w) : 0.f;
    float var = blk_sum(vsum, redB, tid) * (1.0f / 768.0f);
    float rstd = 1.0f / sqrtf(var + 1e-12f);
    if (!act) return;

    float4 gv = *(const float4*)&g[col];
    float4 bv = *(const float4*)&bb[col];
    float cur[4] = {gv.x * d.x * rstd + bv.x, gv.y * d.y * rstd + bv.y,
                    gv.z * d.z * rstd + bv.z, gv.w * d.w * rstd + bv.w};
    size_t idx = base + col;
    if (curout) {
        *(float4*)&curout[idx] = make_float4(cur[0], cur[1], cur[2], cur[3]);
        return;
    }
    float4 mv = first ? make_float4(0.f, 0.f, 0.f, 0.f) : *(const float4*)&mem[idx];
    float4 cv = first ? make_float4(0.f, 0.f, 0.f, 0.f) : *(const float4*)&cnt[idx];
    float m[4] = {mv.x + cur[0], mv.y + cur[1], mv.z + cur[2], mv.w + cur[3]};
    float cn[4]; float pv[4];
    ushort4 cb;
    #pragma unroll
    for (int e = 0; e < 4; e++) {
        float spk = (m[e] >= 1.0f) ? 1.0f : 0.0f;
        m[e] -= spk;
        cn[e] = ((e == 0) ? cv.x : (e == 1) ? cv.y : (e == 2) ? cv.z : cv.w) + spk;
        pv[e] = cn[e] * invt;
    }
    *(float4*)&mem[idx] = make_float4(m[0], m[1], m[2], m[3]);
    *(float4*)&cnt[idx] = make_float4(cn[0], cn[1], cn[2], cn[3]);
    *(float4*)&prev[idx] = make_float4(pv[0], pv[1], pv[2], pv[3]);
    __nv_bfloat16 t;
    t = __float2bfloat16_rn(cn[0]); cb.x = reinterpret_cast<u16&>(t);
    t = __float2bfloat16_rn(cn[1]); cb.y = reinterpret_cast<u16&>(t);
    t = __float2bfloat16_rn(cn[2]); cb.z = reinterpret_cast<u16&>(t);
    t = __float2bfloat16_rn(cn[3]); cb.w = reinterpret_cast<u16&>(t);
    *(ushort4*)&cntP[idx] = cb;
    if (zout) *(float4*)&zout[idx] = make_float4(pv[0], pv[1], pv[2], pv[3]);
}

// ---------------- launch ----------------
extern "C" void kernel_launch(void* const* d_in, const int* in_sizes, int n_in,
                              void* d_out, int out_size)
{
    const float* u    = (const float*)d_in[0];
    const int*   seg  = (const int*)d_in[1];
    const float* mask = (const float*)d_in[2];
    const float* semb = (const float*)d_in[3];
    const float* Wq   = (const float*)d_in[4];  const float* bq = (const float*)d_in[5];
    const float* Wk   = (const float*)d_in[6];  const float* bk = (const float*)d_in[7];
    const float* Wv   = (const float*)d_in[8];  const float* bv = (const float*)d_in[9];
    const float* Wo   = (const float*)d_in[10]; const float* bo = (const float*)d_in[11];
    const float* ln1g = (const float*)d_in[12]; const float* ln1b = (const float*)d_in[13];
    const float* W1   = (const float*)d_in[14]; const float* b1 = (const float*)d_in[15];
    const float* W2   = (const float*)d_in[16]; const float* b2 = (const float*)d_in[17];
    const float* ln2g = (const float*)d_in[18]; const float* ln2b = (const float*)d_in[19];
    // d_in[20] = time_step (always 6)

    float* out  = (float*)d_out;
    float* z    = out;
    float* attn = out + (size_t)5 * PLsz;

    void* p;
    #define FSYM(var, sym) cudaGetSymbolAddress(&p, sym); float* var = (float*)p
    #define USYM(var, sym) cudaGetSymbolAddress(&p, sym); u16* var = (u16*)p
    #define WSYM(var, sym) cudaGetSymbolAddress(&p, sym); u32* var = (u32*)p
    FSYM(xin,  g_xin);  FSYM(prev, g_prev); FSYM(x1, g_x1);
    FSYM(qkv,  g_qkv);  FSYM(aout, g_aout); FSYM(fout, g_fout);
    FSYM(cur0, g_cur0); FSYM(mem,  g_mem);  FSYM(cnt,  g_cnt);
    FSYM(bqkv, g_bqkv);
    USYM(xinP, g_xinP); USYM(cntP, g_cntP); USYM(x1P, g_x1P);
    USYM(ctxP, g_ctxP); USYM(ffhP, g_ffhP);
    WSYM(wqkvP, g_wqkvP); WSYM(woP, g_woP); WSYM(w1P, g_w1P); WSYM(w2P, g_w2P);
    #undef FSYM
    #undef USYM
    #undef WSYM

    cudaFuncSetAttribute(attn_kernel, cudaFuncAttributeMaxDynamicSharedMemorySize,
                         ATTN_SMEM_FLOATS * 4);

    pack_qkvw_all<<<(NL * QKV_KN2 + 255) / 256, 256>>>(Wq, Wk, Wv, bq, bk, bv);
    pack_w_all<<<(NL * WO_KN2 + 255) / 256, 256>>>(Wo, woP, ND, ND);
    pack_w_all<<<(NL * W1_KN2 + 255) / 256, 256>>>(W1, w1P, ND, NF);
    pack_w_all<<<(NL * W2_KN2 + 255) / 256, 256>>>(W2, w2P, NF, ND);
    xin_kernel<<<(NR * ND) / 256, 256>>>(u, seg, semb, z);

    const dim3 gQKV(N3 / 128, NR / 64, 1);   // 18x16
    const dim3 gO  (ND / 128, NR / 64, 4);   // split-K4, klen=192
    const dim3 gF1 (NF / 128, NR / 64, 1);   // 24x16
    const dim3 gF2 (ND / 128, NR / 64, 4);   // split-K4, klen=768
    const dim3 gAttn(4, NH, NB);
    const float inv6 = 1.0f / 6.0f;

    // ---- layer 0: block output constant across time; compute once ----
    {
        gemm_bf<0><<<gQKV, 256>>>(xinP, xinP + PLsz, xinP + 2 * PLsz,
            wqkvP, wqkvP + QKV_KN2, wqkvP + 2 * (size_t)QKV_KN2,
            bqkv, 1.0f, qkv, 0, 0, 0, N3, ND, ND, 0);
        attn_kernel<<<gAttn, 256, ATTN_SMEM_FLOATS * 4>>>(qkv, mask, attn, ctxP, 1.0f, 0);
        gemm_bf<0><<<gO, 256>>>(ctxP, ctxP + PLsz, ctxP + 2 * PLsz,
            woP, woP + WO_KN2, woP + 2 * (size_t)WO_KN2,
            (const float*)0, 1.0f, aout, 0, 0, 0, ND, ND, ND / 4, 0);
        add_ln4_kernel<<<NR, 256>>>(xin, aout, bo, ln1g, ln1b, x1, x1P);
        gemm_bf<0><<<gF1, 256>>>(x1P, x1P + PLsz, x1P + 2 * PLsz,
            w1P, w1P + W1_KN2, w1P + 2 * (size_t)W1_KN2,
            b1, 1.0f, 0, ffhP, ffhP + FFsz, ffhP + 2 * FFsz, NF, ND, ND, 1);
        gemm_bf<0><<<gF2, 256>>>(ffhP, ffhP + FFsz, ffhP + 2 * FFsz,
            w2P, w2P + W2_KN2, w2P + 2 * (size_t)W2_KN2,
            (const float*)0, 1.0f, fout, 0, 0, 0, ND, NF, NF / 4, 0);
        add_ln_spike4_kernel<<<NR, 256>>>(x1, fout, b2, ln2g, ln2b,
            0, 0, 0, 0, 0.f, 0, 0, cur0);
    }

    for (int t = 0; t < NT; t++) {
        float tp1 = (float)(t + 1);
        float invt = 1.0f / tp1;
        rate0_kernel<<<(NR * ND / 4) / 256, 256>>>(tp1,
            (t == NT - 1) ? (z + (size_t)1 * PLsz) : (float*)0);

        for (int l = 1; l < NL; l++) {
            gemm_bf<1><<<gQKV, 256>>>(cntP, cntP, cntP,
                wqkvP + ((size_t)l * 3 + 0) * QKV_KN2,
                wqkvP + ((size_t)l * 3 + 1) * QKV_KN2,
                wqkvP + ((size_t)l * 3 + 2) * QKV_KN2,
                bqkv + l * N3, invt, qkv, 0, 0, 0, N3, ND, ND, 0);
            attn_kernel<<<gAttn, 256, ATTN_SMEM_FLOATS * 4>>>(
                qkv, mask, attn + (size_t)l * NB * NH * NS * NS, ctxP,
                inv6, (t > 0) ? 1 : 0);
            gemm_bf<0><<<gO, 256>>>(ctxP, ctxP + PLsz, ctxP + 2 * PLsz,
                woP + ((size_t)l * 3 + 0) * WO_KN2,
                woP + ((size_t)l * 3 + 1) * WO_KN2,
                woP + ((size_t)l * 3 + 2) * WO_KN2,
                (const float*)0, 1.0f, aout, 0, 0, 0, ND, ND, ND / 4, 0);
            add_ln4_kernel<<<NR, 256>>>(prev, aout, bo + l * ND,
                ln1g + l * ND, ln1b + l * ND, x1, x1P);
            gemm_bf<0><<<gF1, 256>>>(x1P, x1P + PLsz, x1P + 2 * PLsz,
                w1P + ((size_t)l * 3 + 0) * W1_KN2,
                w1P + ((size_t)l * 3 + 1) * W1_KN2,
                w1P + ((size_t)l * 3 + 2) * W1_KN2,
                b1 + l * NF, 1.0f, 0, ffhP, ffhP + FFsz, ffhP + 2 * FFsz, NF, ND, ND, 1);
            gemm_bf<0><<<gF2, 256>>>(ffhP, ffhP + FFsz, ffhP + 2 * FFsz,
                w2P + ((size_t)l * 3 + 0) * W2_KN2,
                w2P + ((size_t)l * 3 + 1) * W2_KN2,
                w2P + ((size_t)l * 3 + 2) * W2_KN2,
                (const float*)0, 1.0f, fout, 0, 0, 0, ND, NF, NF / 4, 0);
            add_ln_spike4_kernel<<<NR, 256>>>(x1, fout, b2 + l * ND,
                ln2g + l * ND, ln2b + l * ND,
                mem + (size_t)l * PLsz, cnt + (size_t)l * PLsz,
                prev, cntP, invt,
                (t == NT - 1) ? (z + (size_t)(1 + l) * PLsz) : (float*)0,
                (t == 0) ? 1 : 0, 0);
        }
    }
}

// round 14
// speedup vs baseline: 1.8616x; 1.0025x over previous
#include <cuda_runtime.h>
#include <cuda_bf16.h>
#include <math.h>

#define NB 4
#define NS 256
#define ND 768
#define NF 3072
#define NL 4
#define NH 12
#define NDH 64
#define NR (NB*NS)   /* 1024 rows */
#define NT 6
#define N3 (3*ND)    /* 2304 */

typedef unsigned int u32;
typedef unsigned short u16;

#define PLsz (NR*ND)
#define FFsz (NR*NF)

// ---------------- scratch (static device globals; no allocs) ----------------
static __device__ float g_xin [PLsz];
static __device__ float g_prev[PLsz];
static __device__ float g_x1  [PLsz];
static __device__ float g_qkv [NR*N3];
static __device__ float g_aout[4*PLsz];
static __device__ float g_fout[4*PLsz];
static __device__ float g_cur0[PLsz];
static __device__ float g_mem [NL*PLsz];
static __device__ float g_cnt [NL*PLsz];
static __device__ float g_bqkv[NL*N3];

// bf16 activation planes
static __device__ u16 g_xinP [3*PLsz];
static __device__ u16 g_cntP [PLsz];      // QUANTIZED spike counts (exact single plane)
static __device__ u16 g_x1P  [3*PLsz];
static __device__ u16 g_ctxP [3*PLsz];
static __device__ u16 g_ffhP [3*FFsz];

// fragment-packed weights (u32 = bf16 pair): [l][plane][K*N/2]
#define QKV_KN2 (ND*N3/2)
#define WO_KN2  (ND*ND/2)
#define W1_KN2  (ND*NF/2)
#define W2_KN2  (NF*ND/2)
static __device__ u32 g_wqkvP[NL*3*QKV_KN2];
static __device__ u32 g_woP  [NL*3*WO_KN2];
static __device__ u32 g_w1P  [NL*3*W1_KN2];
static __device__ u32 g_w2P  [NL*3*W2_KN2];

// ---------------- helpers ----------------
__device__ __forceinline__ void split3(float a, u16& h, u16& m, u16& l) {
    __nv_bfloat16 bh = __float2bfloat16_rn(a);
    float r1 = a - __bfloat162float(bh);
    __nv_bfloat16 bm = __float2bfloat16_rn(r1);
    float r2 = r1 - __bfloat162float(bm);
    __nv_bfloat16 bl = __float2bfloat16_rn(r2);
    h = reinterpret_cast<u16&>(bh);
    m = reinterpret_cast<u16&>(bm);
    l = reinterpret_cast<u16&>(bl);
}

__device__ __forceinline__ float gelu_f(float x) {
    float x3 = x * x * x;
    float t = tanhf(0.7978845608028654f * (x + 0.044715f * x3));
    return 0.5f * x * (1.0f + t);
}

__device__ __forceinline__ float warp_sum(float v) {
    #pragma unroll
    for (int o = 16; o; o >>= 1) v += __shfl_xor_sync(0xffffffffu, v, o);
    return v;
}

__device__ __forceinline__ void mmabf(float* c, const uint4 a, const uint2 b) {
    asm volatile(
        "mma.sync.aligned.m16n8k16.row.col.f32.bf16.bf16.f32 "
        "{%0,%1,%2,%3},{%4,%5,%6,%7},{%8,%9},{%0,%1,%2,%3};"
        : "+f"(c[0]), "+f"(c[1]), "+f"(c[2]), "+f"(c[3])
        : "r"(a.x), "r"(a.y), "r"(a.z), "r"(a.w), "r"(b.x), "r"(b.y));
}

// ---------------- all-layer weight packing into B-fragment layout ----------------
__global__ __launch_bounds__(256) void pack_w_all(
    const float* __restrict__ W, u32* __restrict__ base, int K, int N)
{
    int pos = blockIdx.x * 256 + threadIdx.x;
    const int KN2 = K * N / 2;
    if (pos >= NL * KN2) return;
    int l = pos / KN2, r = pos - l * KN2;
    int perchunk = N * 8;
    int kc = r / perchunk;
    int rem = r - kc * perchunk;
    int nt = rem >> 6;
    int r2 = rem & 63;
    int ln = r2 >> 1, j = r2 & 1;
    int k = kc * 16 + (ln & 3) * 2 + j * 8;
    int n = nt * 8 + (ln >> 2);
    const float* Wl = W + (size_t)l * K * N;
    float w0 = Wl[(size_t)k * N + n];
    float w1 = Wl[(size_t)(k + 1) * N + n];
    u16 h0, m0, l0, h1, m1, l1;
    split3(w0, h0, m0, l0);
    split3(w1, h1, m1, l1);
    base[((size_t)l * 3 + 0) * KN2 + r] = (u32)h0 | ((u32)h1 << 16);
    base[((size_t)l * 3 + 1) * KN2 + r] = (u32)m0 | ((u32)m1 << 16);
    base[((size_t)l * 3 + 2) * KN2 + r] = (u32)l0 | ((u32)l1 << 16);
}

__global__ __launch_bounds__(256) void pack_qkvw_all(
    const float* __restrict__ Wq, const float* __restrict__ Wk, const float* __restrict__ Wv,
    const float* __restrict__ bq, const float* __restrict__ bk, const float* __restrict__ bv)
{
    int pos = blockIdx.x * 256 + threadIdx.x;
    if (pos < NL * N3) {
        int l = pos / N3, n = pos - l * N3;
        int which = n / ND, nn = n - which * ND;
        const float* b = (which == 0) ? bq : (which == 1) ? bk : bv;
        g_bqkv[pos] = b[l * ND + nn];
    }
    if (pos >= NL * QKV_KN2) return;
    int l = pos / QKV_KN2, r = pos - l * QKV_KN2;
    const int N = N3;
    int perchunk = N * 8;
    int kc = r / perchunk;
    int rem = r - kc * perchunk;
    int nt = rem >> 6;
    int r2 = rem & 63;
    int ln = r2 >> 1, j = r2 & 1;
    int k = kc * 16 + (ln & 3) * 2 + j * 8;
    int n = nt * 8 + (ln >> 2);
    int which = n / ND, nn = n - which * ND;
    const float* W = ((which == 0) ? Wq : (which == 1) ? Wk : Wv) + (size_t)l * ND * ND;
    float w0 = W[(size_t)k * ND + nn];
    float w1 = W[(size_t)(k + 1) * ND + nn];
    u16 h0, m0, l0, h1, m1, l1;
    split3(w0, h0, m0, l0);
    split3(w1, h1, m1, l1);
    g_wqkvP[((size_t)l * 3 + 0) * QKV_KN2 + r] = (u32)h0 | ((u32)h1 << 16);
    g_wqkvP[((size_t)l * 3 + 1) * QKV_KN2 + r] = (u32)m0 | ((u32)m1 << 16);
    g_wqkvP[((size_t)l * 3 + 2) * QKV_KN2 + r] = (u32)l0 | ((u32)l1 << 16);
}

// ---------------- x_in = u + seg_emb[segment_ids]; z[0]; splits ----------------
__global__ __launch_bounds__(256) void xin_kernel(
    const float* __restrict__ u, const int* __restrict__ seg,
    const float* __restrict__ semb, float* __restrict__ z0)
{
    int idx = blockIdx.x * 256 + threadIdx.x;
    int srow = idx / ND;
    int d = idx - srow * ND;
    float val = u[idx] + semb[seg[srow] * ND + d];
    g_xin[idx] = val;
    z0[idx] = val;
    u16 h, m, l; split3(val, h, m, l);
    g_xinP[idx] = h; g_xinP[PLsz + idx] = m; g_xinP[2 * PLsz + idx] = l;
}

// ---------------- layer-0 closed-form spike rate (float4) ----------------
__global__ __launch_bounds__(256) void rate0_kernel(float tplus1, float* __restrict__ zout)
{
    int i4 = blockIdx.x * 256 + threadIdx.x;
    float4 c = *((const float4*)g_cur0 + i4);
    float f0 = fminf(fmaxf(floorf(tplus1 * c.x), 0.f), tplus1);
    float f1 = fminf(fmaxf(floorf(tplus1 * c.y), 0.f), tplus1);
    float f2 = fminf(fmaxf(floorf(tplus1 * c.z), 0.f), tplus1);
    float f3 = fminf(fmaxf(floorf(tplus1 * c.w), 0.f), tplus1);
    float inv = 1.0f / tplus1;
    float4 r = make_float4(f0 * inv, f1 * inv, f2 * inv, f3 * inv);
    *((float4*)g_prev + i4) = r;
    ushort4 cb;
    __nv_bfloat16 t;
    t = __float2bfloat16_rn(f0); cb.x = reinterpret_cast<u16&>(t);
    t = __float2bfloat16_rn(f1); cb.y = reinterpret_cast<u16&>(t);
    t = __float2bfloat16_rn(f2); cb.z = reinterpret_cast<u16&>(t);
    t = __float2bfloat16_rn(f3); cb.w = reinterpret_cast<u16&>(t);
    *((ushort4*)g_cntP + i4) = cb;
    if (zout) *((float4*)zout + i4) = r;
}

// ---------------- bf16-split tensor-core GEMM (templated term count) ------------
template<int SA>
__global__ __launch_bounds__(256, 2) void gemm_bf(
    const u16* __restrict__ A0, const u16* __restrict__ A1, const u16* __restrict__ A2,
    const u32* __restrict__ B0, const u32* __restrict__ B1, const u32* __restrict__ B2,
    const float* __restrict__ bias, float oscale,
    float* __restrict__ Cf, u16* __restrict__ C0, u16* __restrict__ C1, u16* __restrict__ C2,
    int N, int K, int klen, int do_gelu)
{
    __shared__ __align__(16) u32 AF[2][1536];
    __shared__ __align__(16) u32 BF[2][3072];

    const int bx = blockIdx.x, by = blockIdx.y, bz = blockIdx.z;
    const int tid = threadIdx.x, lane = tid & 31, wid = tid >> 5;
    const int wm = wid >> 2, wn = wid & 3;
    const int K2 = K >> 1, N8 = N >> 3;
    const int NAS = (SA ? 2 : 6);

    const u32* apln[3] = {(const u32*)A0, (const u32*)A1, (const u32*)A2};
    const u32* ap[6];
    #pragma unroll
    for (int s = 0; s < NAS; s++) {
        int idx = s * 256 + tid;
        int j = idx & 3, ln = (idx >> 2) & 31, mt = (idx >> 7) & 3, pl = idx >> 9;
        int row = by * 64 + mt * 16 + (ln >> 2) + (j & 1) * 8;
        int c2 = (ln & 3) + (j >> 1) * 4;
        ap[s] = apln[pl] + (size_t)row * K2 + ((bz * klen) >> 1) + c2;
    }
    const u32* bpln[3] = {B0, B1, B2};
    const u32* bp[3];
    #pragma unroll
    for (int s = 0; s < 3; s++) {
        int idx4 = s * 256 + tid;
        int pl = idx4 >> 8, rem4 = idx4 & 255;
        int ntl = rem4 >> 4, lnp = (rem4 & 15) * 2;
        size_t goff = ((size_t)(((bz * klen) >> 4) * N8 + bx * 16 + ntl) * 32 + lnp) * 2;
        bp[s] = bpln[pl] + goff;
    }
    const size_t bstep = (size_t)N * 8;

    float acc[8][4];
    #pragma unroll
    for (int i = 0; i < 8; i++)
        #pragma unroll
        for (int j = 0; j < 4; j++) acc[i][j] = 0.f;

    const int nkt = klen >> 4;

    #pragma unroll
    for (int s = 0; s < NAS; s++) AF[0][s * 256 + tid] = ap[s][0];
    #pragma unroll
    for (int s = 0; s < 3; s++) *(uint4*)&BF[0][(s * 256 + tid) * 4] = *(const uint4*)bp[s];
    __syncthreads();

    u32 va[6]; uint4 vb[3];
    for (int kt = 0; kt < nkt; kt++) {
        const int cur = kt & 1;
        const bool more = (kt + 1 < nkt);
        if (more) {
            #pragma unroll
            for (int s = 0; s < NAS; s++) va[s] = ap[s][(kt + 1) * 8];
            #pragma unroll
            for (int s = 0; s < 3; s++) vb[s] = *(const uint4*)(bp[s] + (size_t)(kt + 1) * bstep);
        }

        uint4 aH[2], aM[2], aL[2];
        #pragma unroll
        for (int m2 = 0; m2 < 2; m2++) {
            int mt = wm * 2 + m2;
            aH[m2] = *(const uint4*)&AF[cur][(mt * 32 + lane) * 4];
            if (SA == 0) {
                aM[m2] = *(const uint4*)&AF[cur][((4 + mt) * 32 + lane) * 4];
                aL[m2] = *(const uint4*)&AF[cur][((8 + mt) * 32 + lane) * 4];
            }
        }
        #pragma unroll
        for (int n2 = 0; n2 < 4; n2++) {
            int nt = wn * 4 + n2;
            uint2 bH = *(const uint2*)&BF[cur][(nt * 32 + lane) * 2];
            uint2 bM = *(const uint2*)&BF[cur][1024 + (nt * 32 + lane) * 2];
            uint2 bL = *(const uint2*)&BF[cur][2048 + (nt * 32 + lane) * 2];
            #pragma unroll
            for (int m2 = 0; m2 < 2; m2++) {
                float cc[4] = {0.f, 0.f, 0.f, 0.f};
                if (SA == 1) {
                    mmabf(cc, aH[m2], bL);
                    mmabf(cc, aH[m2], bM);
                    mmabf(cc, aH[m2], bH);
                } else {
                    mmabf(cc, aM[m2], bM);
                    mmabf(cc, aH[m2], bL);
                    mmabf(cc, aL[m2], bH);
                    mmabf(cc, aM[m2], bH);
                    mmabf(cc, aH[m2], bM);
                    mmabf(cc, aH[m2], bH);
                }
                float* c = acc[m2 * 4 + n2];
                #pragma unroll
                for (int q = 0; q < 4; q++) c[q] += cc[q];
            }
        }

        if (more) {
            const int nx = cur ^ 1;
            #pragma unroll
            for (int s = 0; s < NAS; s++) AF[nx][s * 256 + tid] = va[s];
            #pragma unroll
            for (int s = 0; s < 3; s++) *(uint4*)&BF[nx][(s * 256 + tid) * 4] = vb[s];
        }
        __syncthreads();
    }

    float* Cp = Cf;
    if (Cp && gridDim.z > 1) Cp += (size_t)bz * ((size_t)NR * N);

    #pragma unroll
    for (int m2 = 0; m2 < 2; m2++)
        #pragma unroll
        for (int n2 = 0; n2 < 4; n2++) {
            float* c = acc[m2 * 4 + n2];
            int row = by * 64 + wm * 32 + m2 * 16 + (lane >> 2);
            int col = bx * 128 + wn * 32 + n2 * 8 + (lane & 3) * 2;
            float o0 = c[0] * oscale, o1 = c[1] * oscale,
                  o2 = c[2] * oscale, o3 = c[3] * oscale;
            if (bias) {
                float bb0 = bias[col], bb1 = bias[col + 1];
                o0 += bb0; o1 += bb1; o2 += bb0; o3 += bb1;
            }
            if (do_gelu) { o0 = gelu_f(o0); o1 = gelu_f(o1); o2 = gelu_f(o2); o3 = gelu_f(o3); }
            if (C0) {
                u16 h0, m0, l0, h1, m1, l1;
                split3(o0, h0, m0, l0); split3(o1, h1, m1, l1);
                size_t p = ((size_t)row * N + col) >> 1;
                ((u32*)C0)[p] = (u32)h0 | ((u32)h1 << 16);
                ((u32*)C1)[p] = (u32)m0 | ((u32)m1 << 16);
                ((u32*)C2)[p] = (u32)l0 | ((u32)l1 << 16);
                split3(o2, h0, m0, l0); split3(o3, h1, m1, l1);
                p = ((size_t)(row + 8) * N + col) >> 1;
                ((u32*)C0)[p] = (u32)h0 | ((u32)h1 << 16);
                ((u32*)C1)[p] = (u32)m0 | ((u32)m1 << 16);
                ((u32*)C2)[p] = (u32)l0 | ((u32)l1 << 16);
            } else {
                *(float2*)&Cp[(size_t)row * N + col] = make_float2(o0, o1);
                *(float2*)&Cp[(size_t)(row + 8) * N + col] = make_float2(o2, o3);
            }
        }
}

// ---------------- fused attention (32 query rows per block); ctx -> 3 bf16 planes
// per-row math identical to the 64-row version (bitwise-same outputs)
#define ATTN_SMEM_FLOATS (64*257 + 256*64 + 32*256 + 32*64)

__global__ __launch_bounds__(256) void attn_kernel(
    const float* __restrict__ qkv, const float* __restrict__ mask,
    float* __restrict__ asum, u16* __restrict__ ctxP,
    float wgt, int accum)
{
    extern __shared__ float smf[];
    float* Ks = smf;                    // [64][257]
    float* Vs = smf + 64 * 257;         // [256][64]
    float* Ss = Vs + 256 * 64;          // [32][256]
    float* Qs = Ss + 32 * 256;          // [32][64]

    const int rb = blockIdx.x, h = blockIdx.y, b = blockIdx.z;
    const int tid = threadIdx.x;
    const int lane = tid & 31, w = tid >> 5;
    const int i0 = rb * 32;
    const int dq = (tid & 15) * 4;
    const int jb = tid >> 4;

    const float* qb = qkv + ((size_t)b * NS + i0) * N3 + h * NDH;
    const float* kb = qkv + (size_t)b * NS * N3 + ND + h * NDH;
    const float* vb = qkv + (size_t)b * NS * N3 + 2 * ND + h * NDH;

    #pragma unroll
    for (int it = 0; it < 16; it++) {
        int j = jb + it * 16;
        float4 kv = *(const float4*)(kb + (size_t)j * N3 + dq);
        Ks[(dq + 0) * 257 + j] = kv.x;
        Ks[(dq + 1) * 257 + j] = kv.y;
        Ks[(dq + 2) * 257 + j] = kv.z;
        Ks[(dq + 3) * 257 + j] = kv.w;
        float4 vv = *(const float4*)(vb + (size_t)j * N3 + dq);
        *(float4*)&Vs[j * 64 + dq] = vv;
    }
    #pragma unroll
    for (int it = 0; it < 2; it++) {
        int i = jb + it * 16;
        float4 qv = *(const float4*)(qb + (size_t)i * N3 + dq);
        *(float4*)&Qs[i * 64 + dq] = qv;
    }
    __syncthreads();

    float extr[8];
    #pragma unroll
    for (int jj = 0; jj < 8; jj++)
        extr[jj] = (1.0f - mask[b * NS + lane + 32 * jj]) * -10000.0f;

    float acc[4][8];
    #pragma unroll
    for (int r = 0; r < 4; r++)
        #pragma unroll
        for (int jj = 0; jj < 8; jj++) acc[r][jj] = 0.f;

    const int r0 = w * 4;
    for (int d = 0; d < 64; d++) {
        float kr[8];
        #pragma unroll
        for (int jj = 0; jj < 8; jj++) kr[jj] = Ks[d * 257 + lane + 32 * jj];
        #pragma unroll
        for (int r = 0; r < 4; r++) {
            float qv = Qs[(r0 + r) * 64 + d];
            #pragma unroll
            for (int jj = 0; jj < 8; jj++) acc[r][jj] = fmaf(qv, kr[jj], acc[r][jj]);
        }
    }

    #pragma unroll
    for (int r = 0; r < 4; r++) {
        float mx = -3.0e38f;
        #pragma unroll
        for (int jj = 0; jj < 8; jj++) {
            float s = acc[r][jj] * 0.125f + extr[jj];
            acc[r][jj] = s;
            mx = fmaxf(mx, s);
        }
        #pragma unroll
        for (int o = 16; o; o >>= 1) mx = fmaxf(mx, __shfl_xor_sync(0xffffffffu, mx, o));
        float sum = 0.f;
        #pragma unroll
        for (int jj = 0; jj < 8; jj++) { float e = expf(acc[r][jj] - mx); acc[r][jj] = e; sum += e; }
        #pragma unroll
        for (int o = 16; o; o >>= 1) sum += __shfl_xor_sync(0xffffffffu, sum, o);
        float rinv = 1.0f / sum;
        int i = r0 + r;
        float* ar = asum + (((size_t)(b * NH + h)) * NS + (i0 + i)) * NS;
        #pragma unroll
        for (int jj = 0; jj < 8; jj++) {
            float p = acc[r][jj] * rinv;
            int j = lane + 32 * jj;
            Ss[i * 256 + j] = p;
            ar[j] = accum ? (ar[j] + p * wgt) : (p * wgt);
        }
    }
    __syncwarp();

    float c0[4], c1[4];
    #pragma unroll
    for (int r = 0; r < 4; r++) { c0[r] = 0.f; c1[r] = 0.f; }
    for (int j = 0; j < 256; j++) {
        float v0 = Vs[j * 64 + lane];
        float v1 = Vs[j * 64 + lane + 32];
        #pragma unroll
        for (int r = 0; r < 4; r++) {
            float p = Ss[(r0 + r) * 256 + j];
            c0[r] = fmaf(p, v0, c0[r]);
            c1[r] = fmaf(p, v1, c1[r]);
        }
    }
    #pragma unroll
    for (int r = 0; r < 4; r++) {
        size_t base = ((size_t)b * NS + i0 + r0 + r) * ND + h * NDH;
        u16 hh, mm, ll;
        split3(c0[r], hh, mm, ll);
        ctxP[base + lane] = hh;
        ctxP[PLsz + base + lane] = mm;
        ctxP[2 * PLsz + base + lane] = ll;
        split3(c1[r], hh, mm, ll);
        ctxP[base + lane + 32] = hh;
        ctxP[PLsz + base + lane + 32] = mm;
        ctxP[2 * PLsz + base + lane + 32] = ll;
    }
}

// ---------------- warp-per-row: residual + 4 partials + bias + LN + splits ------
// 8 warps/block, 1 row/warp, 24 elems/lane, shuffle-only reductions, no smem/barriers
__global__ __launch_bounds__(256) void add_ln4_kernel(
    const float* __restrict__ x, const float* __restrict__ part,
    const float* __restrict__ gbias,
    const float* __restrict__ g, const float* __restrict__ bb,
    float* __restrict__ out, u16* __restrict__ outP)
{
    const int lane = threadIdx.x & 31, w = threadIdx.x >> 5;
    const int row = blockIdx.x * 8 + w;
    const size_t base = (size_t)row * ND;
    const size_t slab = (size_t)PLsz;

    float4 s[6];
    float tot = 0.f;
    #pragma unroll
    for (int i = 0; i < 6; i++) {
        int col = i * 128 + lane * 4;
        size_t idx = base + col;
        float4 xv = *(const float4*)&x[idx];
        float4 p0 = *(const float4*)&part[idx];
        float4 p1 = *(const float4*)&part[idx + slab];
        float4 p2 = *(const float4*)&part[idx + 2 * slab];
        float4 p3 = *(const float4*)&part[idx + 3 * slab];
        float4 gb = *(const float4*)&gbias[col];
        s[i].x = xv.x + p0.x + p1.x + p2.x + p3.x + gb.x;
        s[i].y = xv.y + p0.y + p1.y + p2.y + p3.y + gb.y;
        s[i].z = xv.z + p0.z + p1.z + p2.z + p3.z + gb.z;
        s[i].w = xv.w + p0.w + p1.w + p2.w + p3.w + gb.w;
        tot += s[i].x + s[i].y + s[i].z + s[i].w;
    }
    float mean = warp_sum(tot) * (1.0f / 768.0f);
    float vtot = 0.f;
    #pragma unroll
    for (int i = 0; i < 6; i++) {
        s[i].x -= mean; s[i].y -= mean; s[i].z -= mean; s[i].w -= mean;
        vtot += s[i].x * s[i].x + s[i].y * s[i].y + s[i].z * s[i].z + s[i].w * s[i].w;
    }
    float rstd = 1.0f / sqrtf(warp_sum(vtot) * (1.0f / 768.0f) + 1e-12f);
    #pragma unroll
    for (int i = 0; i < 6; i++) {
        int col = i * 128 + lane * 4;
        float4 gv = *(const float4*)&g[col];
        float4 bv = *(const float4*)&bb[col];
        float o[4] = {gv.x * s[i].x * rstd + bv.x, gv.y * s[i].y * rstd + bv.y,
                      gv.z * s[i].z * rstd + bv.z, gv.w * s[i].w * rstd + bv.w};
        *(float4*)&out[base + col] = make_float4(o[0], o[1], o[2], o[3]);
        ushort4 vh, vm, vl;
        u16 h, m, l;
        split3(o[0], h, m, l); vh.x = h; vm.x = m; vl.x = l;
        split3(o[1], h, m, l); vh.y = h; vm.y = m; vl.y = l;
        split3(o[2], h, m, l); vh.z = h; vm.z = m; vl.z = l;
        split3(o[3], h, m, l); vh.w = h; vm.w = m; vl.w = l;
        *(ushort4*)&outP[base + col] = vh;
        *(ushort4*)&outP[slab + base + col] = vm;
        *(ushort4*)&outP[2 * slab + base + col] = vl;
    }
}

// ---------------- warp-per-row: residual + LN + IF spike --------------------------
__global__ __launch_bounds__(256) void add_ln_spike4_kernel(
    const float* __restrict__ x, const float* __restrict__ part,
    const float* __restrict__ gbias,
    const float* __restrict__ g, const float* __restrict__ bb,
    float* __restrict__ mem, float* __restrict__ cnt,
    float* __restrict__ prev, u16* __restrict__ cntP,
    float invt, float* __restrict__ zout, int first, float* __restrict__ curout)
{
    const int lane = threadIdx.x & 31, w = threadIdx.x >> 5;
    const int row = blockIdx.x * 8 + w;
    const size_t base = (size_t)row * ND;
    const size_t slab = (size_t)PLsz;

    float4 s[6];
    float tot = 0.f;
    #pragma unroll
    for (int i = 0; i < 6; i++) {
        int col = i * 128 + lane * 4;
        size_t idx = base + col;
        float4 xv = *(const float4*)&x[idx];
        float4 p0 = *(const float4*)&part[idx];
        float4 p1 = *(const float4*)&part[idx + slab];
        float4 p2 = *(const float4*)&part[idx + 2 * slab];
        float4 p3 = *(const float4*)&part[idx + 3 * slab];
        float4 gb = *(const float4*)&gbias[col];
        s[i].x = xv.x + p0.x + p1.x + p2.x + p3.x + gb.x;
        s[i].y = xv.y + p0.y + p1.y + p2.y + p3.y + gb.y;
        s[i].z = xv.z + p0.z + p1.z + p2.z + p3.z + gb.z;
        s[i].w = xv.w + p0.w + p1.w + p2.w + p3.w + gb.w;
        tot += s[i].x + s[i].y + s[i].z + s[i].w;
    }
    float mean = warp_sum(tot) * (1.0f / 768.0f);
    float vtot = 0.f;
    #pragma unroll
    for (int i = 0; i < 6; i++) {
        s[i].x -= mean; s[i].y -= mean; s[i].z -= mean; s[i].w -= mean;
        vtot += s[i].x * s[i].x + s[i].y * s[i].y + s[i].z * s[i].z + s[i].w * s[i].w;
    }
    float rstd = 1.0f / sqrtf(warp_sum(vtot) * (1.0f / 768.0f) + 1e-12f);

    #pragma unroll
    for (int i = 0; i < 6; i++) {
        int col = i * 128 + lane * 4;
        size_t idx = base + col;
        float4 gv = *(const float4*)&g[col];
        float4 bv = *(const float4*)&bb[col];
        float cur[4] = {gv.x * s[i].x * rstd + bv.x, gv.y * s[i].y * rstd + bv.y,
                        gv.z * s[i].z * rstd + bv.z, gv.w * s[i].w * rstd + bv.w};
        if (curout) {
            *(float4*)&curout[idx] = make_float4(cur[0], cur[1], cur[2], cur[3]);
            continue;
        }
        float4 mv = first ? make_float4(0.f, 0.f, 0.f, 0.f) : *(const float4*)&mem[idx];
        float4 cv = first ? make_float4(0.f, 0.f, 0.f, 0.f) : *(const float4*)&cnt[idx];
        float m[4] = {mv.x + cur[0], mv.y + cur[1], mv.z + cur[2], mv.w + cur[3]};
        float cvv[4] = {cv.x, cv.y, cv.z, cv.w};
        float cn[4], pv[4];
        #pragma unroll
        for (int e = 0; e < 4; e++) {
            float spk = (m[e] >= 1.0f) ? 1.0f : 0.0f;
            m[e] -= spk;
            cn[e] = cvv[e] + spk;
            pv[e] = cn[e] * invt;
        }
        *(float4*)&mem[idx] = make_float4(m[0], m[1], m[2], m[3]);
        *(float4*)&cnt[idx] = make_float4(cn[0], cn[1], cn[2], cn[3]);
        *(float4*)&prev[idx] = make_float4(pv[0], pv[1], pv[2], pv[3]);
        ushort4 cb;
        __nv_bfloat16 t;
        t = __float2bfloat16_rn(cn[0]); cb.x = reinterpret_cast<u16&>(t);
        t = __float2bfloat16_rn(cn[1]); cb.y = reinterpret_cast<u16&>(t);
        t = __float2bfloat16_rn(cn[2]); cb.z = reinterpret_cast<u16&>(t);
        t = __float2bfloat16_rn(cn[3]); cb.w = reinterpret_cast<u16&>(t);
        *(ushort4*)&cntP[idx] = cb;
        if (zout) *(float4*)&zout[idx] = make_float4(pv[0], pv[1], pv[2], pv[3]);
    }
}

// ---------------- launch ----------------
extern "C" void kernel_launch(void* const* d_in, const int* in_sizes, int n_in,
                              void* d_out, int out_size)
{
    const float* u    = (const float*)d_in[0];
    const int*   seg  = (const int*)d_in[1];
    const float* mask = (const float*)d_in[2];
    const float* semb = (const float*)d_in[3];
    const float* Wq   = (const float*)d_in[4];  const float* bq = (const float*)d_in[5];
    const float* Wk   = (const float*)d_in[6];  const float* bk = (const float*)d_in[7];
    const float* Wv   = (const float*)d_in[8];  const float* bv = (const float*)d_in[9];
    const float* Wo   = (const float*)d_in[10]; const float* bo = (const float*)d_in[11];
    const float* ln1g = (const float*)d_in[12]; const float* ln1b = (const float*)d_in[13];
    const float* W1   = (const float*)d_in[14]; const float* b1 = (const float*)d_in[15];
    const float* W2   = (const float*)d_in[16]; const float* b2 = (const float*)d_in[17];
    const float* ln2g = (const float*)d_in[18]; const float* ln2b = (const float*)d_in[19];
    // d_in[20] = time_step (always 6)

    float* out  = (float*)d_out;
    float* z    = out;
    float* attn = out + (size_t)5 * PLsz;

    void* p;
    #define FSYM(var, sym) cudaGetSymbolAddress(&p, sym); float* var = (float*)p
    #define USYM(var, sym) cudaGetSymbolAddress(&p, sym); u16* var = (u16*)p
    #define WSYM(var, sym) cudaGetSymbolAddress(&p, sym); u32* var = (u32*)p
    FSYM(xin,  g_xin);  FSYM(prev, g_prev); FSYM(x1, g_x1);
    FSYM(qkv,  g_qkv);  FSYM(aout, g_aout); FSYM(fout, g_fout);
    FSYM(cur0, g_cur0); FSYM(mem,  g_mem);  FSYM(cnt,  g_cnt);
    FSYM(bqkv, g_bqkv);
    USYM(xinP, g_xinP); USYM(cntP, g_cntP); USYM(x1P, g_x1P);
    USYM(ctxP, g_ctxP); USYM(ffhP, g_ffhP);
    WSYM(wqkvP, g_wqkvP); WSYM(woP, g_woP); WSYM(w1P, g_w1P); WSYM(w2P, g_w2P);
    #undef FSYM
    #undef USYM
    #undef WSYM

    cudaFuncSetAttribute(attn_kernel, cudaFuncAttributeMaxDynamicSharedMemorySize,
                         ATTN_SMEM_FLOATS * 4);

    pack_qkvw_all<<<(NL * QKV_KN2 + 255) / 256, 256>>>(Wq, Wk, Wv, bq, bk, bv);
    pack_w_all<<<(NL * WO_KN2 + 255) / 256, 256>>>(Wo, woP, ND, ND);
    pack_w_all<<<(NL * W1_KN2 + 255) / 256, 256>>>(W1, w1P, ND, NF);
    pack_w_all<<<(NL * W2_KN2 + 255) / 256, 256>>>(W2, w2P, NF, ND);
    xin_kernel<<<(NR * ND) / 256, 256>>>(u, seg, semb, z);

    const dim3 gQKV(N3 / 128, NR / 64, 1);   // 18x16
    const dim3 gO  (ND / 128, NR / 64, 4);   // split-K4, klen=192
    const dim3 gF1 (NF / 128, NR / 64, 1);   // 24x16
    const dim3 gF2 (ND / 128, NR / 64, 4);   // split-K4, klen=768
    const dim3 gAttn(8, NH, NB);             // 32 rows/block -> 384 blocks (86% wave fill)
    const int gLN = NR / 8;                  // warp-per-row LN kernels
    const float inv6 = 1.0f / 6.0f;

    // ---- layer 0: block output constant across time; compute once ----
    {
        gemm_bf<0><<<gQKV, 256>>>(xinP, xinP + PLsz, xinP + 2 * PLsz,
            wqkvP, wqkvP + QKV_KN2, wqkvP + 2 * (size_t)QKV_KN2,
            bqkv, 1.0f, qkv, 0, 0, 0, N3, ND, ND, 0);
        attn_kernel<<<gAttn, 256, ATTN_SMEM_FLOATS * 4>>>(qkv, mask, attn, ctxP, 1.0f, 0);
        gemm_bf<0><<<gO, 256>>>(ctxP, ctxP + PLsz, ctxP + 2 * PLsz,
            woP, woP + WO_KN2, woP + 2 * (size_t)WO_KN2,
            (const float*)0, 1.0f, aout, 0, 0, 0, ND, ND, ND / 4, 0);
        add_ln4_kernel<<<gLN, 256>>>(xin, aout, bo, ln1g, ln1b, x1, x1P);
        gemm_bf<0><<<gF1, 256>>>(x1P, x1P + PLsz, x1P + 2 * PLsz,
            w1P, w1P + W1_KN2, w1P + 2 * (size_t)W1_KN2,
            b1, 1.0f, 0, ffhP, ffhP + FFsz, ffhP + 2 * FFsz, NF, ND, ND, 1);
        gemm_bf<0><<<gF2, 256>>>(ffhP, ffhP + FFsz, ffhP + 2 * FFsz,
            w2P, w2P + W2_KN2, w2P + 2 * (size_t)W2_KN2,
            (const float*)0, 1.0f, fout, 0, 0, 0, ND, NF, NF / 4, 0);
        add_ln_spike4_kernel<<<gLN, 256>>>(x1, fout, b2, ln2g, ln2b,
            0, 0, 0, 0, 0.f, 0, 0, cur0);
    }

    for (int t = 0; t < NT; t++) {
        float tp1 = (float)(t + 1);
        float invt = 1.0f / tp1;
        rate0_kernel<<<(NR * ND / 4) / 256, 256>>>(tp1,
            (t == NT - 1) ? (z + (size_t)1 * PLsz) : (float*)0);

        for (int l = 1; l < NL; l++) {
            gemm_bf<1><<<gQKV, 256>>>(cntP, cntP, cntP,
                wqkvP + ((size_t)l * 3 + 0) * QKV_KN2,
                wqkvP + ((size_t)l * 3 + 1) * QKV_KN2,
                wqkvP + ((size_t)l * 3 + 2) * QKV_KN2,
                bqkv + l * N3, invt, qkv, 0, 0, 0, N3, ND, ND, 0);
            attn_kernel<<<gAttn, 256, ATTN_SMEM_FLOATS * 4>>>(
                qkv, mask, attn + (size_t)l * NB * NH * NS * NS, ctxP,
                inv6, (t > 0) ? 1 : 0);
            gemm_bf<0><<<gO, 256>>>(ctxP, ctxP + PLsz, ctxP + 2 * PLsz,
                woP + ((size_t)l * 3 + 0) * WO_KN2,
                woP + ((size_t)l * 3 + 1) * WO_KN2,
                woP + ((size_t)l * 3 + 2) * WO_KN2,
                (const float*)0, 1.0f, aout, 0, 0, 0, ND, ND, ND / 4, 0);
            add_ln4_kernel<<<gLN, 256>>>(prev, aout, bo + l * ND,
                ln1g + l * ND, ln1b + l * ND, x1, x1P);
            gemm_bf<0><<<gF1, 256>>>(x1P, x1P + PLsz, x1P + 2 * PLsz,
                w1P + ((size_t)l * 3 + 0) * W1_KN2,
                w1P + ((size_t)l * 3 + 1) * W1_KN2,
                w1P + ((size_t)l * 3 + 2) * W1_KN2,
                b1 + l * NF, 1.0f, 0, ffhP, ffhP + FFsz, ffhP + 2 * FFsz, NF, ND, ND, 1);
            gemm_bf<0><<<gF2, 256>>>(ffhP, ffhP + FFsz, ffhP + 2 * FFsz,
                w2P + ((size_t)l * 3 + 0) * W2_KN2,
                w2P + ((size_t)l * 3 + 1) * W2_KN2,
                w2P + ((size_t)l * 3 + 2) * W2_KN2,
                (const float*)0, 1.0f, fout, 0, 0, 0, ND, NF, NF / 4, 0);
            add_ln_spike4_kernel<<<gLN, 256>>>(x1, fout, b2 + l * ND,
                ln2g + l * ND, ln2b + l * ND,
                mem + (size_t)l * PLsz, cnt + (size_t)l * PLsz,
                prev, cntP, invt,
                (t == NT - 1) ? (z + (size_t)(1 + l) * PLsz) : (float*)0,
                (t == 0) ? 1 : 0, 0);
        }
    }
}

// round 15
// speedup vs baseline: 1.8711x; 1.0051x over previous
#include <cuda_runtime.h>
#include <cuda_bf16.h>
#include <math.h>

#define NB 4
#define NS 256
#define ND 768
#define NF 3072
#define NL 4
#define NH 12
#define NDH 64
#define NR (NB*NS)   /* 1024 rows */
#define NT 6
#define N3 (3*ND)    /* 2304 */

typedef unsigned int u32;
typedef unsigned short u16;

#define PLsz (NR*ND)
#define FFsz (NR*NF)

// ---------------- scratch (static device globals; no allocs) ----------------
static __device__ float g_xin [PLsz];
static __device__ float g_prev[PLsz];
static __device__ float g_x1  [PLsz];
static __device__ float g_qkv [NR*N3];
static __device__ float g_aout[4*PLsz];
static __device__ float g_fout[4*PLsz];
static __device__ float g_cur0[PLsz];
static __device__ float g_mem [NL*PLsz];
static __device__ float g_cnt [NL*PLsz];
static __device__ float g_bqkv[NL*N3];

// bf16 activation planes
static __device__ u16 g_xinP [3*PLsz];
static __device__ u16 g_cntP [PLsz];
static __device__ u16 g_x1P  [3*PLsz];
static __device__ u16 g_ctxP [3*PLsz];
static __device__ u16 g_ffhP [3*FFsz];

// fragment-packed weights (u32 = bf16 pair): [l][plane][K*N/2]
#define QKV_KN2 (ND*N3/2)
#define WO_KN2  (ND*ND/2)
#define W1_KN2  (ND*NF/2)
#define W2_KN2  (NF*ND/2)
static __device__ u32 g_wqkvP[NL*3*QKV_KN2];
static __device__ u32 g_woP  [NL*3*WO_KN2];
static __device__ u32 g_w1P  [NL*3*W1_KN2];
static __device__ u32 g_w2P  [NL*3*W2_KN2];

// ---------------- helpers ----------------
__device__ __forceinline__ void split3(float a, u16& h, u16& m, u16& l) {
    __nv_bfloat16 bh = __float2bfloat16_rn(a);
    float r1 = a - __bfloat162float(bh);
    __nv_bfloat16 bm = __float2bfloat16_rn(r1);
    float r2 = r1 - __bfloat162float(bm);
    __nv_bfloat16 bl = __float2bfloat16_rn(r2);
    h = reinterpret_cast<u16&>(bh);
    m = reinterpret_cast<u16&>(bm);
    l = reinterpret_cast<u16&>(bl);
}

__device__ __forceinline__ float gelu_f(float x) {
    float x3 = x * x * x;
    float t = tanhf(0.7978845608028654f * (x + 0.044715f * x3));
    return 0.5f * x * (1.0f + t);
}

__device__ __forceinline__ float warp_sum(float v) {
    #pragma unroll
    for (int o = 16; o; o >>= 1) v += __shfl_xor_sync(0xffffffffu, v, o);
    return v;
}

__device__ __forceinline__ void mmabf(float* c, const uint4 a, const uint2 b) {
    asm volatile(
        "mma.sync.aligned.m16n8k16.row.col.f32.bf16.bf16.f32 "
        "{%0,%1,%2,%3},{%4,%5,%6,%7},{%8,%9},{%0,%1,%2,%3};"
        : "+f"(c[0]), "+f"(c[1]), "+f"(c[2]), "+f"(c[3])
        : "r"(a.x), "r"(a.y), "r"(a.z), "r"(a.w), "r"(b.x), "r"(b.y));
}

#define CPA4(dst, src) \
    asm volatile("cp.async.ca.shared.global [%0], [%1], 4;" :: "r"(dst), "l"(src))
#define CPA16(dst, src) \
    asm volatile("cp.async.cg.shared.global [%0], [%1], 16;" :: "r"(dst), "l"(src))
#define CPA_COMMIT() asm volatile("cp.async.commit_group;" ::: "memory")
#define CPA_WAIT2()  asm volatile("cp.async.wait_group 2;" ::: "memory")

// ---------------- all-layer weight packing into B-fragment layout ----------------
__global__ __launch_bounds__(256) void pack_w_all(
    const float* __restrict__ W, u32* __restrict__ base, int K, int N)
{
    int pos = blockIdx.x * 256 + threadIdx.x;
    const int KN2 = K * N / 2;
    if (pos >= NL * KN2) return;
    int l = pos / KN2, r = pos - l * KN2;
    int perchunk = N * 8;
    int kc = r / perchunk;
    int rem = r - kc * perchunk;
    int nt = rem >> 6;
    int r2 = rem & 63;
    int ln = r2 >> 1, j = r2 & 1;
    int k = kc * 16 + (ln & 3) * 2 + j * 8;
    int n = nt * 8 + (ln >> 2);
    const float* Wl = W + (size_t)l * K * N;
    float w0 = Wl[(size_t)k * N + n];
    float w1 = Wl[(size_t)(k + 1) * N + n];
    u16 h0, m0, l0, h1, m1, l1;
    split3(w0, h0, m0, l0);
    split3(w1, h1, m1, l1);
    base[((size_t)l * 3 + 0) * KN2 + r] = (u32)h0 | ((u32)h1 << 16);
    base[((size_t)l * 3 + 1) * KN2 + r] = (u32)m0 | ((u32)m1 << 16);
    base[((size_t)l * 3 + 2) * KN2 + r] = (u32)l0 | ((u32)l1 << 16);
}

__global__ __launch_bounds__(256) void pack_qkvw_all(
    const float* __restrict__ Wq, const float* __restrict__ Wk, const float* __restrict__ Wv,
    const float* __restrict__ bq, const float* __restrict__ bk, const float* __restrict__ bv)
{
    int pos = blockIdx.x * 256 + threadIdx.x;
    if (pos < NL * N3) {
        int l = pos / N3, n = pos - l * N3;
        int which = n / ND, nn = n - which * ND;
        const float* b = (which == 0) ? bq : (which == 1) ? bk : bv;
        g_bqkv[pos] = b[l * ND + nn];
    }
    if (pos >= NL * QKV_KN2) return;
    int l = pos / QKV_KN2, r = pos - l * QKV_KN2;
    const int N = N3;
    int perchunk = N * 8;
    int kc = r / perchunk;
    int rem = r - kc * perchunk;
    int nt = rem >> 6;
    int r2 = rem & 63;
    int ln = r2 >> 1, j = r2 & 1;
    int k = kc * 16 + (ln & 3) * 2 + j * 8;
    int n = nt * 8 + (ln >> 2);
    int which = n / ND, nn = n - which * ND;
    const float* W = ((which == 0) ? Wq : (which == 1) ? Wk : Wv) + (size_t)l * ND * ND;
    float w0 = W[(size_t)k * ND + nn];
    float w1 = W[(size_t)(k + 1) * ND + nn];
    u16 h0, m0, l0, h1, m1, l1;
    split3(w0, h0, m0, l0);
    split3(w1, h1, m1, l1);
    g_wqkvP[((size_t)l * 3 + 0) * QKV_KN2 + r] = (u32)h0 | ((u32)h1 << 16);
    g_wqkvP[((size_t)l * 3 + 1) * QKV_KN2 + r] = (u32)m0 | ((u32)m1 << 16);
    g_wqkvP[((size_t)l * 3 + 2) * QKV_KN2 + r] = (u32)l0 | ((u32)l1 << 16);
}

// ---------------- x_in = u + seg_emb[segment_ids]; z[0]; splits ----------------
__global__ __launch_bounds__(256) void xin_kernel(
    const float* __restrict__ u, const int* __restrict__ seg,
    const float* __restrict__ semb, float* __restrict__ z0)
{
    int idx = blockIdx.x * 256 + threadIdx.x;
    int srow = idx / ND;
    int d = idx - srow * ND;
    float val = u[idx] + semb[seg[srow] * ND + d];
    g_xin[idx] = val;
    z0[idx] = val;
    u16 h, m, l; split3(val, h, m, l);
    g_xinP[idx] = h; g_xinP[PLsz + idx] = m; g_xinP[2 * PLsz + idx] = l;
}

// ---------------- layer-0 closed-form spike rate (float4) ----------------
__global__ __launch_bounds__(256) void rate0_kernel(float tplus1, float* __restrict__ zout)
{
    int i4 = blockIdx.x * 256 + threadIdx.x;
    float4 c = *((const float4*)g_cur0 + i4);
    float f0 = fminf(fmaxf(floorf(tplus1 * c.x), 0.f), tplus1);
    float f1 = fminf(fmaxf(floorf(tplus1 * c.y), 0.f), tplus1);
    float f2 = fminf(fmaxf(floorf(tplus1 * c.z), 0.f), tplus1);
    float f3 = fminf(fmaxf(floorf(tplus1 * c.w), 0.f), tplus1);
    float inv = 1.0f / tplus1;
    float4 r = make_float4(f0 * inv, f1 * inv, f2 * inv, f3 * inv);
    *((float4*)g_prev + i4) = r;
    ushort4 cb;
    __nv_bfloat16 t;
    t = __float2bfloat16_rn(f0); cb.x = reinterpret_cast<u16&>(t);
    t = __float2bfloat16_rn(f1); cb.y = reinterpret_cast<u16&>(t);
    t = __float2bfloat16_rn(f2); cb.z = reinterpret_cast<u16&>(t);
    t = __float2bfloat16_rn(f3); cb.w = reinterpret_cast<u16&>(t);
    *((ushort4*)g_cntP + i4) = cb;
    if (zout) *((float4*)zout + i4) = r;
}

// ---------------- bf16-split tensor-core GEMM, cp.async 4-stage pipeline --------
// SA=0: 6 terms; SA=1: 3 terms on exact single-plane cnt, oscale in epilogue.
// Per-chunk zeroed MMA accumulator + fp32 RN drain (math identical to R13/R14).
// smem: 4 stages x (AF 1536 + BF 3072) u32 = 73728 B dynamic.
#define GB_STAGES 4
#define GB_AF 1536
#define GB_BF 3072
#define GB_SMEM ((GB_STAGES * (GB_AF + GB_BF)) * 4)

template<int SA>
__global__ __launch_bounds__(256, 2) void gemm_bf(
    const u16* __restrict__ A0, const u16* __restrict__ A1, const u16* __restrict__ A2,
    const u32* __restrict__ B0, const u32* __restrict__ B1, const u32* __restrict__ B2,
    const float* __restrict__ bias, float oscale,
    float* __restrict__ Cf, u16* __restrict__ C0, u16* __restrict__ C1, u16* __restrict__ C2,
    int N, int K, int klen, int do_gelu)
{
    extern __shared__ __align__(16) u32 smemraw[];
    u32* AF = smemraw;                       // [stage][1536]
    u32* BF = smemraw + GB_STAGES * GB_AF;   // [stage][3072]

    const int bx = blockIdx.x, by = blockIdx.y, bz = blockIdx.z;
    const int tid = threadIdx.x, lane = tid & 31, wid = tid >> 5;
    const int wm = wid >> 2, wn = wid & 3;
    const int K2 = K >> 1, N8 = N >> 3;
    const int NAS = (SA ? 2 : 6);

    const u32 afb = (u32)__cvta_generic_to_shared(AF);
    const u32 bfb = (u32)__cvta_generic_to_shared(BF);

    // A producer slots (u32 each)
    const u32* apln[3] = {(const u32*)A0, (const u32*)A1, (const u32*)A2};
    const u32* ap[6];
    #pragma unroll
    for (int s = 0; s < NAS; s++) {
        int idx = s * 256 + tid;
        int j = idx & 3, ln = (idx >> 2) & 31, mt = (idx >> 7) & 3, pl = idx >> 9;
        int row = by * 64 + mt * 16 + (ln >> 2) + (j & 1) * 8;
        int c2 = (ln & 3) + (j >> 1) * 4;
        ap[s] = apln[pl] + (size_t)row * K2 + ((bz * klen) >> 1) + c2;
    }
    // B producer slots (uint4 each)
    const u32* bpln[3] = {B0, B1, B2};
    const u32* bp[3];
    #pragma unroll
    for (int s = 0; s < 3; s++) {
        int idx4 = s * 256 + tid;
        int pl = idx4 >> 8, rem4 = idx4 & 255;
        int ntl = rem4 >> 4, lnp = (rem4 & 15) * 2;
        size_t goff = ((size_t)(((bz * klen) >> 4) * N8 + bx * 16 + ntl) * 32 + lnp) * 2;
        bp[s] = bpln[pl] + goff;
    }
    const size_t bstep = (size_t)N * 8;

    float acc[8][4];
    #pragma unroll
    for (int i = 0; i < 8; i++)
        #pragma unroll
        for (int j = 0; j < 4; j++) acc[i][j] = 0.f;

    const int nkt = klen >> 4;

    // ---- prologue: async-fill stages 0 and 1 ----
    #pragma unroll
    for (int pk = 0; pk < 2; pk++) {
        #pragma unroll
        for (int s = 0; s < NAS; s++)
            CPA4(afb + (u32)(pk * GB_AF + s * 256 + tid) * 4, ap[s] + pk * 8);
        #pragma unroll
        for (int s = 0; s < 3; s++)
            CPA16(bfb + (u32)(pk * GB_BF + (s * 256 + tid) * 4) * 4,
                  bp[s] + (size_t)pk * bstep);
        CPA_COMMIT();
    }

    for (int kt = 0; kt < nkt; kt++) {
        const int st = kt & 3;
        // issue stage kt+2
        if (kt + 2 < nkt) {
            const int ns = (kt + 2) & 3;
            #pragma unroll
            for (int s = 0; s < NAS; s++)
                CPA4(afb + (u32)(ns * GB_AF + s * 256 + tid) * 4, ap[s] + (kt + 2) * 8);
            #pragma unroll
            for (int s = 0; s < 3; s++)
                CPA16(bfb + (u32)(ns * GB_BF + (s * 256 + tid) * 4) * 4,
                      bp[s] + (size_t)(kt + 2) * bstep);
        }
        CPA_COMMIT();   // always commit (possibly empty) to keep group count invariant
        CPA_WAIT2();    // stage kt's group retired
        __syncthreads();

        const u32* AFc = AF + st * GB_AF;
        const u32* BFc = BF + st * GB_BF;

        uint4 aH[2], aM[2], aL[2];
        #pragma unroll
        for (int m2 = 0; m2 < 2; m2++) {
            int mt = wm * 2 + m2;
            aH[m2] = *(const uint4*)&AFc[(mt * 32 + lane) * 4];
            if (SA == 0) {
                aM[m2] = *(const uint4*)&AFc[((4 + mt) * 32 + lane) * 4];
                aL[m2] = *(const uint4*)&AFc[((8 + mt) * 32 + lane) * 4];
            }
        }
        #pragma unroll
        for (int n2 = 0; n2 < 4; n2++) {
            int nt = wn * 4 + n2;
            uint2 bH = *(const uint2*)&BFc[(nt * 32 + lane) * 2];
            uint2 bM = *(const uint2*)&BFc[1024 + (nt * 32 + lane) * 2];
            uint2 bL = *(const uint2*)&BFc[2048 + (nt * 32 + lane) * 2];
            #pragma unroll
            for (int m2 = 0; m2 < 2; m2++) {
                float cc[4] = {0.f, 0.f, 0.f, 0.f};
                if (SA == 1) {
                    mmabf(cc, aH[m2], bL);
                    mmabf(cc, aH[m2], bM);
                    mmabf(cc, aH[m2], bH);
                } else {
                    mmabf(cc, aM[m2], bM);
                    mmabf(cc, aH[m2], bL);
                    mmabf(cc, aL[m2], bH);
                    mmabf(cc, aM[m2], bH);
                    mmabf(cc, aH[m2], bM);
                    mmabf(cc, aH[m2], bH);
                }
                float* c = acc[m2 * 4 + n2];
                #pragma unroll
                for (int q = 0; q < 4; q++) c[q] += cc[q];
            }
        }
        // barrier at top of next iteration protects stage reuse (4-stage ring:
        // writes target (kt+3)&3 while reads are kt&3 within any barrier window)
    }

    float* Cp = Cf;
    if (Cp && gridDim.z > 1) Cp += (size_t)bz * ((size_t)NR * N);

    #pragma unroll
    for (int m2 = 0; m2 < 2; m2++)
        #pragma unroll
        for (int n2 = 0; n2 < 4; n2++) {
            float* c = acc[m2 * 4 + n2];
            int row = by * 64 + wm * 32 + m2 * 16 + (lane >> 2);
            int col = bx * 128 + wn * 32 + n2 * 8 + (lane & 3) * 2;
            float o0 = c[0] * oscale, o1 = c[1] * oscale,
                  o2 = c[2] * oscale, o3 = c[3] * oscale;
            if (bias) {
                float bb0 = bias[col], bb1 = bias[col + 1];
                o0 += bb0; o1 += bb1; o2 += bb0; o3 += bb1;
            }
            if (do_gelu) { o0 = gelu_f(o0); o1 = gelu_f(o1); o2 = gelu_f(o2); o3 = gelu_f(o3); }
            if (C0) {
                u16 h0, m0, l0, h1, m1, l1;
                split3(o0, h0, m0, l0); split3(o1, h1, m1, l1);
                size_t p = ((size_t)row * N + col) >> 1;
                ((u32*)C0)[p] = (u32)h0 | ((u32)h1 << 16);
                ((u32*)C1)[p] = (u32)m0 | ((u32)m1 << 16);
                ((u32*)C2)[p] = (u32)l0 | ((u32)l1 << 16);
                split3(o2, h0, m0, l0); split3(o3, h1, m1, l1);
                p = ((size_t)(row + 8) * N + col) >> 1;
                ((u32*)C0)[p] = (u32)h0 | ((u32)h1 << 16);
                ((u32*)C1)[p] = (u32)m0 | ((u32)m1 << 16);
                ((u32*)C2)[p] = (u32)l0 | ((u32)l1 << 16);
            } else {
                *(float2*)&Cp[(size_t)row * N + col] = make_float2(o0, o1);
                *(float2*)&Cp[(size_t)(row + 8) * N + col] = make_float2(o2, o3);
            }
        }
}

// ---------------- fused attention (32 query rows per block); ctx -> 3 bf16 planes
#define ATTN_SMEM_FLOATS (64*257 + 256*64 + 32*256 + 32*64)

__global__ __launch_bounds__(256) void attn_kernel(
    const float* __restrict__ qkv, const float* __restrict__ mask,
    float* __restrict__ asum, u16* __restrict__ ctxP,
    float wgt, int accum)
{
    extern __shared__ float smf[];
    float* Ks = smf;                    // [64][257]
    float* Vs = smf + 64 * 257;         // [256][64]
    float* Ss = Vs + 256 * 64;          // [32][256]
    float* Qs = Ss + 32 * 256;          // [32][64]

    const int rb = blockIdx.x, h = blockIdx.y, b = blockIdx.z;
    const int tid = threadIdx.x;
    const int lane = tid & 31, w = tid >> 5;
    const int i0 = rb * 32;
    const int dq = (tid & 15) * 4;
    const int jb = tid >> 4;

    const float* qb = qkv + ((size_t)b * NS + i0) * N3 + h * NDH;
    const float* kb = qkv + (size_t)b * NS * N3 + ND + h * NDH;
    const float* vb = qkv + (size_t)b * NS * N3 + 2 * ND + h * NDH;

    #pragma unroll
    for (int it = 0; it < 16; it++) {
        int j = jb + it * 16;
        float4 kv = *(const float4*)(kb + (size_t)j * N3 + dq);
        Ks[(dq + 0) * 257 + j] = kv.x;
        Ks[(dq + 1) * 257 + j] = kv.y;
        Ks[(dq + 2) * 257 + j] = kv.z;
        Ks[(dq + 3) * 257 + j] = kv.w;
        float4 vv = *(const float4*)(vb + (size_t)j * N3 + dq);
        *(float4*)&Vs[j * 64 + dq] = vv;
    }
    #pragma unroll
    for (int it = 0; it < 2; it++) {
        int i = jb + it * 16;
        float4 qv = *(const float4*)(qb + (size_t)i * N3 + dq);
        *(float4*)&Qs[i * 64 + dq] = qv;
    }
    __syncthreads();

    float extr[8];
    #pragma unroll
    for (int jj = 0; jj < 8; jj++)
        extr[jj] = (1.0f - mask[b * NS + lane + 32 * jj]) * -10000.0f;

    float acc[4][8];
    #pragma unroll
    for (int r = 0; r < 4; r++)
        #pragma unroll
        for (int jj = 0; jj < 8; jj++) acc[r][jj] = 0.f;

    const int r0 = w * 4;
    for (int d = 0; d < 64; d++) {
        float kr[8];
        #pragma unroll
        for (int jj = 0; jj < 8; jj++) kr[jj] = Ks[d * 257 + lane + 32 * jj];
        #pragma unroll
        for (int r = 0; r < 4; r++) {
            float qv = Qs[(r0 + r) * 64 + d];
            #pragma unroll
            for (int jj = 0; jj < 8; jj++) acc[r][jj] = fmaf(qv, kr[jj], acc[r][jj]);
        }
    }

    #pragma unroll
    for (int r = 0; r < 4; r++) {
        float mx = -3.0e38f;
        #pragma unroll
        for (int jj = 0; jj < 8; jj++) {
            float s = acc[r][jj] * 0.125f + extr[jj];
            acc[r][jj] = s;
            mx = fmaxf(mx, s);
        }
        #pragma unroll
        for (int o = 16; o; o >>= 1) mx = fmaxf(mx, __shfl_xor_sync(0xffffffffu, mx, o));
        float sum = 0.f;
        #pragma unroll
        for (int jj = 0; jj < 8; jj++) { float e = expf(acc[r][jj] - mx); acc[r][jj] = e; sum += e; }
        #pragma unroll
        for (int o = 16; o; o >>= 1) sum += __shfl_xor_sync(0xffffffffu, sum, o);
        float rinv = 1.0f / sum;
        int i = r0 + r;
        float* ar = asum + (((size_t)(b * NH + h)) * NS + (i0 + i)) * NS;
        #pragma unroll
        for (int jj = 0; jj < 8; jj++) {
            float p = acc[r][jj] * rinv;
            int j = lane + 32 * jj;
            Ss[i * 256 + j] = p;
            ar[j] = accum ? (ar[j] + p * wgt) : (p * wgt);
        }
    }
    __syncwarp();

    float c0[4], c1[4];
    #pragma unroll
    for (int r = 0; r < 4; r++) { c0[r] = 0.f; c1[r] = 0.f; }
    for (int j = 0; j < 256; j++) {
        float v0 = Vs[j * 64 + lane];
        float v1 = Vs[j * 64 + lane + 32];
        #pragma unroll
        for (int r = 0; r < 4; r++) {
            float p = Ss[(r0 + r) * 256 + j];
            c0[r] = fmaf(p, v0, c0[r]);
            c1[r] = fmaf(p, v1, c1[r]);
        }
    }
    #pragma unroll
    for (int r = 0; r < 4; r++) {
        size_t base = ((size_t)b * NS + i0 + r0 + r) * ND + h * NDH;
        u16 hh, mm, ll;
        split3(c0[r], hh, mm, ll);
        ctxP[base + lane] = hh;
        ctxP[PLsz + base + lane] = mm;
        ctxP[2 * PLsz + base + lane] = ll;
        split3(c1[r], hh, mm, ll);
        ctxP[base + lane + 32] = hh;
        ctxP[PLsz + base + lane + 32] = mm;
        ctxP[2 * PLsz + base + lane + 32] = ll;
    }
}

// ---------------- warp-per-row: residual + 4 partials + bias + LN + splits ------
__global__ __launch_bounds__(256) void add_ln4_kernel(
    const float* __restrict__ x, const float* __restrict__ part,
    const float* __restrict__ gbias,
    const float* __restrict__ g, const float* __restrict__ bb,
    float* __restrict__ out, u16* __restrict__ outP)
{
    const int lane = threadIdx.x & 31, w = threadIdx.x >> 5;
    const int row = blockIdx.x * 8 + w;
    const size_t base = (size_t)row * ND;
    const size_t slab = (size_t)PLsz;

    float4 s[6];
    float tot = 0.f;
    #pragma unroll
    for (int i = 0; i < 6; i++) {
        int col = i * 128 + lane * 4;
        size_t idx = base + col;
        float4 xv = *(const float4*)&x[idx];
        float4 p0 = *(const float4*)&part[idx];
        float4 p1 = *(const float4*)&part[idx + slab];
        float4 p2 = *(const float4*)&part[idx + 2 * slab];
        float4 p3 = *(const float4*)&part[idx + 3 * slab];
        float4 gb = *(const float4*)&gbias[col];
        s[i].x = xv.x + p0.x + p1.x + p2.x + p3.x + gb.x;
        s[i].y = xv.y + p0.y + p1.y + p2.y + p3.y + gb.y;
        s[i].z = xv.z + p0.z + p1.z + p2.z + p3.z + gb.z;
        s[i].w = xv.w + p0.w + p1.w + p2.w + p3.w + gb.w;
        tot += s[i].x + s[i].y + s[i].z + s[i].w;
    }
    float mean = warp_sum(tot) * (1.0f / 768.0f);
    float vtot = 0.f;
    #pragma unroll
    for (int i = 0; i < 6; i++) {
        s[i].x -= mean; s[i].y -= mean; s[i].z -= mean; s[i].w -= mean;
        vtot += s[i].x * s[i].x + s[i].y * s[i].y + s[i].z * s[i].z + s[i].w * s[i].w;
    }
    float rstd = 1.0f / sqrtf(warp_sum(vtot) * (1.0f / 768.0f) + 1e-12f);
    #pragma unroll
    for (int i = 0; i < 6; i++) {
        int col = i * 128 + lane * 4;
        float4 gv = *(const float4*)&g[col];
        float4 bv = *(const float4*)&bb[col];
        float o[4] = {gv.x * s[i].x * rstd + bv.x, gv.y * s[i].y * rstd + bv.y,
                      gv.z * s[i].z * rstd + bv.z, gv.w * s[i].w * rstd + bv.w};
        *(float4*)&out[base + col] = make_float4(o[0], o[1], o[2], o[3]);
        ushort4 vh, vm, vl;
        u16 h, m, l;
        split3(o[0], h, m, l); vh.x = h; vm.x = m; vl.x = l;
        split3(o[1], h, m, l); vh.y = h; vm.y = m; vl.y = l;
        split3(o[2], h, m, l); vh.z = h; vm.z = m; vl.z = l;
        split3(o[3], h, m, l); vh.w = h; vm.w = m; vl.w = l;
        *(ushort4*)&outP[base + col] = vh;
        *(ushort4*)&outP[slab + base + col] = vm;
        *(ushort4*)&outP[2 * slab + base + col] = vl;
    }
}

// ---------------- warp-per-row: residual + LN + IF spike --------------------------
__global__ __launch_bounds__(256) void add_ln_spike4_kernel(
    const float* __restrict__ x, const float* __restrict__ part,
    const float* __restrict__ gbias,
    const float* __restrict__ g, const float* __restrict__ bb,
    float* __restrict__ mem, float* __restrict__ cnt,
    float* __restrict__ prev, u16* __restrict__ cntP,
    float invt, float* __restrict__ zout, int first, float* __restrict__ curout)
{
    const int lane = threadIdx.x & 31, w = threadIdx.x >> 5;
    const int row = blockIdx.x * 8 + w;
    const size_t base = (size_t)row * ND;
    const size_t slab = (size_t)PLsz;

    float4 s[6];
    float tot = 0.f;
    #pragma unroll
    for (int i = 0; i < 6; i++) {
        int col = i * 128 + lane * 4;
        size_t idx = base + col;
        float4 xv = *(const float4*)&x[idx];
        float4 p0 = *(const float4*)&part[idx];
        float4 p1 = *(const float4*)&part[idx + slab];
        float4 p2 = *(const float4*)&part[idx + 2 * slab];
        float4 p3 = *(const float4*)&part[idx + 3 * slab];
        float4 gb = *(const float4*)&gbias[col];
        s[i].x = xv.x + p0.x + p1.x + p2.x + p3.x + gb.x;
        s[i].y = xv.y + p0.y + p1.y + p2.y + p3.y + gb.y;
        s[i].z = xv.z + p0.z + p1.z + p2.z + p3.z + gb.z;
        s[i].w = xv.w + p0.w + p1.w + p2.w + p3.w + gb.w;
        tot += s[i].x + s[i].y + s[i].z + s[i].w;
    }
    float mean = warp_sum(tot) * (1.0f / 768.0f);
    float vtot = 0.f;
    #pragma unroll
    for (int i = 0; i < 6; i++) {
        s[i].x -= mean; s[i].y -= mean; s[i].z -= mean; s[i].w -= mean;
        vtot += s[i].x * s[i].x + s[i].y * s[i].y + s[i].z * s[i].z + s[i].w * s[i].w;
    }
    float rstd = 1.0f / sqrtf(warp_sum(vtot) * (1.0f / 768.0f) + 1e-12f);

    #pragma unroll
    for (int i = 0; i < 6; i++) {
        int col = i * 128 + lane * 4;
        size_t idx = base + col;
        float4 gv = *(const float4*)&g[col];
        float4 bv = *(const float4*)&bb[col];
        float cur[4] = {gv.x * s[i].x * rstd + bv.x, gv.y * s[i].y * rstd + bv.y,
                        gv.z * s[i].z * rstd + bv.z, gv.w * s[i].w * rstd + bv.w};
        if (curout) {
            *(float4*)&curout[idx] = make_float4(cur[0], cur[1], cur[2], cur[3]);
            continue;
        }
        float4 mv = first ? make_float4(0.f, 0.f, 0.f, 0.f) : *(const float4*)&mem[idx];
        float4 cv = first ? make_float4(0.f, 0.f, 0.f, 0.f) : *(const float4*)&cnt[idx];
        float m[4] = {mv.x + cur[0], mv.y + cur[1], mv.z + cur[2], mv.w + cur[3]};
        float cvv[4] = {cv.x, cv.y, cv.z, cv.w};
        float cn[4], pv[4];
        #pragma unroll
        for (int e = 0; e < 4; e++) {
            float spk = (m[e] >= 1.0f) ? 1.0f : 0.0f;
            m[e] -= spk;
            cn[e] = cvv[e] + spk;
            pv[e] = cn[e] * invt;
        }
        *(float4*)&mem[idx] = make_float4(m[0], m[1], m[2], m[3]);
        *(float4*)&cnt[idx] = make_float4(cn[0], cn[1], cn[2], cn[3]);
        *(float4*)&prev[idx] = make_float4(pv[0], pv[1], pv[2], pv[3]);
        ushort4 cb;
        __nv_bfloat16 t;
        t = __float2bfloat16_rn(cn[0]); cb.x = reinterpret_cast<u16&>(t);
        t = __float2bfloat16_rn(cn[1]); cb.y = reinterpret_cast<u16&>(t);
        t = __float2bfloat16_rn(cn[2]); cb.z = reinterpret_cast<u16&>(t);
        t = __float2bfloat16_rn(cn[3]); cb.w = reinterpret_cast<u16&>(t);
        *(ushort4*)&cntP[idx] = cb;
        if (zout) *(float4*)&zout[idx] = make_float4(pv[0], pv[1], pv[2], pv[3]);
    }
}

// ---------------- launch ----------------
extern "C" void kernel_launch(void* const* d_in, const int* in_sizes, int n_in,
                              void* d_out, int out_size)
{
    const float* u    = (const float*)d_in[0];
    const int*   seg  = (const int*)d_in[1];
    const float* mask = (const float*)d_in[2];
    const float* semb = (const float*)d_in[3];
    const float* Wq   = (const float*)d_in[4];  const float* bq = (const float*)d_in[5];
    const float* Wk   = (const float*)d_in[6];  const float* bk = (const float*)d_in[7];
    const float* Wv   = (const float*)d_in[8];  const float* bv = (const float*)d_in[9];
    const float* Wo   = (const float*)d_in[10]; const float* bo = (const float*)d_in[11];
    const float* ln1g = (const float*)d_in[12]; const float* ln1b = (const float*)d_in[13];
    const float* W1   = (const float*)d_in[14]; const float* b1 = (const float*)d_in[15];
    const float* W2   = (const float*)d_in[16]; const float* b2 = (const float*)d_in[17];
    const float* ln2g = (const float*)d_in[18]; const float* ln2b = (const float*)d_in[19];
    // d_in[20] = time_step (always 6)

    float* out  = (float*)d_out;
    float* z    = out;
    float* attn = out + (size_t)5 * PLsz;

    void* p;
    #define FSYM(var, sym) cudaGetSymbolAddress(&p, sym); float* var = (float*)p
    #define USYM(var, sym) cudaGetSymbolAddress(&p, sym); u16* var = (u16*)p
    #define WSYM(var, sym) cudaGetSymbolAddress(&p, sym); u32* var = (u32*)p
    FSYM(xin,  g_xin);  FSYM(prev, g_prev); FSYM(x1, g_x1);
    FSYM(qkv,  g_qkv);  FSYM(aout, g_aout); FSYM(fout, g_fout);
    FSYM(cur0, g_cur0); FSYM(mem,  g_mem);  FSYM(cnt,  g_cnt);
    FSYM(bqkv, g_bqkv);
    USYM(xinP, g_xinP); USYM(cntP, g_cntP); USYM(x1P, g_x1P);
    USYM(ctxP, g_ctxP); USYM(ffhP, g_ffhP);
    WSYM(wqkvP, g_wqkvP); WSYM(woP, g_woP); WSYM(w1P, g_w1P); WSYM(w2P, g_w2P);
    #undef FSYM
    #undef USYM
    #undef WSYM

    cudaFuncSetAttribute(attn_kernel, cudaFuncAttributeMaxDynamicSharedMemorySize,
                         ATTN_SMEM_FLOATS * 4);
    cudaFuncSetAttribute(gemm_bf<0>, cudaFuncAttributeMaxDynamicSharedMemorySize, GB_SMEM);
    cudaFuncSetAttribute(gemm_bf<1>, cudaFuncAttributeMaxDynamicSharedMemorySize, GB_SMEM);

    pack_qkvw_all<<<(NL * QKV_KN2 + 255) / 256, 256>>>(Wq, Wk, Wv, bq, bk, bv);
    pack_w_all<<<(NL * WO_KN2 + 255) / 256, 256>>>(Wo, woP, ND, ND);
    pack_w_all<<<(NL * W1_KN2 + 255) / 256, 256>>>(W1, w1P, ND, NF);
    pack_w_all<<<(NL * W2_KN2 + 255) / 256, 256>>>(W2, w2P, NF, ND);
    xin_kernel<<<(NR * ND) / 256, 256>>>(u, seg, semb, z);

    const dim3 gQKV(N3 / 128, NR / 64, 1);   // 18x16
    const dim3 gO  (ND / 128, NR / 64, 4);   // split-K4, klen=192
    const dim3 gF1 (NF / 128, NR / 64, 1);   // 24x16
    const dim3 gF2 (ND / 128, NR / 64, 4);   // split-K4, klen=768
    const dim3 gAttn(8, NH, NB);
    const int gLN = NR / 8;
    const float inv6 = 1.0f / 6.0f;

    // ---- layer 0: block output constant across time; compute once ----
    {
        gemm_bf<0><<<gQKV, 256, GB_SMEM>>>(xinP, xinP + PLsz, xinP + 2 * PLsz,
            wqkvP, wqkvP + QKV_KN2, wqkvP + 2 * (size_t)QKV_KN2,
            bqkv, 1.0f, qkv, 0, 0, 0, N3, ND, ND, 0);
        attn_kernel<<<gAttn, 256, ATTN_SMEM_FLOATS * 4>>>(qkv, mask, attn, ctxP, 1.0f, 0);
        gemm_bf<0><<<gO, 256, GB_SMEM>>>(ctxP, ctxP + PLsz, ctxP + 2 * PLsz,
            woP, woP + WO_KN2, woP + 2 * (size_t)WO_KN2,
            (const float*)0, 1.0f, aout, 0, 0, 0, ND, ND, ND / 4, 0);
        add_ln4_kernel<<<gLN, 256>>>(xin, aout, bo, ln1g, ln1b, x1, x1P);
        gemm_bf<0><<<gF1, 256, GB_SMEM>>>(x1P, x1P + PLsz, x1P + 2 * PLsz,
            w1P, w1P + W1_KN2, w1P + 2 * (size_t)W1_KN2,
            b1, 1.0f, 0, ffhP, ffhP + FFsz, ffhP + 2 * FFsz, NF, ND, ND, 1);
        gemm_bf<0><<<gF2, 256, GB_SMEM>>>(ffhP, ffhP + FFsz, ffhP + 2 * FFsz,
            w2P, w2P + W2_KN2, w2P + 2 * (size_t)W2_KN2,
            (const float*)0, 1.0f, fout, 0, 0, 0, ND, NF, NF / 4, 0);
        add_ln_spike4_kernel<<<gLN, 256>>>(x1, fout, b2, ln2g, ln2b,
            0, 0, 0, 0, 0.f, 0, 0, cur0);
    }

    for (int t = 0; t < NT; t++) {
        float tp1 = (float)(t + 1);
        float invt = 1.0f / tp1;
        rate0_kernel<<<(NR * ND / 4) / 256, 256>>>(tp1,
            (t == NT - 1) ? (z + (size_t)1 * PLsz) : (float*)0);

        for (int l = 1; l < NL; l++) {
            gemm_bf<1><<<gQKV, 256, GB_SMEM>>>(cntP, cntP, cntP,
                wqkvP + ((size_t)l * 3 + 0) * QKV_KN2,
                wqkvP + ((size_t)l * 3 + 1) * QKV_KN2,
                wqkvP + ((size_t)l * 3 + 2) * QKV_KN2,
                bqkv + l * N3, invt, qkv, 0, 0, 0, N3, ND, ND, 0);
            attn_kernel<<<gAttn, 256, ATTN_SMEM_FLOATS * 4>>>(
                qkv, mask, attn + (size_t)l * NB * NH * NS * NS, ctxP,
                inv6, (t > 0) ? 1 : 0);
            gemm_bf<0><<<gO, 256, GB_SMEM>>>(ctxP, ctxP + PLsz, ctxP + 2 * PLsz,
                woP + ((size_t)l * 3 + 0) * WO_KN2,
                woP + ((size_t)l * 3 + 1) * WO_KN2,
                woP + ((size_t)l * 3 + 2) * WO_KN2,
                (const float*)0, 1.0f, aout, 0, 0, 0, ND, ND, ND / 4, 0);
            add_ln4_kernel<<<gLN, 256>>>(prev, aout, bo + l * ND,
                ln1g + l * ND, ln1b + l * ND, x1, x1P);
            gemm_bf<0><<<gF1, 256, GB_SMEM>>>(x1P, x1P + PLsz, x1P + 2 * PLsz,
                w1P + ((size_t)l * 3 + 0) * W1_KN2,
                w1P + ((size_t)l * 3 + 1) * W1_KN2,
                w1P + ((size_t)l * 3 + 2) * W1_KN2,
                b1 + l * NF, 1.0f, 0, ffhP, ffhP + FFsz, ffhP + 2 * FFsz, NF, ND, ND, 1);
            gemm_bf<0><<<gF2, 256, GB_SMEM>>>(ffhP, ffhP + FFsz, ffhP + 2 * FFsz,
                w2P + ((size_t)l * 3 + 0) * W2_KN2,
                w2P + ((size_t)l * 3 + 1) * W2_KN2,
                w2P + ((size_t)l * 3 + 2) * W2_KN2,
                (const float*)0, 1.0f, fout, 0, 0, 0, ND, NF, NF / 4, 0);
            add_ln_spike4_kernel<<<gLN, 256>>>(x1, fout, b2 + l * ND,
                ln2g + l * ND, ln2b + l * ND,
                mem + (size_t)l * PLsz, cnt + (size_t)l * PLsz,
                prev, cntP, invt,
                (t == NT - 1) ? (z + (size_t)(1 + l) * PLsz) : (float*)0,
                (t == 0) ? 1 : 0, 0);
        }
    }
}